// round 1
// baseline (speedup 1.0000x reference)
#include <cuda_runtime.h>
#include <math.h>

// Problem dims (fixed by reference setup_inputs)
#define M_TOT 8192          // B*K = 128*64
#define D_DIM 256           // d_model
#define BD    2700          // basis_dim
#define NC    1024          // num_codes
#define EPS_ENT 1e-8f

// Scratch (device globals — no allocation allowed)
__device__ float g_ze[(size_t)M_TOT * BD];     // z_e  [8192,2700]  88.5 MB
__device__ float g_dist[(size_t)M_TOT * NC];   // dist -> probs     33.5 MB
__device__ float g_znorm[M_TOT];
__device__ float g_enorm[NC];
__device__ float g_colsum[NC];
__device__ int   g_idx[M_TOT];
__device__ float g_vqsum;

// ---------------------------------------------------------------------------
__global__ void k_zero() {
    int t = threadIdx.x;
    if (t < NC) g_colsum[t] = 0.f;
    if (t == 0) g_vqsum = 0.f;
}

// ---------------------------------------------------------------------------
// ||embed_row||^2
__global__ void k_enorm(const float* __restrict__ E) {
    int row = blockIdx.x;
    const float* x = E + (size_t)row * BD;
    float s = 0.f;
    for (int i = threadIdx.x; i < BD; i += 256) { float v = x[i]; s += v * v; }
    __shared__ float sw[8];
    for (int o = 16; o > 0; o >>= 1) s += __shfl_down_sync(0xffffffffu, s, o);
    int lane = threadIdx.x & 31, w = threadIdx.x >> 5;
    if (lane == 0) sw[w] = s;
    __syncthreads();
    if (w == 0) {
        s = (lane < 8) ? sw[lane] : 0.f;
        for (int o = 4; o > 0; o >>= 1) s += __shfl_down_sync(0xffffffffu, s, o);
        if (lane == 0) g_enorm[row] = s;
    }
}

// ||z_row||^2
__global__ void k_znorm() {
    int row = blockIdx.x;
    const float* x = g_ze + (size_t)row * BD;
    float s = 0.f;
    for (int i = threadIdx.x; i < BD; i += 256) { float v = x[i]; s += v * v; }
    __shared__ float sw[8];
    for (int o = 16; o > 0; o >>= 1) s += __shfl_down_sync(0xffffffffu, s, o);
    int lane = threadIdx.x & 31, w = threadIdx.x >> 5;
    if (lane == 0) sw[w] = s;
    __syncthreads();
    if (w == 0) {
        s = (lane < 8) ? sw[lane] : 0.f;
        for (int o = 4; o > 0; o >>= 1) s += __shfl_down_sync(0xffffffffu, s, o);
        if (lane == 0) g_znorm[row] = s;
    }
}

// ---------------------------------------------------------------------------
// GEMM1: z_e[m,n] = sum_d sf[m,d]*W[n,d] + b[n]    M=8192, N=2700, K=256
// 64x64 tile, K-tile 16, 256 threads, 4x4 per thread
__global__ void k_gemm1(const float* __restrict__ A, const float* __restrict__ W,
                        const float* __restrict__ bias) {
    __shared__ float As[16][68];
    __shared__ float Bs[16][68];
    const int bm = blockIdx.y * 64;
    const int bn = blockIdx.x * 64;
    const int tid = threadIdx.x;
    const int tx = tid & 15, ty = tid >> 4;
    float acc[4][4];
#pragma unroll
    for (int i = 0; i < 4; i++)
#pragma unroll
        for (int j = 0; j < 4; j++) acc[i][j] = 0.f;

    for (int k0 = 0; k0 < D_DIM; k0 += 16) {
#pragma unroll
        for (int i = 0; i < 4; i++) {
            int e = tid + i * 256;
            int r = e >> 4, c = e & 15;
            As[c][r] = A[(size_t)(bm + r) * D_DIM + k0 + c];
            int gn = bn + r;
            Bs[c][r] = (gn < BD) ? W[(size_t)gn * D_DIM + k0 + c] : 0.f;
        }
        __syncthreads();
#pragma unroll
        for (int kk = 0; kk < 16; kk++) {
            float a[4], b[4];
#pragma unroll
            for (int i = 0; i < 4; i++) a[i] = As[kk][ty * 4 + i];
#pragma unroll
            for (int j = 0; j < 4; j++) b[j] = Bs[kk][tx * 4 + j];
#pragma unroll
            for (int i = 0; i < 4; i++)
#pragma unroll
                for (int j = 0; j < 4; j++) acc[i][j] += a[i] * b[j];
        }
        __syncthreads();
    }
#pragma unroll
    for (int i = 0; i < 4; i++) {
        int gm = bm + ty * 4 + i;
#pragma unroll
        for (int j = 0; j < 4; j++) {
            int gn = bn + tx * 4 + j;
            if (gn < BD) g_ze[(size_t)gm * BD + gn] = acc[i][j] + bias[gn];
        }
    }
}

// ---------------------------------------------------------------------------
// GEMM2: dist[m,c] = znorm[m] - 2*sum_k ze[m,k]*E[c,k] + enorm[c]
// M=8192, N=1024, K=2700
__global__ void k_gemm2(const float* __restrict__ E) {
    __shared__ float As[16][68];
    __shared__ float Bs[16][68];
    const int bm = blockIdx.y * 64;
    const int bn = blockIdx.x * 64;
    const int tid = threadIdx.x;
    const int tx = tid & 15, ty = tid >> 4;
    float acc[4][4];
#pragma unroll
    for (int i = 0; i < 4; i++)
#pragma unroll
        for (int j = 0; j < 4; j++) acc[i][j] = 0.f;

    for (int k0 = 0; k0 < BD; k0 += 16) {
#pragma unroll
        for (int i = 0; i < 4; i++) {
            int e = tid + i * 256;
            int r = e >> 4, c = e & 15;
            int gk = k0 + c;
            bool ok = gk < BD;
            As[c][r] = ok ? g_ze[(size_t)(bm + r) * BD + gk] : 0.f;
            Bs[c][r] = ok ? E[(size_t)(bn + r) * BD + gk] : 0.f;
        }
        __syncthreads();
#pragma unroll
        for (int kk = 0; kk < 16; kk++) {
            float a[4], b[4];
#pragma unroll
            for (int i = 0; i < 4; i++) a[i] = As[kk][ty * 4 + i];
#pragma unroll
            for (int j = 0; j < 4; j++) b[j] = Bs[kk][tx * 4 + j];
#pragma unroll
            for (int i = 0; i < 4; i++)
#pragma unroll
                for (int j = 0; j < 4; j++) acc[i][j] += a[i] * b[j];
        }
        __syncthreads();
    }
#pragma unroll
    for (int i = 0; i < 4; i++) {
        int gm = bm + ty * 4 + i;
        float zn = g_znorm[gm];
#pragma unroll
        for (int j = 0; j < 4; j++) {
            int gn = bn + tx * 4 + j;
            g_dist[(size_t)gm * NC + gn] = zn - 2.f * acc[i][j] + g_enorm[gn];
        }
    }
}

// ---------------------------------------------------------------------------
// Per-row: argmin (first-min tiebreak), softmax(-dist) written back into g_dist
__global__ void k_row(float* __restrict__ out_idx) {
    const int row = blockIdx.x;
    float* d = g_dist + (size_t)row * NC;
    const int tid = threadIdx.x;  // 256 threads, 4 contiguous cols each
    float4 v = reinterpret_cast<float4*>(d)[tid];

    float vmin = v.x; int imin = tid * 4;
    if (v.y < vmin) { vmin = v.y; imin = tid * 4 + 1; }
    if (v.z < vmin) { vmin = v.z; imin = tid * 4 + 2; }
    if (v.w < vmin) { vmin = v.w; imin = tid * 4 + 3; }

    for (int o = 16; o > 0; o >>= 1) {
        float ov = __shfl_down_sync(0xffffffffu, vmin, o);
        int   oi = __shfl_down_sync(0xffffffffu, imin, o);
        if (ov < vmin || (ov == vmin && oi < imin)) { vmin = ov; imin = oi; }
    }
    __shared__ float swv[8];
    __shared__ int   swi[8];
    __shared__ float s_min, s_sum;
    int lane = tid & 31, w = tid >> 5;
    if (lane == 0) { swv[w] = vmin; swi[w] = imin; }
    __syncthreads();
    if (w == 0) {
        vmin = (lane < 8) ? swv[lane] : 3.4e38f;
        imin = (lane < 8) ? swi[lane] : 0x7fffffff;
        for (int o = 4; o > 0; o >>= 1) {
            float ov = __shfl_down_sync(0xffffffffu, vmin, o);
            int   oi = __shfl_down_sync(0xffffffffu, imin, o);
            if (ov < vmin || (ov == vmin && oi < imin)) { vmin = ov; imin = oi; }
        }
        if (lane == 0) {
            s_min = vmin;
            g_idx[row] = imin;
            out_idx[row] = (float)imin;
        }
    }
    __syncthreads();
    float m = s_min;
    float e0 = expf(m - v.x), e1 = expf(m - v.y), e2 = expf(m - v.z), e3 = expf(m - v.w);
    float s = e0 + e1 + e2 + e3;
    for (int o = 16; o > 0; o >>= 1) s += __shfl_down_sync(0xffffffffu, s, o);
    if (lane == 0) swv[w] = s;
    __syncthreads();
    if (w == 0) {
        s = (lane < 8) ? swv[lane] : 0.f;
        for (int o = 4; o > 0; o >>= 1) s += __shfl_down_sync(0xffffffffu, s, o);
        if (lane == 0) s_sum = s;
    }
    __syncthreads();
    float inv = 1.f / s_sum;
    float4 p = make_float4(e0 * inv, e1 * inv, e2 * inv, e3 * inv);
    reinterpret_cast<float4*>(d)[tid] = p;
}

// ---------------------------------------------------------------------------
// Column sums of probs (g_dist now holds probs). 64 blocks x 128 rows each.
__global__ void k_colsum() {
    const int tid = threadIdx.x;  // 256
    const int r0 = blockIdx.x * 128;
    float s0 = 0.f, s1 = 0.f, s2 = 0.f, s3 = 0.f;
    for (int r = r0; r < r0 + 128; r++) {
        const float* row = g_dist + (size_t)r * NC;
        s0 += row[tid];
        s1 += row[tid + 256];
        s2 += row[tid + 512];
        s3 += row[tid + 768];
    }
    atomicAdd(&g_colsum[tid],       s0);
    atomicAdd(&g_colsum[tid + 256], s1);
    atomicAdd(&g_colsum[tid + 512], s2);
    atomicAdd(&g_colsum[tid + 768], s3);
}

// ---------------------------------------------------------------------------
// q_st = embed[idx]  (exactly e_i), and vq partial sums
__global__ void k_gather(const float* __restrict__ E, float* __restrict__ out_q) {
    const int row = blockIdx.x;
    const int idx = g_idx[row];
    const float* e = E + (size_t)idx * BD;
    const float* z = g_ze + (size_t)row * BD;
    float* o = out_q + (size_t)row * BD;
    float s = 0.f;
    for (int i = threadIdx.x; i < BD; i += 256) {
        float ev = e[i];
        o[i] = ev;
        float df = z[i] - ev;
        s += df * df;
    }
    __shared__ float sw[8];
    for (int o2 = 16; o2 > 0; o2 >>= 1) s += __shfl_down_sync(0xffffffffu, s, o2);
    int lane = threadIdx.x & 31, w = threadIdx.x >> 5;
    if (lane == 0) sw[w] = s;
    __syncthreads();
    if (w == 0) {
        s = (lane < 8) ? sw[lane] : 0.f;
        for (int o2 = 4; o2 > 0; o2 >>= 1) s += __shfl_down_sync(0xffffffffu, s, o2);
        if (lane == 0) atomicAdd(&g_vqsum, s);
    }
}

// ---------------------------------------------------------------------------
// entropy + vq_loss scalars
__global__ void k_final(float* __restrict__ out) {
    const int tid = threadIdx.x;  // 1024
    float avg = g_colsum[tid] * (1.0f / (float)M_TOT);
    float t = -avg * logf(avg + EPS_ENT);
    __shared__ float sw[32];
    for (int o = 16; o > 0; o >>= 1) t += __shfl_down_sync(0xffffffffu, t, o);
    int lane = tid & 31, w = tid >> 5;
    if (lane == 0) sw[w] = t;
    __syncthreads();
    if (w == 0) {
        t = sw[lane];
        for (int o = 16; o > 0; o >>= 1) t += __shfl_down_sync(0xffffffffu, t, o);
        if (lane == 0) {
            const size_t OFF = (size_t)M_TOT * BD + M_TOT;
            out[OFF]     = g_vqsum * (1.0f / ((float)M_TOT * (float)BD));  // vq_loss
            out[OFF + 1] = t;                                              // entropy
        }
    }
}

// ---------------------------------------------------------------------------
extern "C" void kernel_launch(void* const* d_in, const int* in_sizes, int n_in,
                              void* d_out, int out_size) {
    const float* sf = (const float*)d_in[0];   // [128,64,256]
    const float* W  = (const float*)d_in[1];   // [2700,256]
    const float* b  = (const float*)d_in[2];   // [2700]
    const float* E  = (const float*)d_in[3];   // [1024,2700]
    float* out      = (float*)d_out;
    float* out_q    = out;
    float* out_idx  = out + (size_t)M_TOT * BD;

    k_zero<<<1, 1024>>>();
    k_enorm<<<NC, 256>>>(E);
    k_gemm1<<<dim3((BD + 63) / 64, M_TOT / 64), 256>>>(sf, W, b);
    k_znorm<<<M_TOT, 256>>>();
    k_gemm2<<<dim3(NC / 64, M_TOT / 64), 256>>>(E);
    k_row<<<M_TOT, 256>>>(out_idx);
    k_colsum<<<64, 256>>>();
    k_gather<<<M_TOT, 256>>>(E, out_q);
    k_final<<<1, 1024>>>(out);
}

// round 3
// speedup vs baseline: 3.0775x; 3.0775x over previous
#include <cuda_runtime.h>
#include <cuda_fp16.h>
#include <math.h>
#include <stdint.h>

// Problem dims
#define M_TOT 8192
#define D_DIM 256
#define BD    2700
#define NC    1024
#define KPAD  2752          // 86 * 32
#define NPAD1 2816          // 11 * 256 (W rows padded)
#define EPS_ENT 1e-8f

// ---------------------------------------------------------------------------
__device__ __forceinline__ uint32_t smem_to_u32(const void* p) {
    uint32_t a;
    asm("{ .reg .u64 t; cvta.to.shared.u64 t, %1; cvt.u32.u64 %0, t; }" : "=r"(a) : "l"(p));
    return a;
}

__device__ __forceinline__ unsigned short f2h(float x) {
    unsigned short r;
    asm("cvt.rn.f16.f32 %0, %1;" : "=h"(r) : "f"(x));
    return r;
}
__device__ __forceinline__ float h2f(unsigned short h) {
    float f;
    asm("cvt.f32.f16 %0, %1;" : "=f"(f) : "h"(h));
    return f;
}

#define LDSM_X4(R, addr) \
    asm volatile("ldmatrix.sync.aligned.m8n8.x4.shared.b16 {%0,%1,%2,%3}, [%4];" \
        : "=r"((R)[0]), "=r"((R)[1]), "=r"((R)[2]), "=r"((R)[3]) : "r"(addr))

__device__ __forceinline__ void mma16816(float* c, const uint32_t* a, const uint32_t* b) {
    asm volatile("mma.sync.aligned.m16n8k16.row.col.f32.f16.f16.f32 "
        "{%0,%1,%2,%3}, {%4,%5,%6,%7}, {%8,%9}, {%0,%1,%2,%3};"
        : "+f"(c[0]), "+f"(c[1]), "+f"(c[2]), "+f"(c[3])
        : "r"(a[0]), "r"(a[1]), "r"(a[2]), "r"(a[3]), "r"(b[0]), "r"(b[1]));
}

__device__ __forceinline__ void cp16(uint32_t dst, const void* src) {
    asm volatile("cp.async.cg.shared.global [%0], [%1], 16;" :: "r"(dst), "l"(src) : "memory");
}
#define CP_COMMIT() asm volatile("cp.async.commit_group;" ::: "memory")

// ---------------------------------------------------------------------------
// Scratch (device globals, zero-initialized; padding never written)
// ---------------------------------------------------------------------------
__device__ __align__(16) unsigned short g_zhi[(size_t)M_TOT * KPAD];
__device__ __align__(16) unsigned short g_zlo[(size_t)M_TOT * KPAD];
__device__ __align__(16) unsigned short g_ehi[(size_t)NC * KPAD];
__device__ __align__(16) unsigned short g_elo[(size_t)NC * KPAD];
__device__ __align__(16) unsigned short g_sfhi[(size_t)M_TOT * D_DIM];
__device__ __align__(16) unsigned short g_sflo[(size_t)M_TOT * D_DIM];
__device__ __align__(16) unsigned short g_whi[(size_t)NPAD1 * D_DIM];
__device__ __align__(16) unsigned short g_wlo[(size_t)NPAD1 * D_DIM];
__device__ __align__(16) float g_dist[(size_t)M_TOT * NC];
__device__ float g_enorm[NC];
__device__ float g_colsum[NC];
__device__ int   g_idx[M_TOT];
__device__ float g_vqsum;

// ---------------------------------------------------------------------------
__global__ void k_zero() {
    int t = threadIdx.x;
    if (t < NC) g_colsum[t] = 0.f;
    if (t == 0) g_vqsum = 0.f;
}

// Convert E -> ehi/elo (padded K) + enorm
__global__ void __launch_bounds__(256) k_prep_E(const float* __restrict__ E) {
    const int row = blockIdx.x;
    const int tid = threadIdx.x;
    const float4* src = (const float4*)(E + (size_t)row * BD);
    uint2* dh = (uint2*)(g_ehi + (size_t)row * KPAD);
    uint2* dl = (uint2*)(g_elo + (size_t)row * KPAD);
    float s = 0.f;
    for (int i = tid; i < BD / 4; i += 256) {
        float4 v = src[i];
        s += v.x * v.x + v.y * v.y + v.z * v.z + v.w * v.w;
        unsigned short h0 = f2h(v.x), h1 = f2h(v.y), h2 = f2h(v.z), h3 = f2h(v.w);
        unsigned short l0 = f2h(v.x - h2f(h0)), l1 = f2h(v.y - h2f(h1));
        unsigned short l2 = f2h(v.z - h2f(h2)), l3 = f2h(v.w - h2f(h3));
        uint2 uh, ul;
        uh.x = (uint32_t)h0 | ((uint32_t)h1 << 16); uh.y = (uint32_t)h2 | ((uint32_t)h3 << 16);
        ul.x = (uint32_t)l0 | ((uint32_t)l1 << 16); ul.y = (uint32_t)l2 | ((uint32_t)l3 << 16);
        dh[i] = uh; dl[i] = ul;
    }
    __shared__ float sw[8];
    for (int o = 16; o > 0; o >>= 1) s += __shfl_down_sync(0xffffffffu, s, o);
    int lane = tid & 31, w = tid >> 5;
    if (lane == 0) sw[w] = s;
    __syncthreads();
    if (w == 0) {
        s = (lane < 8) ? sw[lane] : 0.f;
        for (int o = 4; o > 0; o >>= 1) s += __shfl_down_sync(0xffffffffu, s, o);
        if (lane == 0) g_enorm[row] = s;
    }
}

// Elementwise fp32 -> hi/lo fp16 (contiguous)
__global__ void __launch_bounds__(256) k_split(const float* __restrict__ src,
                                               unsigned short* __restrict__ dh_,
                                               unsigned short* __restrict__ dl_) {
    int idx = blockIdx.x * 256 + threadIdx.x;
    float4 v = ((const float4*)src)[idx];
    unsigned short h0 = f2h(v.x), h1 = f2h(v.y), h2 = f2h(v.z), h3 = f2h(v.w);
    unsigned short l0 = f2h(v.x - h2f(h0)), l1 = f2h(v.y - h2f(h1));
    unsigned short l2 = f2h(v.z - h2f(h2)), l3 = f2h(v.w - h2f(h3));
    uint2 uh, ul;
    uh.x = (uint32_t)h0 | ((uint32_t)h1 << 16); uh.y = (uint32_t)h2 | ((uint32_t)h3 << 16);
    ul.x = (uint32_t)l0 | ((uint32_t)l1 << 16); ul.y = (uint32_t)l2 | ((uint32_t)l3 << 16);
    ((uint2*)dh_)[idx] = uh;
    ((uint2*)dl_)[idx] = ul;
}

// ---------------------------------------------------------------------------
// Shared mainloop: CTA tile 128(M) x 256(N), K-chunk 32 fp16, 8 warps (64x64),
// split-precision: acc += Ahi*Bhi + Ahi*Blo + Alo*Bhi
// SMEM stage: Ahi[128x32]@0, Alo@8192, Bhi[256x32]@16384, Blo@32768 (49152 B)
// XOR swizzle: 16B chunk c8 (0..3) at phys (c8 ^ ((row>>1)&3)) -> conflict-free
// ---------------------------------------------------------------------------
#define STAGE_BYTES 49152
#define SMEM_BYTES  (2 * STAGE_BYTES)

__device__ __forceinline__ void mma_mainloop(
    const unsigned short* __restrict__ Ahi, const unsigned short* __restrict__ Alo, int ldA,
    const unsigned short* __restrict__ Bhi, const unsigned short* __restrict__ Blo, int ldB,
    int m0, int n0, int nch, uint32_t sb0, float (&acc)[4][8][4])
{
    const int tid = threadIdx.x;
    const int lane = tid & 31, wid = tid >> 5;
    const int wm = (wid & 1) * 64;      // warp m offset in CTA tile
    const int wn = (wid >> 1) * 64;     // warp n offset

    // ---- cp.async stage issue ----
    auto issue = [&](int c, int s) {
        const int k0 = c * 32;
        const uint32_t sb = sb0 + s * STAGE_BYTES;
#pragma unroll
        for (int t = 0; t < 2; t++) {
            int u = t * 256 + tid;
            int r = u >> 2, c8 = u & 3;
            uint32_t d = sb + r * 64 + ((c8 ^ ((r >> 1) & 3)) << 4);
            const unsigned short* ga = Ahi + (size_t)(m0 + r) * ldA + k0 + c8 * 8;
            const unsigned short* gl = Alo + (size_t)(m0 + r) * ldA + k0 + c8 * 8;
            cp16(d, ga);
            cp16(d + 8192, gl);
        }
#pragma unroll
        for (int t = 0; t < 4; t++) {
            int u = t * 256 + tid;
            int r = u >> 2, c8 = u & 3;
            uint32_t d = sb + 16384 + r * 64 + ((c8 ^ ((r >> 1) & 3)) << 4);
            const unsigned short* gb = Bhi + (size_t)(n0 + r) * ldB + k0 + c8 * 8;
            const unsigned short* gl = Blo + (size_t)(n0 + r) * ldB + k0 + c8 * 8;
            cp16(d, gb);
            cp16(d + 16384, gl);
        }
        CP_COMMIT();
    };

    issue(0, 0);
    for (int c = 0; c < nch; c++) {
        const int s = c & 1;
        const bool has_next = (c + 1 < nch);
        if (has_next) issue(c + 1, s ^ 1);
        if (has_next) asm volatile("cp.async.wait_group 1;" ::: "memory");
        else          asm volatile("cp.async.wait_group 0;" ::: "memory");
        __syncthreads();

        const uint32_t sb = sb0 + s * STAGE_BYTES;
#pragma unroll
        for (int kb = 0; kb < 2; kb++) {
            uint32_t ah[4][4], al[4][4];
#pragma unroll
            for (int mt = 0; mt < 4; mt++) {
                int row = wm + mt * 16 + (lane & 15);
                int c8 = kb * 2 + (lane >> 4);
                uint32_t a = sb + row * 64 + ((c8 ^ ((row >> 1) & 3)) << 4);
                LDSM_X4(ah[mt], a);
                LDSM_X4(al[mt], a + 8192);
            }
#pragma unroll
            for (int nb2 = 0; nb2 < 4; nb2++) {
                int rn = wn + nb2 * 16 + (lane & 7) + ((lane >> 4) << 3);
                int c8 = kb * 2 + ((lane >> 3) & 1);
                uint32_t baddr = sb + 16384 + rn * 64 + ((c8 ^ ((rn >> 1) & 3)) << 4);
                uint32_t bh[4], bl[4];
                LDSM_X4(bh, baddr);
                LDSM_X4(bl, baddr + 16384);
#pragma unroll
                for (int mt = 0; mt < 4; mt++) {
#pragma unroll
                    for (int j = 0; j < 2; j++) {
                        float* cc = acc[mt][nb2 * 2 + j];
                        mma16816(cc, ah[mt], bh + j * 2);
                        mma16816(cc, ah[mt], bl + j * 2);
                        mma16816(cc, al[mt], bh + j * 2);
                    }
                }
            }
        }
        __syncthreads();
    }
}

// ---------------------------------------------------------------------------
// GEMM1: z = sf @ W^T + b -> fp16 hi/lo into g_zhi/g_zlo. grid (11, 64)
// ---------------------------------------------------------------------------
__global__ void __launch_bounds__(256, 1) g1_kernel(const float* __restrict__ bias) {
    extern __shared__ char smem[];
    uint32_t sb0 = smem_to_u32(smem);
    float acc[4][8][4];
#pragma unroll
    for (int a = 0; a < 4; a++)
#pragma unroll
        for (int b = 0; b < 8; b++)
#pragma unroll
            for (int c = 0; c < 4; c++) acc[a][b][c] = 0.f;

    const int m0 = blockIdx.y * 128, n0 = blockIdx.x * 256;
    mma_mainloop(g_sfhi, g_sflo, D_DIM, g_whi, g_wlo, D_DIM, m0, n0, D_DIM / 32, sb0, acc);

    const int lane = threadIdx.x & 31, wid = threadIdx.x >> 5;
    const int wm = (wid & 1) * 64, wn = (wid >> 1) * 64;
    const int g = lane >> 2, t = lane & 3;
#pragma unroll
    for (int mt = 0; mt < 4; mt++) {
#pragma unroll
        for (int nt = 0; nt < 8; nt++) {
            int col = n0 + wn + nt * 8 + t * 2;
            if (col >= BD) continue;
            float b0 = bias[col], b1 = bias[col + 1];
#pragma unroll
            for (int h = 0; h < 2; h++) {
                int m = m0 + wm + mt * 16 + g + h * 8;
                float v0 = acc[mt][nt][h * 2 + 0] + b0;
                float v1 = acc[mt][nt][h * 2 + 1] + b1;
                unsigned short h0 = f2h(v0), h1 = f2h(v1);
                unsigned short l0 = f2h(v0 - h2f(h0)), l1 = f2h(v1 - h2f(h1));
                *(uint32_t*)(g_zhi + (size_t)m * KPAD + col) = (uint32_t)h0 | ((uint32_t)h1 << 16);
                *(uint32_t*)(g_zlo + (size_t)m * KPAD + col) = (uint32_t)l0 | ((uint32_t)l1 << 16);
            }
        }
    }
}

// ---------------------------------------------------------------------------
// GEMM2: dist = enorm[n] - 2 * (z @ E^T). grid (4, 64)
// ---------------------------------------------------------------------------
__global__ void __launch_bounds__(256, 1) g2_kernel() {
    extern __shared__ char smem[];
    uint32_t sb0 = smem_to_u32(smem);
    float acc[4][8][4];
#pragma unroll
    for (int a = 0; a < 4; a++)
#pragma unroll
        for (int b = 0; b < 8; b++)
#pragma unroll
            for (int c = 0; c < 4; c++) acc[a][b][c] = 0.f;

    const int m0 = blockIdx.y * 128, n0 = blockIdx.x * 256;
    mma_mainloop(g_zhi, g_zlo, KPAD, g_ehi, g_elo, KPAD, m0, n0, KPAD / 32, sb0, acc);

    const int lane = threadIdx.x & 31, wid = threadIdx.x >> 5;
    const int wm = (wid & 1) * 64, wn = (wid >> 1) * 64;
    const int g = lane >> 2, t = lane & 3;
#pragma unroll
    for (int mt = 0; mt < 4; mt++) {
#pragma unroll
        for (int nt = 0; nt < 8; nt++) {
            int col = n0 + wn + nt * 8 + t * 2;
            float2 en = *(const float2*)(g_enorm + col);
#pragma unroll
            for (int h = 0; h < 2; h++) {
                int m = m0 + wm + mt * 16 + g + h * 8;
                float2 o;
                o.x = en.x - 2.f * acc[mt][nt][h * 2 + 0];
                o.y = en.y - 2.f * acc[mt][nt][h * 2 + 1];
                *(float2*)(g_dist + (size_t)m * NC + col) = o;
            }
        }
    }
}

// ---------------------------------------------------------------------------
// Per-row argmin + softmax + fused column-sum accumulation. 8 rows per block.
// ---------------------------------------------------------------------------
__global__ void __launch_bounds__(256) k_row(float* __restrict__ out_idx) {
    const int tid = threadIdx.x, lane = tid & 31, w = tid >> 5;
    __shared__ float swv[8];
    __shared__ int   swi[8];
    __shared__ float s_min, s_sum;
    float cs0 = 0.f, cs1 = 0.f, cs2 = 0.f, cs3 = 0.f;
    const int r0 = blockIdx.x * 8;
    for (int rr = 0; rr < 8; rr++) {
        const int row = r0 + rr;
        float4 v = ((const float4*)(g_dist + (size_t)row * NC))[tid];
        float vmin = v.x; int imin = tid * 4;
        if (v.y < vmin) { vmin = v.y; imin = tid * 4 + 1; }
        if (v.z < vmin) { vmin = v.z; imin = tid * 4 + 2; }
        if (v.w < vmin) { vmin = v.w; imin = tid * 4 + 3; }
        for (int o = 16; o > 0; o >>= 1) {
            float ov = __shfl_down_sync(0xffffffffu, vmin, o);
            int   oi = __shfl_down_sync(0xffffffffu, imin, o);
            if (ov < vmin || (ov == vmin && oi < imin)) { vmin = ov; imin = oi; }
        }
        if (lane == 0) { swv[w] = vmin; swi[w] = imin; }
        __syncthreads();
        if (w == 0) {
            vmin = (lane < 8) ? swv[lane] : 3.4e38f;
            imin = (lane < 8) ? swi[lane] : 0x7fffffff;
            for (int o = 4; o > 0; o >>= 1) {
                float ov = __shfl_down_sync(0xffffffffu, vmin, o);
                int   oi = __shfl_down_sync(0xffffffffu, imin, o);
                if (ov < vmin || (ov == vmin && oi < imin)) { vmin = ov; imin = oi; }
            }
            if (lane == 0) {
                s_min = vmin;
                g_idx[row] = imin;
                out_idx[row] = (float)imin;
            }
        }
        __syncthreads();
        const float mn = s_min;
        float e0 = expf(mn - v.x), e1 = expf(mn - v.y);
        float e2 = expf(mn - v.z), e3 = expf(mn - v.w);
        float ss = e0 + e1 + e2 + e3;
        for (int o = 16; o > 0; o >>= 1) ss += __shfl_down_sync(0xffffffffu, ss, o);
        if (lane == 0) swv[w] = ss;
        __syncthreads();
        if (w == 0) {
            ss = (lane < 8) ? swv[lane] : 0.f;
            for (int o = 4; o > 0; o >>= 1) ss += __shfl_down_sync(0xffffffffu, ss, o);
            if (lane == 0) s_sum = ss;
        }
        __syncthreads();
        const float inv = 1.f / s_sum;
        cs0 += e0 * inv; cs1 += e1 * inv; cs2 += e2 * inv; cs3 += e3 * inv;
        __syncthreads();
    }
    atomicAdd(&g_colsum[tid * 4 + 0], cs0);
    atomicAdd(&g_colsum[tid * 4 + 1], cs1);
    atomicAdd(&g_colsum[tid * 4 + 2], cs2);
    atomicAdd(&g_colsum[tid * 4 + 3], cs3);
}

// ---------------------------------------------------------------------------
// q_st = embed[idx]; vq partial sums from z = hi + lo
// ---------------------------------------------------------------------------
__global__ void __launch_bounds__(256) k_gather(const float* __restrict__ E,
                                                float* __restrict__ out_q) {
    const int row = blockIdx.x;
    const int idx = g_idx[row];
    const float4* e4 = (const float4*)(E + (size_t)idx * BD);
    float4* o4 = (float4*)(out_q + (size_t)row * BD);
    const uint2* zh = (const uint2*)(g_zhi + (size_t)row * KPAD);
    const uint2* zl = (const uint2*)(g_zlo + (size_t)row * KPAD);
    float s = 0.f;
    for (int i = threadIdx.x; i < BD / 4; i += 256) {
        float4 ev = e4[i];
        uint2 h = zh[i], l = zl[i];
        float z0 = h2f((unsigned short)(h.x & 0xffff)) + h2f((unsigned short)(l.x & 0xffff));
        float z1 = h2f((unsigned short)(h.x >> 16))    + h2f((unsigned short)(l.x >> 16));
        float z2 = h2f((unsigned short)(h.y & 0xffff)) + h2f((unsigned short)(l.y & 0xffff));
        float z3 = h2f((unsigned short)(h.y >> 16))    + h2f((unsigned short)(l.y >> 16));
        o4[i] = ev;
        float d0 = z0 - ev.x, d1 = z1 - ev.y, d2 = z2 - ev.z, d3 = z3 - ev.w;
        s += d0 * d0 + d1 * d1 + d2 * d2 + d3 * d3;
    }
    __shared__ float sw[8];
    for (int o = 16; o > 0; o >>= 1) s += __shfl_down_sync(0xffffffffu, s, o);
    int lane = threadIdx.x & 31, w = threadIdx.x >> 5;
    if (lane == 0) sw[w] = s;
    __syncthreads();
    if (w == 0) {
        s = (lane < 8) ? sw[lane] : 0.f;
        for (int o = 4; o > 0; o >>= 1) s += __shfl_down_sync(0xffffffffu, s, o);
        if (lane == 0) atomicAdd(&g_vqsum, s);
    }
}

// ---------------------------------------------------------------------------
__global__ void k_final(float* __restrict__ out) {
    const int tid = threadIdx.x;  // 1024
    float avg = g_colsum[tid] * (1.0f / (float)M_TOT);
    float t = -avg * logf(avg + EPS_ENT);
    __shared__ float sw[32];
    for (int o = 16; o > 0; o >>= 1) t += __shfl_down_sync(0xffffffffu, t, o);
    int lane = tid & 31, w = tid >> 5;
    if (lane == 0) sw[w] = t;
    __syncthreads();
    if (w == 0) {
        t = sw[lane];
        for (int o = 16; o > 0; o >>= 1) t += __shfl_down_sync(0xffffffffu, t, o);
        if (lane == 0) {
            const size_t OFF = (size_t)M_TOT * BD + M_TOT;
            out[OFF]     = g_vqsum * (1.0f / ((float)M_TOT * (float)BD));
            out[OFF + 1] = t;
        }
    }
}

// ---------------------------------------------------------------------------
extern "C" void kernel_launch(void* const* d_in, const int* in_sizes, int n_in,
                              void* d_out, int out_size) {
    const float* sf = (const float*)d_in[0];   // [128,64,256]
    const float* W  = (const float*)d_in[1];   // [2700,256]
    const float* b  = (const float*)d_in[2];   // [2700]
    const float* E  = (const float*)d_in[3];   // [1024,2700]
    float* out      = (float*)d_out;
    float* out_q    = out;
    float* out_idx  = out + (size_t)M_TOT * BD;

    cudaFuncSetAttribute(g1_kernel, cudaFuncAttributeMaxDynamicSharedMemorySize, SMEM_BYTES);
    cudaFuncSetAttribute(g2_kernel, cudaFuncAttributeMaxDynamicSharedMemorySize, SMEM_BYTES);

    unsigned short *sfhi, *sflo, *whi, *wlo;
    cudaGetSymbolAddress((void**)&sfhi, g_sfhi);
    cudaGetSymbolAddress((void**)&sflo, g_sflo);
    cudaGetSymbolAddress((void**)&whi,  g_whi);
    cudaGetSymbolAddress((void**)&wlo,  g_wlo);

    k_zero<<<1, 1024>>>();
    k_prep_E<<<NC, 256>>>(E);
    k_split<<<(M_TOT * D_DIM / 4) / 256, 256>>>(sf, sfhi, sflo);
    k_split<<<(BD * D_DIM / 4) / 256, 256>>>(W, whi, wlo);
    g1_kernel<<<dim3(NPAD1 / 256, M_TOT / 128), 256, SMEM_BYTES>>>(b);
    g2_kernel<<<dim3(NC / 256, M_TOT / 128), 256, SMEM_BYTES>>>();
    k_row<<<M_TOT / 8, 256>>>(out_idx);
    k_gather<<<M_TOT, 256>>>(E, out_q);
    k_final<<<1, 1024>>>(out);
}

// round 4
// speedup vs baseline: 5.1368x; 1.6692x over previous
#include <cuda_runtime.h>
#include <cuda_fp16.h>
#include <math.h>
#include <stdint.h>

// Problem dims
#define M_TOT 8192
#define D_DIM 256
#define BD    2700
#define NC    1024
#define KPAD  2752          // 86 * 32
#define EPS_ENT 1e-8f

// ---------------------------------------------------------------------------
__device__ __forceinline__ uint32_t smem_to_u32(const void* p) {
    uint32_t a;
    asm("{ .reg .u64 t; cvta.to.shared.u64 t, %1; cvt.u32.u64 %0, t; }" : "=r"(a) : "l"(p));
    return a;
}
__device__ __forceinline__ unsigned short f2h(float x) {
    unsigned short r;
    asm("cvt.rn.f16.f32 %0, %1;" : "=h"(r) : "f"(x));
    return r;
}
__device__ __forceinline__ float h2f(unsigned short h) {
    float f;
    asm("cvt.f32.f16 %0, %1;" : "=f"(f) : "h"(h));
    return f;
}
#define LDSM_X4(R, addr) \
    asm volatile("ldmatrix.sync.aligned.m8n8.x4.shared.b16 {%0,%1,%2,%3}, [%4];" \
        : "=r"((R)[0]), "=r"((R)[1]), "=r"((R)[2]), "=r"((R)[3]) : "r"(addr))

__device__ __forceinline__ void mma16816(float* c, const uint32_t* a, const uint32_t* b) {
    asm volatile("mma.sync.aligned.m16n8k16.row.col.f32.f16.f16.f32 "
        "{%0,%1,%2,%3}, {%4,%5,%6,%7}, {%8,%9}, {%0,%1,%2,%3};"
        : "+f"(c[0]), "+f"(c[1]), "+f"(c[2]), "+f"(c[3])
        : "r"(a[0]), "r"(a[1]), "r"(a[2]), "r"(a[3]), "r"(b[0]), "r"(b[1]));
}
__device__ __forceinline__ void cp16(uint32_t dst, const void* src) {
    asm volatile("cp.async.cg.shared.global [%0], [%1], 16;" :: "r"(dst), "l"(src) : "memory");
}
#define CP_COMMIT() asm volatile("cp.async.commit_group;" ::: "memory")

// ---------------------------------------------------------------------------
// Scratch (device globals)
// ---------------------------------------------------------------------------
__device__ __align__(16) unsigned short g_ehi[(size_t)NC * KPAD];      // E split
__device__ __align__(16) unsigned short g_elo[(size_t)NC * KPAD];
__device__ __align__(16) unsigned short g_wthi[(size_t)D_DIM * KPAD];  // W^T split
__device__ __align__(16) unsigned short g_wtlo[(size_t)D_DIM * KPAD];
__device__ __align__(16) unsigned short g_sfhi[(size_t)M_TOT * D_DIM];
__device__ __align__(16) unsigned short g_sflo[(size_t)M_TOT * D_DIM];
__device__ __align__(16) float g_F[(size_t)NC * D_DIM];                // E@W fp32 (atomic)
__device__ __align__(16) float g_G[(size_t)D_DIM * D_DIM];             // W^T W fp32 (atomic)
__device__ __align__(16) unsigned short g_Fhi[(size_t)NC * D_DIM];
__device__ __align__(16) unsigned short g_Flo[(size_t)NC * D_DIM];
__device__ __align__(16) unsigned short g_Ghi[(size_t)D_DIM * D_DIM];
__device__ __align__(16) unsigned short g_Glo[(size_t)D_DIM * D_DIM];
__device__ __align__(16) float g_P[(size_t)M_TOT * D_DIM];             // sf@G
__device__ __align__(16) float g_dist[(size_t)M_TOT * NC];
__device__ __align__(16) float g_ecoef[NC];                            // enorm - 2*(E@b)
__device__ __align__(16) float g_h[D_DIM];                             // W^T b
__device__ float g_colsum[NC];
__device__ int   g_idx[M_TOT];
__device__ float g_vqsum;
__device__ float g_bnorm;

// ---------------------------------------------------------------------------
__global__ void k_zero_all() {
    int idx = blockIdx.x * 256 + threadIdx.x;
    if (idx < NC * D_DIM) g_F[idx] = 0.f;
    int j = idx - NC * D_DIM;
    if (j >= 0 && j < D_DIM * D_DIM) g_G[j] = 0.f;
    if (idx < NC) g_colsum[idx] = 0.f;
    if (idx < D_DIM) g_h[idx] = 0.f;
    if (idx == 0) { g_vqsum = 0.f; g_bnorm = 0.f; }
}

// E -> ehi/elo (K-padded; pads stay zero from static init) + ecoef = ||e||^2 - 2 e.b
__global__ void __launch_bounds__(256) k_prep_E(const float* __restrict__ E,
                                                const float* __restrict__ b) {
    const int row = blockIdx.x;
    const int tid = threadIdx.x;
    const float4* src = (const float4*)(E + (size_t)row * BD);
    const float4* b4 = (const float4*)b;
    uint2* dh = (uint2*)(g_ehi + (size_t)row * KPAD);
    uint2* dl = (uint2*)(g_elo + (size_t)row * KPAD);
    float s = 0.f, s2 = 0.f;
    for (int i = tid; i < BD / 4; i += 256) {
        float4 v = src[i];
        float4 bv = b4[i];
        s  += v.x * v.x + v.y * v.y + v.z * v.z + v.w * v.w;
        s2 += v.x * bv.x + v.y * bv.y + v.z * bv.z + v.w * bv.w;
        unsigned short h0 = f2h(v.x), h1 = f2h(v.y), h2 = f2h(v.z), h3 = f2h(v.w);
        unsigned short l0 = f2h(v.x - h2f(h0)), l1 = f2h(v.y - h2f(h1));
        unsigned short l2 = f2h(v.z - h2f(h2)), l3 = f2h(v.w - h2f(h3));
        uint2 uh, ul;
        uh.x = (uint32_t)h0 | ((uint32_t)h1 << 16); uh.y = (uint32_t)h2 | ((uint32_t)h3 << 16);
        ul.x = (uint32_t)l0 | ((uint32_t)l1 << 16); ul.y = (uint32_t)l2 | ((uint32_t)l3 << 16);
        dh[i] = uh; dl[i] = ul;
    }
    __shared__ float sw[8], sw2[8];
    for (int o = 16; o > 0; o >>= 1) {
        s  += __shfl_down_sync(0xffffffffu, s, o);
        s2 += __shfl_down_sync(0xffffffffu, s2, o);
    }
    int lane = tid & 31, w = tid >> 5;
    if (lane == 0) { sw[w] = s; sw2[w] = s2; }
    __syncthreads();
    if (w == 0) {
        s  = (lane < 8) ? sw[lane] : 0.f;
        s2 = (lane < 8) ? sw2[lane] : 0.f;
        for (int o = 4; o > 0; o >>= 1) {
            s  += __shfl_down_sync(0xffffffffu, s, o);
            s2 += __shfl_down_sync(0xffffffffu, s2, o);
        }
        if (lane == 0) g_ecoef[row] = s - 2.f * s2;
    }
}

// fp32 -> hi/lo fp16 (contiguous)
__global__ void __launch_bounds__(256) k_split(const float* __restrict__ src,
                                               unsigned short* __restrict__ dh_,
                                               unsigned short* __restrict__ dl_) {
    int idx = blockIdx.x * 256 + threadIdx.x;
    float4 v = ((const float4*)src)[idx];
    unsigned short h0 = f2h(v.x), h1 = f2h(v.y), h2 = f2h(v.z), h3 = f2h(v.w);
    unsigned short l0 = f2h(v.x - h2f(h0)), l1 = f2h(v.y - h2f(h1));
    unsigned short l2 = f2h(v.z - h2f(h2)), l3 = f2h(v.w - h2f(h3));
    uint2 uh, ul;
    uh.x = (uint32_t)h0 | ((uint32_t)h1 << 16); uh.y = (uint32_t)h2 | ((uint32_t)h3 << 16);
    ul.x = (uint32_t)l0 | ((uint32_t)l1 << 16); ul.y = (uint32_t)l2 | ((uint32_t)l3 << 16);
    ((uint2*)dh_)[idx] = uh;
    ((uint2*)dl_)[idx] = ul;
}

// W [2700,256] -> W^T hi/lo [256, KPAD] via smem tile transpose
__global__ void __launch_bounds__(256) k_prep_W(const float* __restrict__ W) {
    __shared__ float tile[32][33];
    const int tx = threadIdx.x, ty = threadIdx.y;  // (32, 8)
    const int d0 = blockIdx.x * 32, n0 = blockIdx.y * 32;
#pragma unroll
    for (int i = 0; i < 4; i++) {
        int n = n0 + ty + i * 8;
        tile[ty + i * 8][tx] = (n < BD) ? W[(size_t)n * D_DIM + d0 + tx] : 0.f;
    }
    __syncthreads();
#pragma unroll
    for (int i = 0; i < 4; i++) {
        int d = d0 + ty + i * 8;
        int n = n0 + tx;
        float v = tile[tx][ty + i * 8];
        unsigned short h = f2h(v);
        g_wthi[(size_t)d * KPAD + n] = h;
        g_wtlo[(size_t)d * KPAD + n] = f2h(v - h2f(h));
    }
}

// h = W^T b (atomics) + ||b||^2
__global__ void __launch_bounds__(256) k_hb(const float* __restrict__ W,
                                            const float* __restrict__ b) {
    const int tid = threadIdx.x;
    const int n0 = blockIdx.x * 16;
    float hacc = 0.f;
    for (int r = 0; r < 16; r++) {
        int n = n0 + r;
        if (n < BD) hacc += __ldg(b + n) * W[(size_t)n * D_DIM + tid];
    }
    atomicAdd(&g_h[tid], hacc);
    if (tid < 16 && n0 + tid < BD) {
        float bv = b[n0 + tid];
        atomicAdd(&g_bnorm, bv * bv);
    }
}

// ---------------------------------------------------------------------------
// MMA mainloop: CTA tile 128(M) x 256(N), K-chunk 32, 8 warps (64x64).
// split passes: hi*hi + hi*lo + lo*hi (+ lo*lo when LOLO)
// ---------------------------------------------------------------------------
#define STAGE_BYTES 49152
#define SMEM_BYTES  (2 * STAGE_BYTES)

template <int LOLO>
__device__ __forceinline__ void mma_mainloop(
    const unsigned short* __restrict__ Ahi, const unsigned short* __restrict__ Alo, int ldA,
    const unsigned short* __restrict__ Bhi, const unsigned short* __restrict__ Blo, int ldB,
    int m0, int n0, int kbeg, int kend, uint32_t sb0, float (&acc)[4][8][4])
{
    const int tid = threadIdx.x;
    const int lane = tid & 31, wid = tid >> 5;
    const int wm = (wid & 1) * 64;
    const int wn = (wid >> 1) * 64;

    auto issue = [&](int c, int s) {
        const int k0 = c * 32;
        const uint32_t sb = sb0 + s * STAGE_BYTES;
#pragma unroll
        for (int t = 0; t < 2; t++) {
            int u = t * 256 + tid;
            int r = u >> 2, c8 = u & 3;
            uint32_t d = sb + r * 64 + ((c8 ^ ((r >> 1) & 3)) << 4);
            cp16(d,        Ahi + (size_t)(m0 + r) * ldA + k0 + c8 * 8);
            cp16(d + 8192, Alo + (size_t)(m0 + r) * ldA + k0 + c8 * 8);
        }
#pragma unroll
        for (int t = 0; t < 4; t++) {
            int u = t * 256 + tid;
            int r = u >> 2, c8 = u & 3;
            uint32_t d = sb + 16384 + r * 64 + ((c8 ^ ((r >> 1) & 3)) << 4);
            cp16(d,         Bhi + (size_t)(n0 + r) * ldB + k0 + c8 * 8);
            cp16(d + 16384, Blo + (size_t)(n0 + r) * ldB + k0 + c8 * 8);
        }
        CP_COMMIT();
    };

    issue(kbeg, 0);
    for (int c = kbeg; c < kend; c++) {
        const int s = (c - kbeg) & 1;
        const bool has_next = (c + 1 < kend);
        if (has_next) issue(c + 1, s ^ 1);
        if (has_next) asm volatile("cp.async.wait_group 1;" ::: "memory");
        else          asm volatile("cp.async.wait_group 0;" ::: "memory");
        __syncthreads();

        const uint32_t sb = sb0 + s * STAGE_BYTES;
#pragma unroll
        for (int kb = 0; kb < 2; kb++) {
            uint32_t ah[4][4], al[4][4];
#pragma unroll
            for (int mt = 0; mt < 4; mt++) {
                int row = wm + mt * 16 + (lane & 15);
                int c8 = kb * 2 + (lane >> 4);
                uint32_t a = sb + row * 64 + ((c8 ^ ((row >> 1) & 3)) << 4);
                LDSM_X4(ah[mt], a);
                LDSM_X4(al[mt], a + 8192);
            }
#pragma unroll
            for (int nb2 = 0; nb2 < 4; nb2++) {
                int rn = wn + nb2 * 16 + (lane & 7) + ((lane >> 4) << 3);
                int c8 = kb * 2 + ((lane >> 3) & 1);
                uint32_t baddr = sb + 16384 + rn * 64 + ((c8 ^ ((rn >> 1) & 3)) << 4);
                uint32_t bh[4], bl[4];
                LDSM_X4(bh, baddr);
                LDSM_X4(bl, baddr + 16384);
#pragma unroll
                for (int mt = 0; mt < 4; mt++) {
#pragma unroll
                    for (int j = 0; j < 2; j++) {
                        float* cc = acc[mt][nb2 * 2 + j];
                        mma16816(cc, ah[mt], bh + j * 2);
                        mma16816(cc, ah[mt], bl + j * 2);
                        mma16816(cc, al[mt], bh + j * 2);
                        if (LOLO) mma16816(cc, al[mt], bl + j * 2);
                    }
                }
            }
        }
        __syncthreads();
    }
}

#define ACC_DECL float acc[4][8][4]; \
    _Pragma("unroll") for (int a_ = 0; a_ < 4; a_++) \
    _Pragma("unroll") for (int b_ = 0; b_ < 8; b_++) \
    _Pragma("unroll") for (int c_ = 0; c_ < 4; c_++) acc[a_][b_][c_] = 0.f;

// F = E @ W  (M=1024 over E rows, N=256 over d, K=2752) split-K=2, atomic fp32
__global__ void __launch_bounds__(256, 1) gF_kernel() {
    extern __shared__ char smem[];
    uint32_t sb0 = smem_to_u32(smem);
    ACC_DECL;
    const int m0 = blockIdx.y * 128;
    const int kbeg = blockIdx.z * 43, kend = kbeg + 43;
    mma_mainloop<1>(g_ehi, g_elo, KPAD, g_wthi, g_wtlo, KPAD, m0, 0, kbeg, kend, sb0, acc);
    const int lane = threadIdx.x & 31, wid = threadIdx.x >> 5;
    const int wm = (wid & 1) * 64, wn = (wid >> 1) * 64;
    const int g = lane >> 2, t = lane & 3;
#pragma unroll
    for (int mt = 0; mt < 4; mt++)
#pragma unroll
        for (int nt = 0; nt < 8; nt++) {
            int col = wn + nt * 8 + t * 2;
#pragma unroll
            for (int h = 0; h < 2; h++) {
                int m = m0 + wm + mt * 16 + g + h * 8;
                atomicAdd(&g_F[(size_t)m * D_DIM + col],     acc[mt][nt][h * 2 + 0]);
                atomicAdd(&g_F[(size_t)m * D_DIM + col + 1], acc[mt][nt][h * 2 + 1]);
            }
        }
}

// G = W^T W  (M=256, N=256, K=2752) split-K=4, atomic fp32
__global__ void __launch_bounds__(256, 1) gG_kernel() {
    extern __shared__ char smem[];
    uint32_t sb0 = smem_to_u32(smem);
    ACC_DECL;
    const int m0 = blockIdx.y * 128;
    const int kbeg = blockIdx.z * 22;
    const int kend = (kbeg + 22 < 86) ? kbeg + 22 : 86;
    mma_mainloop<1>(g_wthi, g_wtlo, KPAD, g_wthi, g_wtlo, KPAD, m0, 0, kbeg, kend, sb0, acc);
    const int lane = threadIdx.x & 31, wid = threadIdx.x >> 5;
    const int wm = (wid & 1) * 64, wn = (wid >> 1) * 64;
    const int g = lane >> 2, t = lane & 3;
#pragma unroll
    for (int mt = 0; mt < 4; mt++)
#pragma unroll
        for (int nt = 0; nt < 8; nt++) {
            int col = wn + nt * 8 + t * 2;
#pragma unroll
            for (int h = 0; h < 2; h++) {
                int m = m0 + wm + mt * 16 + g + h * 8;
                atomicAdd(&g_G[(size_t)m * D_DIM + col],     acc[mt][nt][h * 2 + 0]);
                atomicAdd(&g_G[(size_t)m * D_DIM + col + 1], acc[mt][nt][h * 2 + 1]);
            }
        }
}

// split F (65536 float4) and G (16384 float4) into fp16 hi/lo
__global__ void __launch_bounds__(256) k_splitFG() {
    int idx = blockIdx.x * 256 + threadIdx.x;
    const float4* s;
    uint2 *dh, *dl;
    int j;
    if (idx < 65536) { s = (const float4*)g_F; dh = (uint2*)g_Fhi; dl = (uint2*)g_Flo; j = idx; }
    else { s = (const float4*)g_G; dh = (uint2*)g_Ghi; dl = (uint2*)g_Glo; j = idx - 65536; }
    float4 v = s[j];
    unsigned short h0 = f2h(v.x), h1 = f2h(v.y), h2 = f2h(v.z), h3 = f2h(v.w);
    unsigned short l0 = f2h(v.x - h2f(h0)), l1 = f2h(v.y - h2f(h1));
    unsigned short l2 = f2h(v.z - h2f(h2)), l3 = f2h(v.w - h2f(h3));
    uint2 uh, ul;
    uh.x = (uint32_t)h0 | ((uint32_t)h1 << 16); uh.y = (uint32_t)h2 | ((uint32_t)h3 << 16);
    ul.x = (uint32_t)l0 | ((uint32_t)l1 << 16); ul.y = (uint32_t)l2 | ((uint32_t)l3 << 16);
    dh[j] = uh; dl[j] = ul;
}

// S-GEMM: dist[m,c] = ecoef[c] - 2 * (sf @ F^T). grid (4, 64), K=8 chunks
__global__ void __launch_bounds__(256, 1) gS_kernel() {
    extern __shared__ char smem[];
    uint32_t sb0 = smem_to_u32(smem);
    ACC_DECL;
    const int m0 = blockIdx.y * 128, n0 = blockIdx.x * 256;
    mma_mainloop<0>(g_sfhi, g_sflo, D_DIM, g_Fhi, g_Flo, D_DIM, m0, n0, 0, 8, sb0, acc);
    const int lane = threadIdx.x & 31, wid = threadIdx.x >> 5;
    const int wm = (wid & 1) * 64, wn = (wid >> 1) * 64;
    const int g = lane >> 2, t = lane & 3;
#pragma unroll
    for (int mt = 0; mt < 4; mt++)
#pragma unroll
        for (int nt = 0; nt < 8; nt++) {
            int col = n0 + wn + nt * 8 + t * 2;
            float2 ec = *(const float2*)(g_ecoef + col);
#pragma unroll
            for (int h = 0; h < 2; h++) {
                int m = m0 + wm + mt * 16 + g + h * 8;
                float2 o;
                o.x = ec.x - 2.f * acc[mt][nt][h * 2 + 0];
                o.y = ec.y - 2.f * acc[mt][nt][h * 2 + 1];
                *(float2*)(g_dist + (size_t)m * NC + col) = o;
            }
        }
}

// P = sf @ G (symmetric G). grid (1, 64), K=8 chunks
__global__ void __launch_bounds__(256, 1) gP_kernel() {
    extern __shared__ char smem[];
    uint32_t sb0 = smem_to_u32(smem);
    ACC_DECL;
    const int m0 = blockIdx.y * 128;
    mma_mainloop<0>(g_sfhi, g_sflo, D_DIM, g_Ghi, g_Glo, D_DIM, m0, 0, 0, 8, sb0, acc);
    const int lane = threadIdx.x & 31, wid = threadIdx.x >> 5;
    const int wm = (wid & 1) * 64, wn = (wid >> 1) * 64;
    const int g = lane >> 2, t = lane & 3;
#pragma unroll
    for (int mt = 0; mt < 4; mt++)
#pragma unroll
        for (int nt = 0; nt < 8; nt++) {
            int col = wn + nt * 8 + t * 2;
#pragma unroll
            for (int h = 0; h < 2; h++) {
                int m = m0 + wm + mt * 16 + g + h * 8;
                float2 o;
                o.x = acc[mt][nt][h * 2 + 0];
                o.y = acc[mt][nt][h * 2 + 1];
                *(float2*)(g_P + (size_t)m * D_DIM + col) = o;
            }
        }
}

// znorm_m = sf . (P + 2h) + ||b||^2, accumulate sum into g_vqsum (warp per row)
__global__ void __launch_bounds__(256) k_znorm2(const float* __restrict__ sf) {
    const int row = blockIdx.x * 8 + (threadIdx.x >> 5);
    const int lane = threadIdx.x & 31;
    const float4* s4 = (const float4*)(sf + (size_t)row * D_DIM);
    const float4* p4 = (const float4*)(g_P + (size_t)row * D_DIM);
    const float4* h4 = (const float4*)g_h;
    float acc = 0.f;
#pragma unroll
    for (int i = 0; i < 2; i++) {
        int j = lane + i * 32;
        float4 a = s4[j], p = p4[j], hh = h4[j];
        acc += a.x * (p.x + 2.f * hh.x) + a.y * (p.y + 2.f * hh.y)
             + a.z * (p.z + 2.f * hh.z) + a.w * (p.w + 2.f * hh.w);
    }
    for (int o = 16; o > 0; o >>= 1) acc += __shfl_down_sync(0xffffffffu, acc, o);
    if (lane == 0) atomicAdd(&g_vqsum, acc + g_bnorm);
}

// ---------------------------------------------------------------------------
// Per-row argmin + softmax + fused column-sum + dmin accumulation (8 rows/blk)
// ---------------------------------------------------------------------------
__global__ void __launch_bounds__(256) k_row(float* __restrict__ out_idx) {
    const int tid = threadIdx.x, lane = tid & 31, w = tid >> 5;
    __shared__ float swv[8];
    __shared__ int   swi[8];
    __shared__ float s_min, s_sum;
    float cs0 = 0.f, cs1 = 0.f, cs2 = 0.f, cs3 = 0.f;
    float dmin_sum = 0.f;
    const int r0 = blockIdx.x * 8;
    for (int rr = 0; rr < 8; rr++) {
        const int row = r0 + rr;
        float4 v = ((const float4*)(g_dist + (size_t)row * NC))[tid];
        float vmin = v.x; int imin = tid * 4;
        if (v.y < vmin) { vmin = v.y; imin = tid * 4 + 1; }
        if (v.z < vmin) { vmin = v.z; imin = tid * 4 + 2; }
        if (v.w < vmin) { vmin = v.w; imin = tid * 4 + 3; }
        for (int o = 16; o > 0; o >>= 1) {
            float ov = __shfl_down_sync(0xffffffffu, vmin, o);
            int   oi = __shfl_down_sync(0xffffffffu, imin, o);
            if (ov < vmin || (ov == vmin && oi < imin)) { vmin = ov; imin = oi; }
        }
        if (lane == 0) { swv[w] = vmin; swi[w] = imin; }
        __syncthreads();
        if (w == 0) {
            vmin = (lane < 8) ? swv[lane] : 3.4e38f;
            imin = (lane < 8) ? swi[lane] : 0x7fffffff;
            for (int o = 4; o > 0; o >>= 1) {
                float ov = __shfl_down_sync(0xffffffffu, vmin, o);
                int   oi = __shfl_down_sync(0xffffffffu, imin, o);
                if (ov < vmin || (ov == vmin && oi < imin)) { vmin = ov; imin = oi; }
            }
            if (lane == 0) {
                s_min = vmin;
                g_idx[row] = imin;
                out_idx[row] = (float)imin;
            }
        }
        __syncthreads();
        const float mn = s_min;
        if (tid == 0) dmin_sum += mn;
        float e0 = expf(mn - v.x), e1 = expf(mn - v.y);
        float e2 = expf(mn - v.z), e3 = expf(mn - v.w);
        float ss = e0 + e1 + e2 + e3;
        for (int o = 16; o > 0; o >>= 1) ss += __shfl_down_sync(0xffffffffu, ss, o);
        if (lane == 0) swv[w] = ss;
        __syncthreads();
        if (w == 0) {
            ss = (lane < 8) ? swv[lane] : 0.f;
            for (int o = 4; o > 0; o >>= 1) ss += __shfl_down_sync(0xffffffffu, ss, o);
            if (lane == 0) s_sum = ss;
        }
        __syncthreads();
        const float inv = 1.f / s_sum;
        cs0 += e0 * inv; cs1 += e1 * inv; cs2 += e2 * inv; cs3 += e3 * inv;
        __syncthreads();
    }
    atomicAdd(&g_colsum[tid * 4 + 0], cs0);
    atomicAdd(&g_colsum[tid * 4 + 1], cs1);
    atomicAdd(&g_colsum[tid * 4 + 2], cs2);
    atomicAdd(&g_colsum[tid * 4 + 3], cs3);
    if (tid == 0) atomicAdd(&g_vqsum, dmin_sum);
}

// q_st = embed[idx] (pure gather)
__global__ void __launch_bounds__(256) k_gather(const float* __restrict__ E,
                                                float* __restrict__ out_q) {
    const int row = blockIdx.x;
    const int idx = g_idx[row];
    const float4* e4 = (const float4*)(E + (size_t)idx * BD);
    float4* o4 = (float4*)(out_q + (size_t)row * BD);
    for (int i = threadIdx.x; i < BD / 4; i += 256) o4[i] = e4[i];
}

__global__ void k_final(float* __restrict__ out) {
    const int tid = threadIdx.x;  // 1024
    float avg = g_colsum[tid] * (1.0f / (float)M_TOT);
    float t = -avg * logf(avg + EPS_ENT);
    __shared__ float sw[32];
    for (int o = 16; o > 0; o >>= 1) t += __shfl_down_sync(0xffffffffu, t, o);
    int lane = tid & 31, w = tid >> 5;
    if (lane == 0) sw[w] = t;
    __syncthreads();
    if (w == 0) {
        t = sw[lane];
        for (int o = 16; o > 0; o >>= 1) t += __shfl_down_sync(0xffffffffu, t, o);
        if (lane == 0) {
            const size_t OFF = (size_t)M_TOT * BD + M_TOT;
            out[OFF]     = g_vqsum * (1.0f / ((float)M_TOT * (float)BD));  // vq_loss
            out[OFF + 1] = t;                                              // entropy
        }
    }
}

// ---------------------------------------------------------------------------
extern "C" void kernel_launch(void* const* d_in, const int* in_sizes, int n_in,
                              void* d_out, int out_size) {
    const float* sf = (const float*)d_in[0];   // [128,64,256]
    const float* W  = (const float*)d_in[1];   // [2700,256]
    const float* b  = (const float*)d_in[2];   // [2700]
    const float* E  = (const float*)d_in[3];   // [1024,2700]
    float* out      = (float*)d_out;
    float* out_q    = out;
    float* out_idx  = out + (size_t)M_TOT * BD;

    cudaFuncSetAttribute(gF_kernel, cudaFuncAttributeMaxDynamicSharedMemorySize, SMEM_BYTES);
    cudaFuncSetAttribute(gG_kernel, cudaFuncAttributeMaxDynamicSharedMemorySize, SMEM_BYTES);
    cudaFuncSetAttribute(gS_kernel, cudaFuncAttributeMaxDynamicSharedMemorySize, SMEM_BYTES);
    cudaFuncSetAttribute(gP_kernel, cudaFuncAttributeMaxDynamicSharedMemorySize, SMEM_BYTES);

    unsigned short *sfhi, *sflo;
    cudaGetSymbolAddress((void**)&sfhi, g_sfhi);
    cudaGetSymbolAddress((void**)&sflo, g_sflo);

    k_zero_all<<<1290, 256>>>();
    k_prep_E<<<NC, 256>>>(E, b);
    k_split<<<(M_TOT * D_DIM / 4) / 256, 256>>>(sf, sfhi, sflo);
    k_prep_W<<<dim3(8, 86), dim3(32, 8)>>>(W);
    k_hb<<<169, 256>>>(W, b);
    gF_kernel<<<dim3(1, 8, 2), 256, SMEM_BYTES>>>();
    gG_kernel<<<dim3(1, 2, 4), 256, SMEM_BYTES>>>();
    k_splitFG<<<320, 256>>>();
    gS_kernel<<<dim3(4, 64), 256, SMEM_BYTES>>>();
    gP_kernel<<<dim3(1, 64), 256, SMEM_BYTES>>>();
    k_znorm2<<<M_TOT / 8, 256>>>(sf);
    k_row<<<M_TOT / 8, 256>>>(out_idx);
    k_gather<<<M_TOT, 256>>>(E, out_q);
    k_final<<<1, 1024>>>(out);
}

// round 5
// speedup vs baseline: 8.7893x; 1.7110x over previous
#include <cuda_runtime.h>
#include <cuda_fp16.h>
#include <math.h>
#include <stdint.h>

// Problem dims
#define M_TOT 8192
#define D_DIM 256
#define BD    2700
#define NC    1024
#define KPAD  2752          // 86 * 32
#define NFG   1280          // NC + D_DIM = 5 * 256
#define EPS_ENT 1e-8f

// ---------------------------------------------------------------------------
__device__ __forceinline__ uint32_t smem_to_u32(const void* p) {
    uint32_t a;
    asm("{ .reg .u64 t; cvta.to.shared.u64 t, %1; cvt.u32.u64 %0, t; }" : "=r"(a) : "l"(p));
    return a;
}
__device__ __forceinline__ unsigned short f2h(float x) {
    unsigned short r;
    asm("cvt.rn.f16.f32 %0, %1;" : "=h"(r) : "f"(x));
    return r;
}
__device__ __forceinline__ float h2f(unsigned short h) {
    float f;
    asm("cvt.f32.f16 %0, %1;" : "=f"(f) : "h"(h));
    return f;
}
#define LDSM_X4(R, addr) \
    asm volatile("ldmatrix.sync.aligned.m8n8.x4.shared.b16 {%0,%1,%2,%3}, [%4];" \
        : "=r"((R)[0]), "=r"((R)[1]), "=r"((R)[2]), "=r"((R)[3]) : "r"(addr))

__device__ __forceinline__ void mma16816(float* c, const uint32_t* a, const uint32_t* b) {
    asm volatile("mma.sync.aligned.m16n8k16.row.col.f32.f16.f16.f32 "
        "{%0,%1,%2,%3}, {%4,%5,%6,%7}, {%8,%9}, {%0,%1,%2,%3};"
        : "+f"(c[0]), "+f"(c[1]), "+f"(c[2]), "+f"(c[3])
        : "r"(a[0]), "r"(a[1]), "r"(a[2]), "r"(a[3]), "r"(b[0]), "r"(b[1]));
}
__device__ __forceinline__ void cp16(uint32_t dst, const void* src) {
    asm volatile("cp.async.cg.shared.global [%0], [%1], 16;" :: "r"(dst), "l"(src) : "memory");
}
#define CP_COMMIT() asm volatile("cp.async.commit_group;" ::: "memory")

// ---------------------------------------------------------------------------
// Scratch (device globals)
// ---------------------------------------------------------------------------
__device__ __align__(16) unsigned short g_ehi[(size_t)NC * KPAD];      // E split
__device__ __align__(16) unsigned short g_elo[(size_t)NC * KPAD];
__device__ __align__(16) unsigned short g_wthi[(size_t)D_DIM * KPAD];  // W^T split
__device__ __align__(16) unsigned short g_wtlo[(size_t)D_DIM * KPAD];
__device__ __align__(16) unsigned short g_sfhi[(size_t)M_TOT * D_DIM];
__device__ __align__(16) unsigned short g_sflo[(size_t)M_TOT * D_DIM];
__device__ __align__(16) float g_FG[(size_t)NFG * D_DIM];              // [F; G] fp32 (atomic)
__device__ __align__(16) unsigned short g_FGhi[(size_t)NFG * D_DIM];
__device__ __align__(16) unsigned short g_FGlo[(size_t)NFG * D_DIM];
__device__ __align__(16) float g_P[(size_t)M_TOT * D_DIM];             // sf@G
__device__ __align__(16) float g_dist[(size_t)M_TOT * NC];
__device__ __align__(16) float g_ecoef[NC];                            // enorm - 2*(E@b)
__device__ __align__(16) float g_h[D_DIM];                             // W^T b
__device__ float g_colsum[NC];
__device__ int   g_idx[M_TOT];
__device__ float g_vqsum;
__device__ float g_bnorm;

// ---------------------------------------------------------------------------
__global__ void k_zero_all() {
    int idx = blockIdx.x * 256 + threadIdx.x;
    if (idx < NFG * D_DIM) g_FG[idx] = 0.f;
    if (idx < NC) g_colsum[idx] = 0.f;
    if (idx < D_DIM) g_h[idx] = 0.f;
    if (idx == 0) { g_vqsum = 0.f; g_bnorm = 0.f; }
}

// E -> ehi/elo (K-padded; pads stay zero from static init) + ecoef = ||e||^2 - 2 e.b
__global__ void __launch_bounds__(256) k_prep_E(const float* __restrict__ E,
                                                const float* __restrict__ b) {
    const int row = blockIdx.x;
    const int tid = threadIdx.x;
    const float4* src = (const float4*)(E + (size_t)row * BD);
    const float4* b4 = (const float4*)b;
    uint2* dh = (uint2*)(g_ehi + (size_t)row * KPAD);
    uint2* dl = (uint2*)(g_elo + (size_t)row * KPAD);
    float s = 0.f, s2 = 0.f;
    for (int i = tid; i < BD / 4; i += 256) {
        float4 v = src[i];
        float4 bv = b4[i];
        s  += v.x * v.x + v.y * v.y + v.z * v.z + v.w * v.w;
        s2 += v.x * bv.x + v.y * bv.y + v.z * bv.z + v.w * bv.w;
        unsigned short h0 = f2h(v.x), h1 = f2h(v.y), h2 = f2h(v.z), h3 = f2h(v.w);
        unsigned short l0 = f2h(v.x - h2f(h0)), l1 = f2h(v.y - h2f(h1));
        unsigned short l2 = f2h(v.z - h2f(h2)), l3 = f2h(v.w - h2f(h3));
        uint2 uh, ul;
        uh.x = (uint32_t)h0 | ((uint32_t)h1 << 16); uh.y = (uint32_t)h2 | ((uint32_t)h3 << 16);
        ul.x = (uint32_t)l0 | ((uint32_t)l1 << 16); ul.y = (uint32_t)l2 | ((uint32_t)l3 << 16);
        dh[i] = uh; dl[i] = ul;
    }
    __shared__ float sw[8], sw2[8];
    for (int o = 16; o > 0; o >>= 1) {
        s  += __shfl_down_sync(0xffffffffu, s, o);
        s2 += __shfl_down_sync(0xffffffffu, s2, o);
    }
    int lane = tid & 31, w = tid >> 5;
    if (lane == 0) { sw[w] = s; sw2[w] = s2; }
    __syncthreads();
    if (w == 0) {
        s  = (lane < 8) ? sw[lane] : 0.f;
        s2 = (lane < 8) ? sw2[lane] : 0.f;
        for (int o = 4; o > 0; o >>= 1) {
            s  += __shfl_down_sync(0xffffffffu, s, o);
            s2 += __shfl_down_sync(0xffffffffu, s2, o);
        }
        if (lane == 0) g_ecoef[row] = s - 2.f * s2;
    }
}

// fp32 -> hi/lo fp16 (contiguous)
__global__ void __launch_bounds__(256) k_split(const float* __restrict__ src,
                                               unsigned short* __restrict__ dh_,
                                               unsigned short* __restrict__ dl_) {
    int idx = blockIdx.x * 256 + threadIdx.x;
    float4 v = ((const float4*)src)[idx];
    unsigned short h0 = f2h(v.x), h1 = f2h(v.y), h2 = f2h(v.z), h3 = f2h(v.w);
    unsigned short l0 = f2h(v.x - h2f(h0)), l1 = f2h(v.y - h2f(h1));
    unsigned short l2 = f2h(v.z - h2f(h2)), l3 = f2h(v.w - h2f(h3));
    uint2 uh, ul;
    uh.x = (uint32_t)h0 | ((uint32_t)h1 << 16); uh.y = (uint32_t)h2 | ((uint32_t)h3 << 16);
    ul.x = (uint32_t)l0 | ((uint32_t)l1 << 16); ul.y = (uint32_t)l2 | ((uint32_t)l3 << 16);
    ((uint2*)dh_)[idx] = uh;
    ((uint2*)dl_)[idx] = ul;
}

// W [2700,256] -> W^T hi/lo [256, KPAD] via smem tile transpose
__global__ void __launch_bounds__(256) k_prep_W(const float* __restrict__ W) {
    __shared__ float tile[32][33];
    const int tx = threadIdx.x, ty = threadIdx.y;  // (32, 8)
    const int d0 = blockIdx.x * 32, n0 = blockIdx.y * 32;
#pragma unroll
    for (int i = 0; i < 4; i++) {
        int n = n0 + ty + i * 8;
        tile[ty + i * 8][tx] = (n < BD) ? W[(size_t)n * D_DIM + d0 + tx] : 0.f;
    }
    __syncthreads();
#pragma unroll
    for (int i = 0; i < 4; i++) {
        int d = d0 + ty + i * 8;
        int n = n0 + tx;
        float v = tile[tx][ty + i * 8];
        unsigned short h = f2h(v);
        g_wthi[(size_t)d * KPAD + n] = h;
        g_wtlo[(size_t)d * KPAD + n] = f2h(v - h2f(h));
    }
}

// h = W^T b (atomics) + ||b||^2
__global__ void __launch_bounds__(256) k_hb(const float* __restrict__ W,
                                            const float* __restrict__ b) {
    const int tid = threadIdx.x;
    const int n0 = blockIdx.x * 16;
    float hacc = 0.f;
    for (int r = 0; r < 16; r++) {
        int n = n0 + r;
        if (n < BD) hacc += __ldg(b + n) * W[(size_t)n * D_DIM + tid];
    }
    atomicAdd(&g_h[tid], hacc);
    if (tid < 16 && n0 + tid < BD) {
        float bv = b[n0 + tid];
        atomicAdd(&g_bnorm, bv * bv);
    }
}

// ---------------------------------------------------------------------------
// MMA mainloop: CTA tile 128(M) x 256(N), K-chunk 32, 8 warps (64x64).
// split passes: hi*hi + hi*lo + lo*hi (+ lo*lo when LOLO)
// ---------------------------------------------------------------------------
#define STAGE_BYTES 49152
#define SMEM_BYTES  (2 * STAGE_BYTES)

template <int LOLO>
__device__ __forceinline__ void mma_mainloop(
    const unsigned short* __restrict__ Ahi, const unsigned short* __restrict__ Alo, int ldA,
    const unsigned short* __restrict__ Bhi, const unsigned short* __restrict__ Blo, int ldB,
    int m0, int n0, int kbeg, int kend, uint32_t sb0, float (&acc)[4][8][4])
{
    const int tid = threadIdx.x;
    const int lane = tid & 31, wid = tid >> 5;
    const int wm = (wid & 1) * 64;
    const int wn = (wid >> 1) * 64;

    auto issue = [&](int c, int s) {
        const int k0 = c * 32;
        const uint32_t sb = sb0 + s * STAGE_BYTES;
#pragma unroll
        for (int t = 0; t < 2; t++) {
            int u = t * 256 + tid;
            int r = u >> 2, c8 = u & 3;
            uint32_t d = sb + r * 64 + ((c8 ^ ((r >> 1) & 3)) << 4);
            cp16(d,        Ahi + (size_t)(m0 + r) * ldA + k0 + c8 * 8);
            cp16(d + 8192, Alo + (size_t)(m0 + r) * ldA + k0 + c8 * 8);
        }
#pragma unroll
        for (int t = 0; t < 4; t++) {
            int u = t * 256 + tid;
            int r = u >> 2, c8 = u & 3;
            uint32_t d = sb + 16384 + r * 64 + ((c8 ^ ((r >> 1) & 3)) << 4);
            cp16(d,         Bhi + (size_t)(n0 + r) * ldB + k0 + c8 * 8);
            cp16(d + 16384, Blo + (size_t)(n0 + r) * ldB + k0 + c8 * 8);
        }
        CP_COMMIT();
    };

    issue(kbeg, 0);
    for (int c = kbeg; c < kend; c++) {
        const int s = (c - kbeg) & 1;
        const bool has_next = (c + 1 < kend);
        if (has_next) issue(c + 1, s ^ 1);
        if (has_next) asm volatile("cp.async.wait_group 1;" ::: "memory");
        else          asm volatile("cp.async.wait_group 0;" ::: "memory");
        __syncthreads();

        const uint32_t sb = sb0 + s * STAGE_BYTES;
#pragma unroll
        for (int kb = 0; kb < 2; kb++) {
            uint32_t ah[4][4], al[4][4];
#pragma unroll
            for (int mt = 0; mt < 4; mt++) {
                int row = wm + mt * 16 + (lane & 15);
                int c8 = kb * 2 + (lane >> 4);
                uint32_t a = sb + row * 64 + ((c8 ^ ((row >> 1) & 3)) << 4);
                LDSM_X4(ah[mt], a);
                LDSM_X4(al[mt], a + 8192);
            }
#pragma unroll
            for (int nb2 = 0; nb2 < 4; nb2++) {
                int rn = wn + nb2 * 16 + (lane & 7) + ((lane >> 4) << 3);
                int c8 = kb * 2 + ((lane >> 3) & 1);
                uint32_t baddr = sb + 16384 + rn * 64 + ((c8 ^ ((rn >> 1) & 3)) << 4);
                uint32_t bh[4], bl[4];
                LDSM_X4(bh, baddr);
                LDSM_X4(bl, baddr + 16384);
#pragma unroll
                for (int mt = 0; mt < 4; mt++) {
#pragma unroll
                    for (int j = 0; j < 2; j++) {
                        float* cc = acc[mt][nb2 * 2 + j];
                        mma16816(cc, ah[mt], bh + j * 2);
                        mma16816(cc, ah[mt], bl + j * 2);
                        mma16816(cc, al[mt], bh + j * 2);
                        if (LOLO) mma16816(cc, al[mt], bl + j * 2);
                    }
                }
            }
        }
        __syncthreads();
    }
}

#define ACC_DECL float acc[4][8][4]; \
    _Pragma("unroll") for (int a_ = 0; a_ < 4; a_++) \
    _Pragma("unroll") for (int b_ = 0; b_ < 8; b_++) \
    _Pragma("unroll") for (int c_ = 0; c_ < 4; c_++) acc[a_][b_][c_] = 0.f;

// F = E @ W (rows 0..1023 of FG). grid (1, 8, 15): split-K 15 x 6 chunks
__global__ void __launch_bounds__(256, 1) gF_kernel() {
    extern __shared__ char smem[];
    uint32_t sb0 = smem_to_u32(smem);
    ACC_DECL;
    const int m0 = blockIdx.y * 128;
    const int kbeg = blockIdx.z * 6;
    int kend = kbeg + 6; if (kend > 86) kend = 86;
    mma_mainloop<1>(g_ehi, g_elo, KPAD, g_wthi, g_wtlo, KPAD, m0, 0, kbeg, kend, sb0, acc);
    const int lane = threadIdx.x & 31, wid = threadIdx.x >> 5;
    const int wm = (wid & 1) * 64, wn = (wid >> 1) * 64;
    const int g = lane >> 2, t = lane & 3;
#pragma unroll
    for (int mt = 0; mt < 4; mt++)
#pragma unroll
        for (int nt = 0; nt < 8; nt++) {
            int col = wn + nt * 8 + t * 2;
#pragma unroll
            for (int h = 0; h < 2; h++) {
                int m = m0 + wm + mt * 16 + g + h * 8;
                atomicAdd(&g_FG[(size_t)m * D_DIM + col],     acc[mt][nt][h * 2 + 0]);
                atomicAdd(&g_FG[(size_t)m * D_DIM + col + 1], acc[mt][nt][h * 2 + 1]);
            }
        }
}

// G = W^T W (rows 1024..1279 of FG). grid (1, 2, 43): split-K 43 x 2 chunks
__global__ void __launch_bounds__(256, 1) gG_kernel() {
    extern __shared__ char smem[];
    uint32_t sb0 = smem_to_u32(smem);
    ACC_DECL;
    const int m0 = blockIdx.y * 128;
    const int kbeg = blockIdx.z * 2, kend = kbeg + 2;
    mma_mainloop<1>(g_wthi, g_wtlo, KPAD, g_wthi, g_wtlo, KPAD, m0, 0, kbeg, kend, sb0, acc);
    const int lane = threadIdx.x & 31, wid = threadIdx.x >> 5;
    const int wm = (wid & 1) * 64, wn = (wid >> 1) * 64;
    const int g = lane >> 2, t = lane & 3;
    float* Gbase = g_FG + (size_t)NC * D_DIM;
#pragma unroll
    for (int mt = 0; mt < 4; mt++)
#pragma unroll
        for (int nt = 0; nt < 8; nt++) {
            int col = wn + nt * 8 + t * 2;
#pragma unroll
            for (int h = 0; h < 2; h++) {
                int m = m0 + wm + mt * 16 + g + h * 8;
                atomicAdd(&Gbase[(size_t)m * D_DIM + col],     acc[mt][nt][h * 2 + 0]);
                atomicAdd(&Gbase[(size_t)m * D_DIM + col + 1], acc[mt][nt][h * 2 + 1]);
            }
        }
}

// split FG (81920 float4) into fp16 hi/lo
__global__ void __launch_bounds__(256) k_splitFG() {
    int idx = blockIdx.x * 256 + threadIdx.x;
    float4 v = ((const float4*)g_FG)[idx];
    unsigned short h0 = f2h(v.x), h1 = f2h(v.y), h2 = f2h(v.z), h3 = f2h(v.w);
    unsigned short l0 = f2h(v.x - h2f(h0)), l1 = f2h(v.y - h2f(h1));
    unsigned short l2 = f2h(v.z - h2f(h2)), l3 = f2h(v.w - h2f(h3));
    uint2 uh, ul;
    uh.x = (uint32_t)h0 | ((uint32_t)h1 << 16); uh.y = (uint32_t)h2 | ((uint32_t)h3 << 16);
    ul.x = (uint32_t)l0 | ((uint32_t)l1 << 16); ul.y = (uint32_t)l2 | ((uint32_t)l3 << 16);
    ((uint2*)g_FGhi)[idx] = uh;
    ((uint2*)g_FGlo)[idx] = ul;
}

// Fused S-GEMM: cols 0..1023 -> dist = ecoef - 2*(sf@F^T); cols 1024..1279 -> P = sf@G
// grid (5, 64), K = 8 chunks of 32
__global__ void __launch_bounds__(256, 1) gS_kernel() {
    extern __shared__ char smem[];
    uint32_t sb0 = smem_to_u32(smem);
    ACC_DECL;
    const int m0 = blockIdx.y * 128, n0 = blockIdx.x * 256;
    mma_mainloop<0>(g_sfhi, g_sflo, D_DIM, g_FGhi, g_FGlo, D_DIM, m0, n0, 0, 8, sb0, acc);
    const int lane = threadIdx.x & 31, wid = threadIdx.x >> 5;
    const int wm = (wid & 1) * 64, wn = (wid >> 1) * 64;
    const int g = lane >> 2, t = lane & 3;
    if (blockIdx.x < 4) {
#pragma unroll
        for (int mt = 0; mt < 4; mt++)
#pragma unroll
            for (int nt = 0; nt < 8; nt++) {
                int col = n0 + wn + nt * 8 + t * 2;
                float2 ec = *(const float2*)(g_ecoef + col);
#pragma unroll
                for (int h = 0; h < 2; h++) {
                    int m = m0 + wm + mt * 16 + g + h * 8;
                    float2 o;
                    o.x = ec.x - 2.f * acc[mt][nt][h * 2 + 0];
                    o.y = ec.y - 2.f * acc[mt][nt][h * 2 + 1];
                    *(float2*)(g_dist + (size_t)m * NC + col) = o;
                }
            }
    } else {
#pragma unroll
        for (int mt = 0; mt < 4; mt++)
#pragma unroll
            for (int nt = 0; nt < 8; nt++) {
                int col = wn + nt * 8 + t * 2;   // P col 0..255
#pragma unroll
                for (int h = 0; h < 2; h++) {
                    int m = m0 + wm + mt * 16 + g + h * 8;
                    float2 o;
                    o.x = acc[mt][nt][h * 2 + 0];
                    o.y = acc[mt][nt][h * 2 + 1];
                    *(float2*)(g_P + (size_t)m * D_DIM + col) = o;
                }
            }
    }
}

// znorm_m = sf . (P + 2h) + ||b||^2, accumulate sum into g_vqsum (warp per row)
__global__ void __launch_bounds__(256) k_znorm2(const float* __restrict__ sf) {
    const int row = blockIdx.x * 8 + (threadIdx.x >> 5);
    const int lane = threadIdx.x & 31;
    const float4* s4 = (const float4*)(sf + (size_t)row * D_DIM);
    const float4* p4 = (const float4*)(g_P + (size_t)row * D_DIM);
    const float4* h4 = (const float4*)g_h;
    float acc = 0.f;
#pragma unroll
    for (int i = 0; i < 2; i++) {
        int j = lane + i * 32;
        float4 a = s4[j], p = p4[j], hh = h4[j];
        acc += a.x * (p.x + 2.f * hh.x) + a.y * (p.y + 2.f * hh.y)
             + a.z * (p.z + 2.f * hh.z) + a.w * (p.w + 2.f * hh.w);
    }
    for (int o = 16; o > 0; o >>= 1) acc += __shfl_down_sync(0xffffffffu, acc, o);
    if (lane == 0) atomicAdd(&g_vqsum, acc + g_bnorm);
}

// ---------------------------------------------------------------------------
// Per-row argmin + softmax + fused column-sum + dmin accumulation (8 rows/blk)
// ---------------------------------------------------------------------------
__global__ void __launch_bounds__(256) k_row(float* __restrict__ out_idx) {
    const int tid = threadIdx.x, lane = tid & 31, w = tid >> 5;
    __shared__ float swv[8];
    __shared__ int   swi[8];
    __shared__ float s_min, s_sum;
    float cs0 = 0.f, cs1 = 0.f, cs2 = 0.f, cs3 = 0.f;
    float dmin_sum = 0.f;
    const int r0 = blockIdx.x * 8;
    for (int rr = 0; rr < 8; rr++) {
        const int row = r0 + rr;
        float4 v = ((const float4*)(g_dist + (size_t)row * NC))[tid];
        float vmin = v.x; int imin = tid * 4;
        if (v.y < vmin) { vmin = v.y; imin = tid * 4 + 1; }
        if (v.z < vmin) { vmin = v.z; imin = tid * 4 + 2; }
        if (v.w < vmin) { vmin = v.w; imin = tid * 4 + 3; }
        for (int o = 16; o > 0; o >>= 1) {
            float ov = __shfl_down_sync(0xffffffffu, vmin, o);
            int   oi = __shfl_down_sync(0xffffffffu, imin, o);
            if (ov < vmin || (ov == vmin && oi < imin)) { vmin = ov; imin = oi; }
        }
        if (lane == 0) { swv[w] = vmin; swi[w] = imin; }
        __syncthreads();
        if (w == 0) {
            vmin = (lane < 8) ? swv[lane] : 3.4e38f;
            imin = (lane < 8) ? swi[lane] : 0x7fffffff;
            for (int o = 4; o > 0; o >>= 1) {
                float ov = __shfl_down_sync(0xffffffffu, vmin, o);
                int   oi = __shfl_down_sync(0xffffffffu, imin, o);
                if (ov < vmin || (ov == vmin && oi < imin)) { vmin = ov; imin = oi; }
            }
            if (lane == 0) {
                s_min = vmin;
                g_idx[row] = imin;
                out_idx[row] = (float)imin;
            }
        }
        __syncthreads();
        const float mn = s_min;
        if (tid == 0) dmin_sum += mn;
        float e0 = expf(mn - v.x), e1 = expf(mn - v.y);
        float e2 = expf(mn - v.z), e3 = expf(mn - v.w);
        float ss = e0 + e1 + e2 + e3;
        for (int o = 16; o > 0; o >>= 1) ss += __shfl_down_sync(0xffffffffu, ss, o);
        if (lane == 0) swv[w] = ss;
        __syncthreads();
        if (w == 0) {
            ss = (lane < 8) ? swv[lane] : 0.f;
            for (int o = 4; o > 0; o >>= 1) ss += __shfl_down_sync(0xffffffffu, ss, o);
            if (lane == 0) s_sum = ss;
        }
        __syncthreads();
        const float inv = 1.f / s_sum;
        cs0 += e0 * inv; cs1 += e1 * inv; cs2 += e2 * inv; cs3 += e3 * inv;
        __syncthreads();
    }
    atomicAdd(&g_colsum[tid * 4 + 0], cs0);
    atomicAdd(&g_colsum[tid * 4 + 1], cs1);
    atomicAdd(&g_colsum[tid * 4 + 2], cs2);
    atomicAdd(&g_colsum[tid * 4 + 3], cs3);
    if (tid == 0) atomicAdd(&g_vqsum, dmin_sum);
}

// q_st = embed[idx] (pure gather)
__global__ void __launch_bounds__(256) k_gather(const float* __restrict__ E,
                                                float* __restrict__ out_q) {
    const int row = blockIdx.x;
    const int idx = g_idx[row];
    const float4* e4 = (const float4*)(E + (size_t)idx * BD);
    float4* o4 = (float4*)(out_q + (size_t)row * BD);
    for (int i = threadIdx.x; i < BD / 4; i += 256) o4[i] = e4[i];
}

__global__ void k_final(float* __restrict__ out) {
    const int tid = threadIdx.x;  // 1024
    float avg = g_colsum[tid] * (1.0f / (float)M_TOT);
    float t = -avg * logf(avg + EPS_ENT);
    __shared__ float sw[32];
    for (int o = 16; o > 0; o >>= 1) t += __shfl_down_sync(0xffffffffu, t, o);
    int lane = tid & 31, w = tid >> 5;
    if (lane == 0) sw[w] = t;
    __syncthreads();
    if (w == 0) {
        t = sw[lane];
        for (int o = 16; o > 0; o >>= 1) t += __shfl_down_sync(0xffffffffu, t, o);
        if (lane == 0) {
            const size_t OFF = (size_t)M_TOT * BD + M_TOT;
            out[OFF]     = g_vqsum * (1.0f / ((float)M_TOT * (float)BD));  // vq_loss
            out[OFF + 1] = t;                                              // entropy
        }
    }
}

// ---------------------------------------------------------------------------
extern "C" void kernel_launch(void* const* d_in, const int* in_sizes, int n_in,
                              void* d_out, int out_size) {
    const float* sf = (const float*)d_in[0];   // [128,64,256]
    const float* W  = (const float*)d_in[1];   // [2700,256]
    const float* b  = (const float*)d_in[2];   // [2700]
    const float* E  = (const float*)d_in[3];   // [1024,2700]
    float* out      = (float*)d_out;
    float* out_q    = out;
    float* out_idx  = out + (size_t)M_TOT * BD;

    cudaFuncSetAttribute(gF_kernel, cudaFuncAttributeMaxDynamicSharedMemorySize, SMEM_BYTES);
    cudaFuncSetAttribute(gG_kernel, cudaFuncAttributeMaxDynamicSharedMemorySize, SMEM_BYTES);
    cudaFuncSetAttribute(gS_kernel, cudaFuncAttributeMaxDynamicSharedMemorySize, SMEM_BYTES);

    unsigned short *sfhi, *sflo;
    cudaGetSymbolAddress((void**)&sfhi, g_sfhi);
    cudaGetSymbolAddress((void**)&sflo, g_sflo);

    k_zero_all<<<1280, 256>>>();
    k_prep_E<<<NC, 256>>>(E, b);
    k_split<<<(M_TOT * D_DIM / 4) / 256, 256>>>(sf, sfhi, sflo);
    k_prep_W<<<dim3(8, 86), dim3(32, 8)>>>(W);
    k_hb<<<169, 256>>>(W, b);
    gF_kernel<<<dim3(1, 8, 15), 256, SMEM_BYTES>>>();
    gG_kernel<<<dim3(1, 2, 43), 256, SMEM_BYTES>>>();
    k_splitFG<<<320, 256>>>();
    gS_kernel<<<dim3(5, 64), 256, SMEM_BYTES>>>();
    k_znorm2<<<M_TOT / 8, 256>>>(sf);
    k_row<<<M_TOT / 8, 256>>>(out_idx);
    k_gather<<<M_TOT, 256>>>(E, out_q);
    k_final<<<1, 1024>>>(out);
}

// round 6
// speedup vs baseline: 10.3377x; 1.1762x over previous
#include <cuda_runtime.h>
#include <cuda_fp16.h>
#include <math.h>
#include <stdint.h>

// Problem dims
#define M_TOT 8192
#define D_DIM 256
#define BD    2700
#define NC    1024
#define KPAD  2752          // 86 * 32
#define NFG   1280          // NC + D_DIM = 5 * 256
#define EPS_ENT 1e-8f

// ---------------------------------------------------------------------------
__device__ __forceinline__ uint32_t smem_to_u32(const void* p) {
    uint32_t a;
    asm("{ .reg .u64 t; cvta.to.shared.u64 t, %1; cvt.u32.u64 %0, t; }" : "=r"(a) : "l"(p));
    return a;
}
__device__ __forceinline__ unsigned short f2h(float x) {
    unsigned short r;
    asm("cvt.rn.f16.f32 %0, %1;" : "=h"(r) : "f"(x));
    return r;
}
__device__ __forceinline__ float h2f(unsigned short h) {
    float f;
    asm("cvt.f32.f16 %0, %1;" : "=f"(f) : "h"(h));
    return f;
}
#define LDSM_X4(R, addr) \
    asm volatile("ldmatrix.sync.aligned.m8n8.x4.shared.b16 {%0,%1,%2,%3}, [%4];" \
        : "=r"((R)[0]), "=r"((R)[1]), "=r"((R)[2]), "=r"((R)[3]) : "r"(addr))

__device__ __forceinline__ void mma16816(float* c, const uint32_t* a, const uint32_t* b) {
    asm volatile("mma.sync.aligned.m16n8k16.row.col.f32.f16.f16.f32 "
        "{%0,%1,%2,%3}, {%4,%5,%6,%7}, {%8,%9}, {%0,%1,%2,%3};"
        : "+f"(c[0]), "+f"(c[1]), "+f"(c[2]), "+f"(c[3])
        : "r"(a[0]), "r"(a[1]), "r"(a[2]), "r"(a[3]), "r"(b[0]), "r"(b[1]));
}
__device__ __forceinline__ void cp16(uint32_t dst, const void* src) {
    asm volatile("cp.async.cg.shared.global [%0], [%1], 16;" :: "r"(dst), "l"(src) : "memory");
}
#define CP_COMMIT() asm volatile("cp.async.commit_group;" ::: "memory")

// ---------------------------------------------------------------------------
// Scratch (device globals)
// ---------------------------------------------------------------------------
__device__ __align__(16) unsigned short g_ehi[(size_t)NC * KPAD];      // E split
__device__ __align__(16) unsigned short g_elo[(size_t)NC * KPAD];
__device__ __align__(16) unsigned short g_wthi[(size_t)D_DIM * KPAD];  // W^T split
__device__ __align__(16) unsigned short g_wtlo[(size_t)D_DIM * KPAD];
__device__ __align__(16) unsigned short g_sfhi[(size_t)M_TOT * D_DIM];
__device__ __align__(16) unsigned short g_sflo[(size_t)M_TOT * D_DIM];
__device__ __align__(16) float g_FG[(size_t)NFG * D_DIM];              // [F; G] fp32 (atomic)
__device__ __align__(16) unsigned short g_FGhi[(size_t)NFG * D_DIM];
__device__ __align__(16) unsigned short g_FGlo[(size_t)NFG * D_DIM];
__device__ __align__(16) float g_P[(size_t)M_TOT * D_DIM];             // sf@G
__device__ __align__(16) float g_dist[(size_t)M_TOT * NC];
__device__ __align__(16) float g_ecoef[NC];                            // enorm - 2*(E@b)
__device__ __align__(16) float g_h[D_DIM];                             // W^T b
__device__ float g_colsum[NC];
__device__ int   g_idx[M_TOT];
__device__ float g_vqsum;
__device__ float g_bnorm;

// ===========================================================================
// PREP kernel: role-dispatched block ranges
//   [0, 1280)            zero g_FG
//   [1280, 2304)         prep_E (1024 rows)
//   [2304, 4352)         split sf (2048 blocks)
//   [4352, 5040)         prep_W transpose+split (688 = 8 x 86)
//   [5040, 5041)         misc: zero colsum/h/vqsum, bnorm
// ===========================================================================
#define PREP_ZERO_END  1280
#define PREP_E_END     2304
#define PREP_SF_END    4352
#define PREP_W_END     5040
#define PREP_BLOCKS    5041

__global__ void __launch_bounds__(256) k_prep(const float* __restrict__ E,
                                              const float* __restrict__ b,
                                              const float* __restrict__ sf,
                                              const float* __restrict__ W) {
    const int bid = blockIdx.x;
    const int tid = threadIdx.x;

    if (bid < PREP_ZERO_END) {
        g_FG[bid * 256 + tid] = 0.f;
        return;
    }
    if (bid < PREP_E_END) {
        // prep_E: row = local, split + ecoef
        const int row = bid - PREP_ZERO_END;
        const float4* src = (const float4*)(E + (size_t)row * BD);
        const float4* b4 = (const float4*)b;
        uint2* dh = (uint2*)(g_ehi + (size_t)row * KPAD);
        uint2* dl = (uint2*)(g_elo + (size_t)row * KPAD);
        float s = 0.f, s2 = 0.f;
        for (int i = tid; i < BD / 4; i += 256) {
            float4 v = src[i];
            float4 bv = b4[i];
            s  += v.x * v.x + v.y * v.y + v.z * v.z + v.w * v.w;
            s2 += v.x * bv.x + v.y * bv.y + v.z * bv.z + v.w * bv.w;
            unsigned short h0 = f2h(v.x), h1 = f2h(v.y), h2 = f2h(v.z), h3 = f2h(v.w);
            unsigned short l0 = f2h(v.x - h2f(h0)), l1 = f2h(v.y - h2f(h1));
            unsigned short l2 = f2h(v.z - h2f(h2)), l3 = f2h(v.w - h2f(h3));
            uint2 uh, ul;
            uh.x = (uint32_t)h0 | ((uint32_t)h1 << 16); uh.y = (uint32_t)h2 | ((uint32_t)h3 << 16);
            ul.x = (uint32_t)l0 | ((uint32_t)l1 << 16); ul.y = (uint32_t)l2 | ((uint32_t)l3 << 16);
            dh[i] = uh; dl[i] = ul;
        }
        __shared__ float sw[8], sw2[8];
        for (int o = 16; o > 0; o >>= 1) {
            s  += __shfl_down_sync(0xffffffffu, s, o);
            s2 += __shfl_down_sync(0xffffffffu, s2, o);
        }
        int lane = tid & 31, w = tid >> 5;
        if (lane == 0) { sw[w] = s; sw2[w] = s2; }
        __syncthreads();
        if (w == 0) {
            s  = (lane < 8) ? sw[lane] : 0.f;
            s2 = (lane < 8) ? sw2[lane] : 0.f;
            for (int o = 4; o > 0; o >>= 1) {
                s  += __shfl_down_sync(0xffffffffu, s, o);
                s2 += __shfl_down_sync(0xffffffffu, s2, o);
            }
            if (lane == 0) g_ecoef[row] = s - 2.f * s2;
        }
        return;
    }
    if (bid < PREP_SF_END) {
        // split sf
        int idx = (bid - PREP_E_END) * 256 + tid;
        float4 v = ((const float4*)sf)[idx];
        unsigned short h0 = f2h(v.x), h1 = f2h(v.y), h2 = f2h(v.z), h3 = f2h(v.w);
        unsigned short l0 = f2h(v.x - h2f(h0)), l1 = f2h(v.y - h2f(h1));
        unsigned short l2 = f2h(v.z - h2f(h2)), l3 = f2h(v.w - h2f(h3));
        uint2 uh, ul;
        uh.x = (uint32_t)h0 | ((uint32_t)h1 << 16); uh.y = (uint32_t)h2 | ((uint32_t)h3 << 16);
        ul.x = (uint32_t)l0 | ((uint32_t)l1 << 16); ul.y = (uint32_t)l2 | ((uint32_t)l3 << 16);
        ((uint2*)g_sfhi)[idx] = uh;
        ((uint2*)g_sflo)[idx] = ul;
        return;
    }
    if (bid < PREP_W_END) {
        // prep_W: transpose 32x32 tile + split
        __shared__ float tile[32][33];
        const int l = bid - PREP_SF_END;
        const int d0 = (l & 7) * 32, n0 = (l >> 3) * 32;
        const int tx = tid & 31, ty = tid >> 5;
#pragma unroll
        for (int i = 0; i < 4; i++) {
            int n = n0 + ty + i * 8;
            tile[ty + i * 8][tx] = (n < BD) ? W[(size_t)n * D_DIM + d0 + tx] : 0.f;
        }
        __syncthreads();
#pragma unroll
        for (int i = 0; i < 4; i++) {
            int d = d0 + ty + i * 8;
            int n = n0 + tx;
            float v = tile[tx][ty + i * 8];
            unsigned short h = f2h(v);
            g_wthi[(size_t)d * KPAD + n] = h;
            g_wtlo[(size_t)d * KPAD + n] = f2h(v - h2f(h));
        }
        return;
    }
    // misc block: zero colsum, g_h, vqsum; compute bnorm
    {
#pragma unroll
        for (int i = 0; i < 4; i++) g_colsum[tid + i * 256] = 0.f;
        g_h[tid] = 0.f;
        if (tid == 0) g_vqsum = 0.f;
        float s = 0.f;
        for (int i = tid; i < BD; i += 256) { float bv = b[i]; s += bv * bv; }
        __shared__ float sw[8];
        for (int o = 16; o > 0; o >>= 1) s += __shfl_down_sync(0xffffffffu, s, o);
        int lane = tid & 31, w = tid >> 5;
        if (lane == 0) sw[w] = s;
        __syncthreads();
        if (w == 0) {
            s = (lane < 8) ? sw[lane] : 0.f;
            for (int o = 4; o > 0; o >>= 1) s += __shfl_down_sync(0xffffffffu, s, o);
            if (lane == 0) g_bnorm = s;
        }
    }
}

// ---------------------------------------------------------------------------
// MMA mainloop: CTA tile 128(M) x 256(N), K-chunk 32, 8 warps (64x64).
// ---------------------------------------------------------------------------
#define STAGE_BYTES 49152
#define SMEM_BYTES  (2 * STAGE_BYTES)

template <int LOLO>
__device__ __forceinline__ void mma_mainloop(
    const unsigned short* __restrict__ Ahi, const unsigned short* __restrict__ Alo, int ldA,
    const unsigned short* __restrict__ Bhi, const unsigned short* __restrict__ Blo, int ldB,
    int m0, int n0, int kbeg, int kend, uint32_t sb0, float (&acc)[4][8][4])
{
    const int tid = threadIdx.x;
    const int lane = tid & 31, wid = tid >> 5;
    const int wm = (wid & 1) * 64;
    const int wn = (wid >> 1) * 64;

    auto issue = [&](int c, int s) {
        const int k0 = c * 32;
        const uint32_t sb = sb0 + s * STAGE_BYTES;
#pragma unroll
        for (int t = 0; t < 2; t++) {
            int u = t * 256 + tid;
            int r = u >> 2, c8 = u & 3;
            uint32_t d = sb + r * 64 + ((c8 ^ ((r >> 1) & 3)) << 4);
            cp16(d,        Ahi + (size_t)(m0 + r) * ldA + k0 + c8 * 8);
            cp16(d + 8192, Alo + (size_t)(m0 + r) * ldA + k0 + c8 * 8);
        }
#pragma unroll
        for (int t = 0; t < 4; t++) {
            int u = t * 256 + tid;
            int r = u >> 2, c8 = u & 3;
            uint32_t d = sb + 16384 + r * 64 + ((c8 ^ ((r >> 1) & 3)) << 4);
            cp16(d,         Bhi + (size_t)(n0 + r) * ldB + k0 + c8 * 8);
            cp16(d + 16384, Blo + (size_t)(n0 + r) * ldB + k0 + c8 * 8);
        }
        CP_COMMIT();
    };

    issue(kbeg, 0);
    for (int c = kbeg; c < kend; c++) {
        const int s = (c - kbeg) & 1;
        const bool has_next = (c + 1 < kend);
        if (has_next) issue(c + 1, s ^ 1);
        if (has_next) asm volatile("cp.async.wait_group 1;" ::: "memory");
        else          asm volatile("cp.async.wait_group 0;" ::: "memory");
        __syncthreads();

        const uint32_t sb = sb0 + s * STAGE_BYTES;
#pragma unroll
        for (int kb = 0; kb < 2; kb++) {
            uint32_t ah[4][4], al[4][4];
#pragma unroll
            for (int mt = 0; mt < 4; mt++) {
                int row = wm + mt * 16 + (lane & 15);
                int c8 = kb * 2 + (lane >> 4);
                uint32_t a = sb + row * 64 + ((c8 ^ ((row >> 1) & 3)) << 4);
                LDSM_X4(ah[mt], a);
                LDSM_X4(al[mt], a + 8192);
            }
#pragma unroll
            for (int nb2 = 0; nb2 < 4; nb2++) {
                int rn = wn + nb2 * 16 + (lane & 7) + ((lane >> 4) << 3);
                int c8 = kb * 2 + ((lane >> 3) & 1);
                uint32_t baddr = sb + 16384 + rn * 64 + ((c8 ^ ((rn >> 1) & 3)) << 4);
                uint32_t bh[4], bl[4];
                LDSM_X4(bh, baddr);
                LDSM_X4(bl, baddr + 16384);
#pragma unroll
                for (int mt = 0; mt < 4; mt++) {
#pragma unroll
                    for (int j = 0; j < 2; j++) {
                        float* cc = acc[mt][nb2 * 2 + j];
                        mma16816(cc, ah[mt], bh + j * 2);
                        mma16816(cc, ah[mt], bl + j * 2);
                        mma16816(cc, al[mt], bh + j * 2);
                        if (LOLO) mma16816(cc, al[mt], bl + j * 2);
                    }
                }
            }
        }
        __syncthreads();
    }
}

#define ACC_DECL float acc[4][8][4]; \
    _Pragma("unroll") for (int a_ = 0; a_ < 4; a_++) \
    _Pragma("unroll") for (int b_ = 0; b_ < 8; b_++) \
    _Pragma("unroll") for (int c_ = 0; c_ < 4; c_++) acc[a_][b_][c_] = 0.f;

// ===========================================================================
// gFG kernel: roles
//   [0, 120)    F = E@W    (8 m-tiles x 15 split-K of 6 chunks)
//   [120, 206)  G = W^T W  (2 m-tiles x 43 split-K of 2 chunks)
//   [206, 375)  h = W^T b  (atomics, 169 blocks x 16 rows)
// ===========================================================================
#define GFG_F_END 120
#define GFG_G_END 206
#define GFG_BLOCKS 375

__global__ void __launch_bounds__(256, 1) gFG_kernel(const float* __restrict__ W,
                                                     const float* __restrict__ b) {
    const int bid = blockIdx.x;
    if (bid >= GFG_G_END) {
        // h = W^T b
        const int tid = threadIdx.x;
        const int n0 = (bid - GFG_G_END) * 16;
        float hacc = 0.f;
        for (int r = 0; r < 16; r++) {
            int n = n0 + r;
            if (n < BD) hacc += __ldg(b + n) * W[(size_t)n * D_DIM + tid];
        }
        atomicAdd(&g_h[tid], hacc);
        return;
    }
    extern __shared__ char smem[];
    uint32_t sb0 = smem_to_u32(smem);
    ACC_DECL;
    const int lane = threadIdx.x & 31, wid = threadIdx.x >> 5;
    const int wm = (wid & 1) * 64, wn = (wid >> 1) * 64;
    const int g = lane >> 2, t = lane & 3;

    if (bid < GFG_F_END) {
        const int m0 = (bid / 15) * 128;
        const int kbeg = (bid % 15) * 6;
        int kend = kbeg + 6; if (kend > 86) kend = 86;
        mma_mainloop<1>(g_ehi, g_elo, KPAD, g_wthi, g_wtlo, KPAD, m0, 0, kbeg, kend, sb0, acc);
#pragma unroll
        for (int mt = 0; mt < 4; mt++)
#pragma unroll
            for (int nt = 0; nt < 8; nt++) {
                int col = wn + nt * 8 + t * 2;
#pragma unroll
                for (int h = 0; h < 2; h++) {
                    int m = m0 + wm + mt * 16 + g + h * 8;
                    atomicAdd(&g_FG[(size_t)m * D_DIM + col],     acc[mt][nt][h * 2 + 0]);
                    atomicAdd(&g_FG[(size_t)m * D_DIM + col + 1], acc[mt][nt][h * 2 + 1]);
                }
            }
    } else {
        const int l = bid - GFG_F_END;
        const int m0 = (l / 43) * 128;
        const int kbeg = (l % 43) * 2, kend = kbeg + 2;
        mma_mainloop<1>(g_wthi, g_wtlo, KPAD, g_wthi, g_wtlo, KPAD, m0, 0, kbeg, kend, sb0, acc);
        float* Gbase = g_FG + (size_t)NC * D_DIM;
#pragma unroll
        for (int mt = 0; mt < 4; mt++)
#pragma unroll
            for (int nt = 0; nt < 8; nt++) {
                int col = wn + nt * 8 + t * 2;
#pragma unroll
                for (int h = 0; h < 2; h++) {
                    int m = m0 + wm + mt * 16 + g + h * 8;
                    atomicAdd(&Gbase[(size_t)m * D_DIM + col],     acc[mt][nt][h * 2 + 0]);
                    atomicAdd(&Gbase[(size_t)m * D_DIM + col + 1], acc[mt][nt][h * 2 + 1]);
                }
            }
    }
}

// split FG (81920 float4) into fp16 hi/lo
__global__ void __launch_bounds__(256) k_splitFG() {
    int idx = blockIdx.x * 256 + threadIdx.x;
    float4 v = ((const float4*)g_FG)[idx];
    unsigned short h0 = f2h(v.x), h1 = f2h(v.y), h2 = f2h(v.z), h3 = f2h(v.w);
    unsigned short l0 = f2h(v.x - h2f(h0)), l1 = f2h(v.y - h2f(h1));
    unsigned short l2 = f2h(v.z - h2f(h2)), l3 = f2h(v.w - h2f(h3));
    uint2 uh, ul;
    uh.x = (uint32_t)h0 | ((uint32_t)h1 << 16); uh.y = (uint32_t)h2 | ((uint32_t)h3 << 16);
    ul.x = (uint32_t)l0 | ((uint32_t)l1 << 16); ul.y = (uint32_t)l2 | ((uint32_t)l3 << 16);
    ((uint2*)g_FGhi)[idx] = uh;
    ((uint2*)g_FGlo)[idx] = ul;
}

// Fused S-GEMM: cols 0..1023 -> dist = ecoef - 2*(sf@F^T); cols 1024..1279 -> P = sf@G
__global__ void __launch_bounds__(256, 1) gS_kernel() {
    extern __shared__ char smem[];
    uint32_t sb0 = smem_to_u32(smem);
    ACC_DECL;
    const int m0 = blockIdx.y * 128, n0 = blockIdx.x * 256;
    mma_mainloop<0>(g_sfhi, g_sflo, D_DIM, g_FGhi, g_FGlo, D_DIM, m0, n0, 0, 8, sb0, acc);
    const int lane = threadIdx.x & 31, wid = threadIdx.x >> 5;
    const int wm = (wid & 1) * 64, wn = (wid >> 1) * 64;
    const int g = lane >> 2, t = lane & 3;
    if (blockIdx.x < 4) {
#pragma unroll
        for (int mt = 0; mt < 4; mt++)
#pragma unroll
            for (int nt = 0; nt < 8; nt++) {
                int col = n0 + wn + nt * 8 + t * 2;
                float2 ec = *(const float2*)(g_ecoef + col);
#pragma unroll
                for (int h = 0; h < 2; h++) {
                    int m = m0 + wm + mt * 16 + g + h * 8;
                    float2 o;
                    o.x = ec.x - 2.f * acc[mt][nt][h * 2 + 0];
                    o.y = ec.y - 2.f * acc[mt][nt][h * 2 + 1];
                    *(float2*)(g_dist + (size_t)m * NC + col) = o;
                }
            }
    } else {
#pragma unroll
        for (int mt = 0; mt < 4; mt++)
#pragma unroll
            for (int nt = 0; nt < 8; nt++) {
                int col = wn + nt * 8 + t * 2;
#pragma unroll
                for (int h = 0; h < 2; h++) {
                    int m = m0 + wm + mt * 16 + g + h * 8;
                    float2 o;
                    o.x = acc[mt][nt][h * 2 + 0];
                    o.y = acc[mt][nt][h * 2 + 1];
                    *(float2*)(g_P + (size_t)m * D_DIM + col) = o;
                }
            }
    }
}

// ===========================================================================
// rowz kernel: roles
//   [0, 1024)     k_row: argmin + softmax + colsum + dmin (8 rows/blk)
//   [1024, 2048)  znorm2: vqsum partials (8 rows/blk)
// ===========================================================================
__global__ void __launch_bounds__(256) k_rowz(float* __restrict__ out_idx,
                                              const float* __restrict__ sf) {
    const int bid = blockIdx.x;
    const int tid = threadIdx.x, lane = tid & 31, w = tid >> 5;
    if (bid >= 1024) {
        const int row = (bid - 1024) * 8 + w;
        const float4* s4 = (const float4*)(sf + (size_t)row * D_DIM);
        const float4* p4 = (const float4*)(g_P + (size_t)row * D_DIM);
        const float4* h4 = (const float4*)g_h;
        float acc = 0.f;
#pragma unroll
        for (int i = 0; i < 2; i++) {
            int j = lane + i * 32;
            float4 a = s4[j], p = p4[j], hh = h4[j];
            acc += a.x * (p.x + 2.f * hh.x) + a.y * (p.y + 2.f * hh.y)
                 + a.z * (p.z + 2.f * hh.z) + a.w * (p.w + 2.f * hh.w);
        }
        for (int o = 16; o > 0; o >>= 1) acc += __shfl_down_sync(0xffffffffu, acc, o);
        if (lane == 0) atomicAdd(&g_vqsum, acc + g_bnorm);
        return;
    }
    __shared__ float swv[8];
    __shared__ int   swi[8];
    __shared__ float s_min, s_sum;
    float cs0 = 0.f, cs1 = 0.f, cs2 = 0.f, cs3 = 0.f;
    float dmin_sum = 0.f;
    const int r0 = bid * 8;
    for (int rr = 0; rr < 8; rr++) {
        const int row = r0 + rr;
        float4 v = ((const float4*)(g_dist + (size_t)row * NC))[tid];
        float vmin = v.x; int imin = tid * 4;
        if (v.y < vmin) { vmin = v.y; imin = tid * 4 + 1; }
        if (v.z < vmin) { vmin = v.z; imin = tid * 4 + 2; }
        if (v.w < vmin) { vmin = v.w; imin = tid * 4 + 3; }
        for (int o = 16; o > 0; o >>= 1) {
            float ov = __shfl_down_sync(0xffffffffu, vmin, o);
            int   oi = __shfl_down_sync(0xffffffffu, imin, o);
            if (ov < vmin || (ov == vmin && oi < imin)) { vmin = ov; imin = oi; }
        }
        if (lane == 0) { swv[w] = vmin; swi[w] = imin; }
        __syncthreads();
        if (w == 0) {
            vmin = (lane < 8) ? swv[lane] : 3.4e38f;
            imin = (lane < 8) ? swi[lane] : 0x7fffffff;
            for (int o = 4; o > 0; o >>= 1) {
                float ov = __shfl_down_sync(0xffffffffu, vmin, o);
                int   oi = __shfl_down_sync(0xffffffffu, imin, o);
                if (ov < vmin || (ov == vmin && oi < imin)) { vmin = ov; imin = oi; }
            }
            if (lane == 0) {
                s_min = vmin;
                g_idx[row] = imin;
                out_idx[row] = (float)imin;
            }
        }
        __syncthreads();
        const float mn = s_min;
        if (tid == 0) dmin_sum += mn;
        float e0 = expf(mn - v.x), e1 = expf(mn - v.y);
        float e2 = expf(mn - v.z), e3 = expf(mn - v.w);
        float ss = e0 + e1 + e2 + e3;
        for (int o = 16; o > 0; o >>= 1) ss += __shfl_down_sync(0xffffffffu, ss, o);
        if (lane == 0) swv[w] = ss;
        __syncthreads();
        if (w == 0) {
            ss = (lane < 8) ? swv[lane] : 0.f;
            for (int o = 4; o > 0; o >>= 1) ss += __shfl_down_sync(0xffffffffu, ss, o);
            if (lane == 0) s_sum = ss;
        }
        __syncthreads();
        const float inv = 1.f / s_sum;
        cs0 += e0 * inv; cs1 += e1 * inv; cs2 += e2 * inv; cs3 += e3 * inv;
        __syncthreads();
    }
    atomicAdd(&g_colsum[tid * 4 + 0], cs0);
    atomicAdd(&g_colsum[tid * 4 + 1], cs1);
    atomicAdd(&g_colsum[tid * 4 + 2], cs2);
    atomicAdd(&g_colsum[tid * 4 + 3], cs3);
    if (tid == 0) atomicAdd(&g_vqsum, dmin_sum);
}

// ===========================================================================
// gather + final: blocks [0,8192) gather q_st; block 8192 computes scalars
// ===========================================================================
__global__ void __launch_bounds__(256) k_gatherfinal(const float* __restrict__ E,
                                                     float* __restrict__ out) {
    const int bid = blockIdx.x;
    const int tid = threadIdx.x;
    if (bid < M_TOT) {
        const int idx = g_idx[bid];
        const float4* e4 = (const float4*)(E + (size_t)idx * BD);
        float4* o4 = (float4*)(out + (size_t)bid * BD);
        for (int i = tid; i < BD / 4; i += 256) o4[i] = e4[i];
        return;
    }
    // final scalars
    float t = 0.f;
#pragma unroll
    for (int i = 0; i < 4; i++) {
        float avg = g_colsum[tid + i * 256] * (1.0f / (float)M_TOT);
        t += -avg * logf(avg + EPS_ENT);
    }
    __shared__ float sw[8];
    for (int o = 16; o > 0; o >>= 1) t += __shfl_down_sync(0xffffffffu, t, o);
    int lane = tid & 31, w = tid >> 5;
    if (lane == 0) sw[w] = t;
    __syncthreads();
    if (w == 0) {
        t = (lane < 8) ? sw[lane] : 0.f;
        for (int o = 4; o > 0; o >>= 1) t += __shfl_down_sync(0xffffffffu, t, o);
        if (lane == 0) {
            const size_t OFF = (size_t)M_TOT * BD + M_TOT;
            out[OFF]     = g_vqsum * (1.0f / ((float)M_TOT * (float)BD));  // vq_loss
            out[OFF + 1] = t;                                              // entropy
        }
    }
}

// ---------------------------------------------------------------------------
extern "C" void kernel_launch(void* const* d_in, const int* in_sizes, int n_in,
                              void* d_out, int out_size) {
    const float* sf = (const float*)d_in[0];   // [128,64,256]
    const float* W  = (const float*)d_in[1];   // [2700,256]
    const float* b  = (const float*)d_in[2];   // [2700]
    const float* E  = (const float*)d_in[3];   // [1024,2700]
    float* out      = (float*)d_out;
    float* out_idx  = out + (size_t)M_TOT * BD;

    cudaFuncSetAttribute(gFG_kernel, cudaFuncAttributeMaxDynamicSharedMemorySize, SMEM_BYTES);
    cudaFuncSetAttribute(gS_kernel,  cudaFuncAttributeMaxDynamicSharedMemorySize, SMEM_BYTES);

    k_prep<<<PREP_BLOCKS, 256>>>(E, b, sf, W);
    gFG_kernel<<<GFG_BLOCKS, 256, SMEM_BYTES>>>(W, b);
    k_splitFG<<<320, 256>>>();
    gS_kernel<<<dim3(5, 64), 256, SMEM_BYTES>>>();
    k_rowz<<<2048, 256>>>(out_idx, sf);
    k_gatherfinal<<<M_TOT + 1, 256>>>(E, out);
}

// round 7
// speedup vs baseline: 11.5463x; 1.1169x over previous
#include <cuda_runtime.h>
#include <cuda_fp16.h>
#include <math.h>
#include <stdint.h>

// Problem dims
#define M_TOT 8192
#define D_DIM 256
#define BD    2700
#define NC    1024
#define KPAD  2752          // 86 * 32
#define NFG   1280          // NC + D_DIM = 5 * 256
#define EPS_ENT 1e-8f

// ---------------------------------------------------------------------------
__device__ __forceinline__ uint32_t smem_to_u32(const void* p) {
    uint32_t a;
    asm("{ .reg .u64 t; cvta.to.shared.u64 t, %1; cvt.u32.u64 %0, t; }" : "=r"(a) : "l"(p));
    return a;
}
__device__ __forceinline__ unsigned short f2h(float x) {
    unsigned short r;
    asm("cvt.rn.f16.f32 %0, %1;" : "=h"(r) : "f"(x));
    return r;
}
__device__ __forceinline__ float h2f(unsigned short h) {
    float f;
    asm("cvt.f32.f16 %0, %1;" : "=f"(f) : "h"(h));
    return f;
}
#define LDSM_X4(R, addr) \
    asm volatile("ldmatrix.sync.aligned.m8n8.x4.shared.b16 {%0,%1,%2,%3}, [%4];" \
        : "=r"((R)[0]), "=r"((R)[1]), "=r"((R)[2]), "=r"((R)[3]) : "r"(addr))

__device__ __forceinline__ void mma16816(float* c, const uint32_t* a, const uint32_t* b) {
    asm volatile("mma.sync.aligned.m16n8k16.row.col.f32.f16.f16.f32 "
        "{%0,%1,%2,%3}, {%4,%5,%6,%7}, {%8,%9}, {%0,%1,%2,%3};"
        : "+f"(c[0]), "+f"(c[1]), "+f"(c[2]), "+f"(c[3])
        : "r"(a[0]), "r"(a[1]), "r"(a[2]), "r"(a[3]), "r"(b[0]), "r"(b[1]));
}
__device__ __forceinline__ void cp16(uint32_t dst, const void* src) {
    asm volatile("cp.async.cg.shared.global [%0], [%1], 16;" :: "r"(dst), "l"(src) : "memory");
}
#define CP_COMMIT() asm volatile("cp.async.commit_group;" ::: "memory")

// ---------------------------------------------------------------------------
// Scratch (device globals)
// ---------------------------------------------------------------------------
__device__ __align__(16) unsigned short g_ehi[(size_t)NC * KPAD];
__device__ __align__(16) unsigned short g_elo[(size_t)NC * KPAD];
__device__ __align__(16) unsigned short g_wthi[(size_t)D_DIM * KPAD];
__device__ __align__(16) unsigned short g_wtlo[(size_t)D_DIM * KPAD];
__device__ __align__(16) unsigned short g_sfhi[(size_t)M_TOT * D_DIM];
__device__ __align__(16) unsigned short g_sflo[(size_t)M_TOT * D_DIM];
__device__ __align__(16) float g_FG[(size_t)NFG * D_DIM];
__device__ __align__(16) unsigned short g_FGhi[(size_t)NFG * D_DIM];
__device__ __align__(16) unsigned short g_FGlo[(size_t)NFG * D_DIM];
__device__ __align__(16) float g_P[(size_t)M_TOT * D_DIM];
__device__ __align__(16) float g_dist[(size_t)M_TOT * NC];
__device__ __align__(16) float g_ecoef[NC];
__device__ __align__(16) float g_h[D_DIM];
__device__ float g_colsum[NC];
__device__ int   g_idx[M_TOT];
__device__ float g_vqsum;
__device__ float g_bnorm;

// ===========================================================================
// PREP kernel (unchanged roles)
// ===========================================================================
#define PREP_ZERO_END  1280
#define PREP_E_END     2304
#define PREP_SF_END    4352
#define PREP_W_END     5040
#define PREP_BLOCKS    5041

__global__ void __launch_bounds__(256) k_prep(const float* __restrict__ E,
                                              const float* __restrict__ b,
                                              const float* __restrict__ sf,
                                              const float* __restrict__ W) {
    const int bid = blockIdx.x;
    const int tid = threadIdx.x;

    if (bid < PREP_ZERO_END) {
        g_FG[bid * 256 + tid] = 0.f;
        return;
    }
    if (bid < PREP_E_END) {
        const int row = bid - PREP_ZERO_END;
        const float4* src = (const float4*)(E + (size_t)row * BD);
        const float4* b4 = (const float4*)b;
        uint2* dh = (uint2*)(g_ehi + (size_t)row * KPAD);
        uint2* dl = (uint2*)(g_elo + (size_t)row * KPAD);
        float s = 0.f, s2 = 0.f;
        for (int i = tid; i < BD / 4; i += 256) {
            float4 v = src[i];
            float4 bv = b4[i];
            s  += v.x * v.x + v.y * v.y + v.z * v.z + v.w * v.w;
            s2 += v.x * bv.x + v.y * bv.y + v.z * bv.z + v.w * bv.w;
            unsigned short h0 = f2h(v.x), h1 = f2h(v.y), h2 = f2h(v.z), h3 = f2h(v.w);
            unsigned short l0 = f2h(v.x - h2f(h0)), l1 = f2h(v.y - h2f(h1));
            unsigned short l2 = f2h(v.z - h2f(h2)), l3 = f2h(v.w - h2f(h3));
            uint2 uh, ul;
            uh.x = (uint32_t)h0 | ((uint32_t)h1 << 16); uh.y = (uint32_t)h2 | ((uint32_t)h3 << 16);
            ul.x = (uint32_t)l0 | ((uint32_t)l1 << 16); ul.y = (uint32_t)l2 | ((uint32_t)l3 << 16);
            dh[i] = uh; dl[i] = ul;
        }
        __shared__ float sw[8], sw2[8];
        for (int o = 16; o > 0; o >>= 1) {
            s  += __shfl_down_sync(0xffffffffu, s, o);
            s2 += __shfl_down_sync(0xffffffffu, s2, o);
        }
        int lane = tid & 31, w = tid >> 5;
        if (lane == 0) { sw[w] = s; sw2[w] = s2; }
        __syncthreads();
        if (w == 0) {
            s  = (lane < 8) ? sw[lane] : 0.f;
            s2 = (lane < 8) ? sw2[lane] : 0.f;
            for (int o = 4; o > 0; o >>= 1) {
                s  += __shfl_down_sync(0xffffffffu, s, o);
                s2 += __shfl_down_sync(0xffffffffu, s2, o);
            }
            if (lane == 0) g_ecoef[row] = s - 2.f * s2;
        }
        return;
    }
    if (bid < PREP_SF_END) {
        int idx = (bid - PREP_E_END) * 256 + tid;
        float4 v = ((const float4*)sf)[idx];
        unsigned short h0 = f2h(v.x), h1 = f2h(v.y), h2 = f2h(v.z), h3 = f2h(v.w);
        unsigned short l0 = f2h(v.x - h2f(h0)), l1 = f2h(v.y - h2f(h1));
        unsigned short l2 = f2h(v.z - h2f(h2)), l3 = f2h(v.w - h2f(h3));
        uint2 uh, ul;
        uh.x = (uint32_t)h0 | ((uint32_t)h1 << 16); uh.y = (uint32_t)h2 | ((uint32_t)h3 << 16);
        ul.x = (uint32_t)l0 | ((uint32_t)l1 << 16); ul.y = (uint32_t)l2 | ((uint32_t)l3 << 16);
        ((uint2*)g_sfhi)[idx] = uh;
        ((uint2*)g_sflo)[idx] = ul;
        return;
    }
    if (bid < PREP_W_END) {
        __shared__ float tile[32][33];
        const int l = bid - PREP_SF_END;
        const int d0 = (l & 7) * 32, n0 = (l >> 3) * 32;
        const int tx = tid & 31, ty = tid >> 5;
#pragma unroll
        for (int i = 0; i < 4; i++) {
            int n = n0 + ty + i * 8;
            tile[ty + i * 8][tx] = (n < BD) ? W[(size_t)n * D_DIM + d0 + tx] : 0.f;
        }
        __syncthreads();
#pragma unroll
        for (int i = 0; i < 4; i++) {
            int d = d0 + ty + i * 8;
            int n = n0 + tx;
            float v = tile[tx][ty + i * 8];
            unsigned short h = f2h(v);
            g_wthi[(size_t)d * KPAD + n] = h;
            g_wtlo[(size_t)d * KPAD + n] = f2h(v - h2f(h));
        }
        return;
    }
    {
#pragma unroll
        for (int i = 0; i < 4; i++) g_colsum[tid + i * 256] = 0.f;
        g_h[tid] = 0.f;
        if (tid == 0) g_vqsum = 0.f;
        float s = 0.f;
        for (int i = tid; i < BD; i += 256) { float bv = b[i]; s += bv * bv; }
        __shared__ float sw[8];
        for (int o = 16; o > 0; o >>= 1) s += __shfl_down_sync(0xffffffffu, s, o);
        int lane = tid & 31, w = tid >> 5;
        if (lane == 0) sw[w] = s;
        __syncthreads();
        if (w == 0) {
            s = (lane < 8) ? sw[lane] : 0.f;
            for (int o = 4; o > 0; o >>= 1) s += __shfl_down_sync(0xffffffffu, s, o);
            if (lane == 0) g_bnorm = s;
        }
    }
}

// ---------------------------------------------------------------------------
// MMA mainloop: CTA tile 128(M) x 128(N), K-chunk 32, 8 warps (warp 64x32).
// acc[4 mt][4 n8][4] = 64 regs -> 2 CTAs/SM.
// SMEM stage: Ahi@0 Alo@8192 Bhi@16384 Blo@24576 (32 KB); double buffered.
// ---------------------------------------------------------------------------
#define STAGE_BYTES 32768
#define SMEM_BYTES  (2 * STAGE_BYTES)

template <int LOLO>
__device__ __forceinline__ void mma_mainloop(
    const unsigned short* __restrict__ Ahi, const unsigned short* __restrict__ Alo, int ldA,
    const unsigned short* __restrict__ Bhi, const unsigned short* __restrict__ Blo, int ldB,
    int m0, int n0, int kbeg, int kend, uint32_t sb0, float (&acc)[4][4][4])
{
    const int tid = threadIdx.x;
    const int lane = tid & 31, wid = tid >> 5;
    const int wm = (wid & 1) * 64;
    const int wn = (wid >> 1) * 32;

    auto issue = [&](int c, int s) {
        const int k0 = c * 32;
        const uint32_t sb = sb0 + s * STAGE_BYTES;
#pragma unroll
        for (int t = 0; t < 2; t++) {
            int u = t * 256 + tid;
            int r = u >> 2, c8 = u & 3;
            uint32_t off = r * 64 + ((c8 ^ ((r >> 1) & 3)) << 4);
            cp16(sb + off,         Ahi + (size_t)(m0 + r) * ldA + k0 + c8 * 8);
            cp16(sb + off + 8192,  Alo + (size_t)(m0 + r) * ldA + k0 + c8 * 8);
            cp16(sb + off + 16384, Bhi + (size_t)(n0 + r) * ldB + k0 + c8 * 8);
            cp16(sb + off + 24576, Blo + (size_t)(n0 + r) * ldB + k0 + c8 * 8);
        }
        CP_COMMIT();
    };

    issue(kbeg, 0);
    for (int c = kbeg; c < kend; c++) {
        const int s = (c - kbeg) & 1;
        const bool has_next = (c + 1 < kend);
        if (has_next) issue(c + 1, s ^ 1);
        if (has_next) asm volatile("cp.async.wait_group 1;" ::: "memory");
        else          asm volatile("cp.async.wait_group 0;" ::: "memory");
        __syncthreads();

        const uint32_t sb = sb0 + s * STAGE_BYTES;
#pragma unroll
        for (int kb = 0; kb < 2; kb++) {
            uint32_t ah[4][4], al[4][4], bh[8], bl[8];
#pragma unroll
            for (int mt = 0; mt < 4; mt++) {
                int row = wm + mt * 16 + (lane & 15);
                int c8 = kb * 2 + (lane >> 4);
                uint32_t a = sb + row * 64 + ((c8 ^ ((row >> 1) & 3)) << 4);
                LDSM_X4(ah[mt], a);
                LDSM_X4(al[mt], a + 8192);
            }
#pragma unroll
            for (int nb = 0; nb < 2; nb++) {
                int rn = wn + nb * 16 + (lane & 7) + ((lane >> 4) << 3);
                int c8 = kb * 2 + ((lane >> 3) & 1);
                uint32_t baddr = sb + 16384 + rn * 64 + ((c8 ^ ((rn >> 1) & 3)) << 4);
                LDSM_X4(bh + nb * 4, baddr);
                LDSM_X4(bl + nb * 4, baddr + 8192);
            }
#pragma unroll
            for (int mt = 0; mt < 4; mt++) {
#pragma unroll
                for (int n8 = 0; n8 < 4; n8++) {
                    float* cc = acc[mt][n8];
                    mma16816(cc, ah[mt], bh + n8 * 2);
                    mma16816(cc, ah[mt], bl + n8 * 2);
                    mma16816(cc, al[mt], bh + n8 * 2);
                    if (LOLO) mma16816(cc, al[mt], bl + n8 * 2);
                }
            }
        }
        __syncthreads();
    }
}

#define ACC_DECL float acc[4][4][4]; \
    _Pragma("unroll") for (int a_ = 0; a_ < 4; a_++) \
    _Pragma("unroll") for (int b_ = 0; b_ < 4; b_++) \
    _Pragma("unroll") for (int c_ = 0; c_ < 4; c_++) acc[a_][b_][c_] = 0.f;

// ===========================================================================
// gFG kernel: roles
//   [0, 240)    F = E@W    (8 m x 2 n x 15 split-K of 6 chunks)
//   [240, 412)  G = W^T W  (2 m x 2 n x 43 split-K of 2 chunks)
//   [412, 581)  h = W^T b
// ===========================================================================
#define GFG_F_END 240
#define GFG_G_END 412
#define GFG_BLOCKS 581

__global__ void __launch_bounds__(256, 2) gFG_kernel(const float* __restrict__ W,
                                                     const float* __restrict__ b) {
    const int bid = blockIdx.x;
    if (bid >= GFG_G_END) {
        const int tid = threadIdx.x;
        const int n0 = (bid - GFG_G_END) * 16;
        float hacc = 0.f;
        for (int r = 0; r < 16; r++) {
            int n = n0 + r;
            if (n < BD) hacc += __ldg(b + n) * W[(size_t)n * D_DIM + tid];
        }
        atomicAdd(&g_h[tid], hacc);
        return;
    }
    extern __shared__ char smem[];
    uint32_t sb0 = smem_to_u32(smem);
    ACC_DECL;
    const int lane = threadIdx.x & 31, wid = threadIdx.x >> 5;
    const int wm = (wid & 1) * 64, wn = (wid >> 1) * 32;
    const int g = lane >> 2, t = lane & 3;

    int m0, n0, kbeg, kend;
    const unsigned short *Ah, *Al;
    float* outbase;
    if (bid < GFG_F_END) {
        m0 = (bid / 30) * 128;
        int rem = bid % 30;
        n0 = (rem / 15) * 128;
        kbeg = (rem % 15) * 6;
        kend = kbeg + 6; if (kend > 86) kend = 86;
        Ah = g_ehi; Al = g_elo;
        outbase = g_FG;
    } else {
        int l = bid - GFG_F_END;
        m0 = (l / 86) * 128;
        int rem = l % 86;
        n0 = (rem / 43) * 128;
        kbeg = (rem % 43) * 2;
        kend = kbeg + 2;
        Ah = g_wthi; Al = g_wtlo;
        outbase = g_FG + (size_t)NC * D_DIM;
    }
    mma_mainloop<1>(Ah, Al, KPAD, g_wthi, g_wtlo, KPAD, m0, n0, kbeg, kend, sb0, acc);
#pragma unroll
    for (int mt = 0; mt < 4; mt++)
#pragma unroll
        for (int n8 = 0; n8 < 4; n8++) {
            int col = n0 + wn + n8 * 8 + t * 2;
#pragma unroll
            for (int h = 0; h < 2; h++) {
                int m = m0 + wm + mt * 16 + g + h * 8;
                atomicAdd(&outbase[(size_t)m * D_DIM + col],     acc[mt][n8][h * 2 + 0]);
                atomicAdd(&outbase[(size_t)m * D_DIM + col + 1], acc[mt][n8][h * 2 + 1]);
            }
        }
}

// split FG (81920 float4) into fp16 hi/lo
__global__ void __launch_bounds__(256) k_splitFG() {
    int idx = blockIdx.x * 256 + threadIdx.x;
    float4 v = ((const float4*)g_FG)[idx];
    unsigned short h0 = f2h(v.x), h1 = f2h(v.y), h2 = f2h(v.z), h3 = f2h(v.w);
    unsigned short l0 = f2h(v.x - h2f(h0)), l1 = f2h(v.y - h2f(h1));
    unsigned short l2 = f2h(v.z - h2f(h2)), l3 = f2h(v.w - h2f(h3));
    uint2 uh, ul;
    uh.x = (uint32_t)h0 | ((uint32_t)h1 << 16); uh.y = (uint32_t)h2 | ((uint32_t)h3 << 16);
    ul.x = (uint32_t)l0 | ((uint32_t)l1 << 16); ul.y = (uint32_t)l2 | ((uint32_t)l3 << 16);
    ((uint2*)g_FGhi)[idx] = uh;
    ((uint2*)g_FGlo)[idx] = ul;
}

// Fused S-GEMM: n-tiles 0..7 -> dist = ecoef - 2*(sf@F^T); 8..9 -> P = sf@G
// grid (10, 64)
__global__ void __launch_bounds__(256, 2) gS_kernel() {
    extern __shared__ char smem[];
    uint32_t sb0 = smem_to_u32(smem);
    ACC_DECL;
    const int m0 = blockIdx.y * 128, n0 = blockIdx.x * 128;
    mma_mainloop<0>(g_sfhi, g_sflo, D_DIM, g_FGhi, g_FGlo, D_DIM, m0, n0, 0, 8, sb0, acc);
    const int lane = threadIdx.x & 31, wid = threadIdx.x >> 5;
    const int wm = (wid & 1) * 64, wn = (wid >> 1) * 32;
    const int g = lane >> 2, t = lane & 3;
    if (blockIdx.x < 8) {
#pragma unroll
        for (int mt = 0; mt < 4; mt++)
#pragma unroll
            for (int n8 = 0; n8 < 4; n8++) {
                int col = n0 + wn + n8 * 8 + t * 2;
                float2 ec = *(const float2*)(g_ecoef + col);
#pragma unroll
                for (int h = 0; h < 2; h++) {
                    int m = m0 + wm + mt * 16 + g + h * 8;
                    float2 o;
                    o.x = ec.x - 2.f * acc[mt][n8][h * 2 + 0];
                    o.y = ec.y - 2.f * acc[mt][n8][h * 2 + 1];
                    *(float2*)(g_dist + (size_t)m * NC + col) = o;
                }
            }
    } else {
        const int p0 = (blockIdx.x - 8) * 128;
#pragma unroll
        for (int mt = 0; mt < 4; mt++)
#pragma unroll
            for (int n8 = 0; n8 < 4; n8++) {
                int col = p0 + wn + n8 * 8 + t * 2;
#pragma unroll
                for (int h = 0; h < 2; h++) {
                    int m = m0 + wm + mt * 16 + g + h * 8;
                    float2 o;
                    o.x = acc[mt][n8][h * 2 + 0];
                    o.y = acc[mt][n8][h * 2 + 1];
                    *(float2*)(g_P + (size_t)m * D_DIM + col) = o;
                }
            }
    }
}

// ===========================================================================
// rowz kernel (unchanged)
// ===========================================================================
__global__ void __launch_bounds__(256) k_rowz(float* __restrict__ out_idx,
                                              const float* __restrict__ sf) {
    const int bid = blockIdx.x;
    const int tid = threadIdx.x, lane = tid & 31, w = tid >> 5;
    if (bid >= 1024) {
        const int row = (bid - 1024) * 8 + w;
        const float4* s4 = (const float4*)(sf + (size_t)row * D_DIM);
        const float4* p4 = (const float4*)(g_P + (size_t)row * D_DIM);
        const float4* h4 = (const float4*)g_h;
        float acc = 0.f;
#pragma unroll
        for (int i = 0; i < 2; i++) {
            int j = lane + i * 32;
            float4 a = s4[j], p = p4[j], hh = h4[j];
            acc += a.x * (p.x + 2.f * hh.x) + a.y * (p.y + 2.f * hh.y)
                 + a.z * (p.z + 2.f * hh.z) + a.w * (p.w + 2.f * hh.w);
        }
        for (int o = 16; o > 0; o >>= 1) acc += __shfl_down_sync(0xffffffffu, acc, o);
        if (lane == 0) atomicAdd(&g_vqsum, acc + g_bnorm);
        return;
    }
    __shared__ float swv[8];
    __shared__ int   swi[8];
    __shared__ float s_min, s_sum;
    float cs0 = 0.f, cs1 = 0.f, cs2 = 0.f, cs3 = 0.f;
    float dmin_sum = 0.f;
    const int r0 = bid * 8;
    for (int rr = 0; rr < 8; rr++) {
        const int row = r0 + rr;
        float4 v = ((const float4*)(g_dist + (size_t)row * NC))[tid];
        float vmin = v.x; int imin = tid * 4;
        if (v.y < vmin) { vmin = v.y; imin = tid * 4 + 1; }
        if (v.z < vmin) { vmin = v.z; imin = tid * 4 + 2; }
        if (v.w < vmin) { vmin = v.w; imin = tid * 4 + 3; }
        for (int o = 16; o > 0; o >>= 1) {
            float ov = __shfl_down_sync(0xffffffffu, vmin, o);
            int   oi = __shfl_down_sync(0xffffffffu, imin, o);
            if (ov < vmin || (ov == vmin && oi < imin)) { vmin = ov; imin = oi; }
        }
        if (lane == 0) { swv[w] = vmin; swi[w] = imin; }
        __syncthreads();
        if (w == 0) {
            vmin = (lane < 8) ? swv[lane] : 3.4e38f;
            imin = (lane < 8) ? swi[lane] : 0x7fffffff;
            for (int o = 4; o > 0; o >>= 1) {
                float ov = __shfl_down_sync(0xffffffffu, vmin, o);
                int   oi = __shfl_down_sync(0xffffffffu, imin, o);
                if (ov < vmin || (ov == vmin && oi < imin)) { vmin = ov; imin = oi; }
            }
            if (lane == 0) {
                s_min = vmin;
                g_idx[row] = imin;
                out_idx[row] = (float)imin;
            }
        }
        __syncthreads();
        const float mn = s_min;
        if (tid == 0) dmin_sum += mn;
        float e0 = expf(mn - v.x), e1 = expf(mn - v.y);
        float e2 = expf(mn - v.z), e3 = expf(mn - v.w);
        float ss = e0 + e1 + e2 + e3;
        for (int o = 16; o > 0; o >>= 1) ss += __shfl_down_sync(0xffffffffu, ss, o);
        if (lane == 0) swv[w] = ss;
        __syncthreads();
        if (w == 0) {
            ss = (lane < 8) ? swv[lane] : 0.f;
            for (int o = 4; o > 0; o >>= 1) ss += __shfl_down_sync(0xffffffffu, ss, o);
            if (lane == 0) s_sum = ss;
        }
        __syncthreads();
        const float inv = 1.f / s_sum;
        cs0 += e0 * inv; cs1 += e1 * inv; cs2 += e2 * inv; cs3 += e3 * inv;
        __syncthreads();
    }
    atomicAdd(&g_colsum[tid * 4 + 0], cs0);
    atomicAdd(&g_colsum[tid * 4 + 1], cs1);
    atomicAdd(&g_colsum[tid * 4 + 2], cs2);
    atomicAdd(&g_colsum[tid * 4 + 3], cs3);
    if (tid == 0) atomicAdd(&g_vqsum, dmin_sum);
}

// ===========================================================================
// gather + final (unchanged)
// ===========================================================================
__global__ void __launch_bounds__(256) k_gatherfinal(const float* __restrict__ E,
                                                     float* __restrict__ out) {
    const int bid = blockIdx.x;
    const int tid = threadIdx.x;
    if (bid < M_TOT) {
        const int idx = g_idx[bid];
        const float4* e4 = (const float4*)(E + (size_t)idx * BD);
        float4* o4 = (float4*)(out + (size_t)bid * BD);
        for (int i = tid; i < BD / 4; i += 256) o4[i] = e4[i];
        return;
    }
    float t = 0.f;
#pragma unroll
    for (int i = 0; i < 4; i++) {
        float avg = g_colsum[tid + i * 256] * (1.0f / (float)M_TOT);
        t += -avg * logf(avg + EPS_ENT);
    }
    __shared__ float sw[8];
    for (int o = 16; o > 0; o >>= 1) t += __shfl_down_sync(0xffffffffu, t, o);
    int lane = tid & 31, w = tid >> 5;
    if (lane == 0) sw[w] = t;
    __syncthreads();
    if (w == 0) {
        t = (lane < 8) ? sw[lane] : 0.f;
        for (int o = 4; o > 0; o >>= 1) t += __shfl_down_sync(0xffffffffu, t, o);
        if (lane == 0) {
            const size_t OFF = (size_t)M_TOT * BD + M_TOT;
            out[OFF]     = g_vqsum * (1.0f / ((float)M_TOT * (float)BD));
            out[OFF + 1] = t;
        }
    }
}

// ---------------------------------------------------------------------------
extern "C" void kernel_launch(void* const* d_in, const int* in_sizes, int n_in,
                              void* d_out, int out_size) {
    const float* sf = (const float*)d_in[0];
    const float* W  = (const float*)d_in[1];
    const float* b  = (const float*)d_in[2];
    const float* E  = (const float*)d_in[3];
    float* out      = (float*)d_out;
    float* out_idx  = out + (size_t)M_TOT * BD;

    cudaFuncSetAttribute(gFG_kernel, cudaFuncAttributeMaxDynamicSharedMemorySize, SMEM_BYTES);
    cudaFuncSetAttribute(gS_kernel,  cudaFuncAttributeMaxDynamicSharedMemorySize, SMEM_BYTES);

    k_prep<<<PREP_BLOCKS, 256>>>(E, b, sf, W);
    gFG_kernel<<<GFG_BLOCKS, 256, SMEM_BYTES>>>(W, b);
    k_splitFG<<<320, 256>>>();
    gS_kernel<<<dim3(10, 64), 256, SMEM_BYTES>>>();
    k_rowz<<<2048, 256>>>(out_idx, sf);
    k_gatherfinal<<<M_TOT + 1, 256>>>(E, out);
}

// round 8
// speedup vs baseline: 11.5676x; 1.0018x over previous
#include <cuda_runtime.h>
#include <cuda_fp16.h>
#include <math.h>
#include <stdint.h>

// Problem dims
#define M_TOT 8192
#define D_DIM 256
#define BD    2700
#define NC    1024
#define KPAD  2752          // 86 * 32
#define NFG   1280          // NC + D_DIM = 5 * 256
#define EPS_ENT 1e-8f

// ---------------------------------------------------------------------------
__device__ __forceinline__ uint32_t smem_to_u32(const void* p) {
    uint32_t a;
    asm("{ .reg .u64 t; cvta.to.shared.u64 t, %1; cvt.u32.u64 %0, t; }" : "=r"(a) : "l"(p));
    return a;
}
__device__ __forceinline__ unsigned short f2h(float x) {
    unsigned short r;
    asm("cvt.rn.f16.f32 %0, %1;" : "=h"(r) : "f"(x));
    return r;
}
__device__ __forceinline__ float h2f(unsigned short h) {
    float f;
    asm("cvt.f32.f16 %0, %1;" : "=f"(f) : "h"(h));
    return f;
}
#define LDSM_X4(R, addr) \
    asm volatile("ldmatrix.sync.aligned.m8n8.x4.shared.b16 {%0,%1,%2,%3}, [%4];" \
        : "=r"((R)[0]), "=r"((R)[1]), "=r"((R)[2]), "=r"((R)[3]) : "r"(addr))

__device__ __forceinline__ void mma16816(float* c, const uint32_t* a, const uint32_t* b) {
    asm volatile("mma.sync.aligned.m16n8k16.row.col.f32.f16.f16.f32 "
        "{%0,%1,%2,%3}, {%4,%5,%6,%7}, {%8,%9}, {%0,%1,%2,%3};"
        : "+f"(c[0]), "+f"(c[1]), "+f"(c[2]), "+f"(c[3])
        : "r"(a[0]), "r"(a[1]), "r"(a[2]), "r"(a[3]), "r"(b[0]), "r"(b[1]));
}
__device__ __forceinline__ void cp16(uint32_t dst, const void* src) {
    asm volatile("cp.async.cg.shared.global [%0], [%1], 16;" :: "r"(dst), "l"(src) : "memory");
}
#define CP_COMMIT() asm volatile("cp.async.commit_group;" ::: "memory")

// ---------------------------------------------------------------------------
// Scratch (device globals)
// ---------------------------------------------------------------------------
__device__ __align__(16) unsigned short g_ehi[(size_t)NC * KPAD];
__device__ __align__(16) unsigned short g_elo[(size_t)NC * KPAD];
__device__ __align__(16) unsigned short g_wthi[(size_t)D_DIM * KPAD];
__device__ __align__(16) unsigned short g_wtlo[(size_t)D_DIM * KPAD];
__device__ __align__(16) unsigned short g_sfhi[(size_t)M_TOT * D_DIM];
__device__ __align__(16) unsigned short g_sflo[(size_t)M_TOT * D_DIM];
__device__ __align__(16) float g_FG[(size_t)NFG * D_DIM];
__device__ __align__(16) unsigned short g_FGhi[(size_t)NFG * D_DIM];
__device__ __align__(16) unsigned short g_FGlo[(size_t)NFG * D_DIM];
__device__ __align__(16) float g_P[(size_t)M_TOT * D_DIM];
__device__ __align__(16) float g_dist[(size_t)M_TOT * NC];
__device__ __align__(16) float g_ecoef[NC];
__device__ __align__(16) float g_h[D_DIM];
__device__ float g_colsum[NC];
__device__ int   g_idx[M_TOT];
__device__ float g_vqsum;
__device__ float g_bnorm;

// ===========================================================================
// PREP kernel
// ===========================================================================
#define PREP_ZERO_END  1280
#define PREP_E_END     2304
#define PREP_SF_END    4352
#define PREP_W_END     5040
#define PREP_BLOCKS    5041

__global__ void __launch_bounds__(256) k_prep(const float* __restrict__ E,
                                              const float* __restrict__ b,
                                              const float* __restrict__ sf,
                                              const float* __restrict__ W) {
    const int bid = blockIdx.x;
    const int tid = threadIdx.x;

    if (bid < PREP_ZERO_END) {
        g_FG[bid * 256 + tid] = 0.f;
        return;
    }
    if (bid < PREP_E_END) {
        const int row = bid - PREP_ZERO_END;
        const float4* src = (const float4*)(E + (size_t)row * BD);
        const float4* b4 = (const float4*)b;
        uint2* dh = (uint2*)(g_ehi + (size_t)row * KPAD);
        uint2* dl = (uint2*)(g_elo + (size_t)row * KPAD);
        float s = 0.f, s2 = 0.f;
        for (int i = tid; i < BD / 4; i += 256) {
            float4 v = src[i];
            float4 bv = b4[i];
            s  += v.x * v.x + v.y * v.y + v.z * v.z + v.w * v.w;
            s2 += v.x * bv.x + v.y * bv.y + v.z * bv.z + v.w * bv.w;
            unsigned short h0 = f2h(v.x), h1 = f2h(v.y), h2 = f2h(v.z), h3 = f2h(v.w);
            unsigned short l0 = f2h(v.x - h2f(h0)), l1 = f2h(v.y - h2f(h1));
            unsigned short l2 = f2h(v.z - h2f(h2)), l3 = f2h(v.w - h2f(h3));
            uint2 uh, ul;
            uh.x = (uint32_t)h0 | ((uint32_t)h1 << 16); uh.y = (uint32_t)h2 | ((uint32_t)h3 << 16);
            ul.x = (uint32_t)l0 | ((uint32_t)l1 << 16); ul.y = (uint32_t)l2 | ((uint32_t)l3 << 16);
            dh[i] = uh; dl[i] = ul;
        }
        __shared__ float sw[8], sw2[8];
        for (int o = 16; o > 0; o >>= 1) {
            s  += __shfl_down_sync(0xffffffffu, s, o);
            s2 += __shfl_down_sync(0xffffffffu, s2, o);
        }
        int lane = tid & 31, w = tid >> 5;
        if (lane == 0) { sw[w] = s; sw2[w] = s2; }
        __syncthreads();
        if (w == 0) {
            s  = (lane < 8) ? sw[lane] : 0.f;
            s2 = (lane < 8) ? sw2[lane] : 0.f;
            for (int o = 4; o > 0; o >>= 1) {
                s  += __shfl_down_sync(0xffffffffu, s, o);
                s2 += __shfl_down_sync(0xffffffffu, s2, o);
            }
            if (lane == 0) g_ecoef[row] = s - 2.f * s2;
        }
        return;
    }
    if (bid < PREP_SF_END) {
        int idx = (bid - PREP_E_END) * 256 + tid;
        float4 v = ((const float4*)sf)[idx];
        unsigned short h0 = f2h(v.x), h1 = f2h(v.y), h2 = f2h(v.z), h3 = f2h(v.w);
        unsigned short l0 = f2h(v.x - h2f(h0)), l1 = f2h(v.y - h2f(h1));
        unsigned short l2 = f2h(v.z - h2f(h2)), l3 = f2h(v.w - h2f(h3));
        uint2 uh, ul;
        uh.x = (uint32_t)h0 | ((uint32_t)h1 << 16); uh.y = (uint32_t)h2 | ((uint32_t)h3 << 16);
        ul.x = (uint32_t)l0 | ((uint32_t)l1 << 16); ul.y = (uint32_t)l2 | ((uint32_t)l3 << 16);
        ((uint2*)g_sfhi)[idx] = uh;
        ((uint2*)g_sflo)[idx] = ul;
        return;
    }
    if (bid < PREP_W_END) {
        __shared__ float tile[32][33];
        const int l = bid - PREP_SF_END;
        const int d0 = (l & 7) * 32, n0 = (l >> 3) * 32;
        const int tx = tid & 31, ty = tid >> 5;
#pragma unroll
        for (int i = 0; i < 4; i++) {
            int n = n0 + ty + i * 8;
            tile[ty + i * 8][tx] = (n < BD) ? W[(size_t)n * D_DIM + d0 + tx] : 0.f;
        }
        __syncthreads();
#pragma unroll
        for (int i = 0; i < 4; i++) {
            int d = d0 + ty + i * 8;
            int n = n0 + tx;
            float v = tile[tx][ty + i * 8];
            unsigned short h = f2h(v);
            g_wthi[(size_t)d * KPAD + n] = h;
            g_wtlo[(size_t)d * KPAD + n] = f2h(v - h2f(h));
        }
        return;
    }
    {
#pragma unroll
        for (int i = 0; i < 4; i++) g_colsum[tid + i * 256] = 0.f;
        g_h[tid] = 0.f;
        if (tid == 0) g_vqsum = 0.f;
        float s = 0.f;
        for (int i = tid; i < BD; i += 256) { float bv = b[i]; s += bv * bv; }
        __shared__ float sw[8];
        for (int o = 16; o > 0; o >>= 1) s += __shfl_down_sync(0xffffffffu, s, o);
        int lane = tid & 31, w = tid >> 5;
        if (lane == 0) sw[w] = s;
        __syncthreads();
        if (w == 0) {
            s = (lane < 8) ? sw[lane] : 0.f;
            for (int o = 4; o > 0; o >>= 1) s += __shfl_down_sync(0xffffffffu, s, o);
            if (lane == 0) g_bnorm = s;
        }
    }
}

// ---------------------------------------------------------------------------
// MMA mainloop: CTA 128x128, K-chunk 32, 8 warps (warp 64x32), 3-stage
// cp.async ring with ONE __syncthreads per chunk; pass-major MMA ordering.
// ---------------------------------------------------------------------------
#define STAGE_BYTES 32768
#define SMEM_BYTES  (3 * STAGE_BYTES)

template <int LOLO>
__device__ __forceinline__ void mma_mainloop(
    const unsigned short* __restrict__ Ahi, const unsigned short* __restrict__ Alo, int ldA,
    const unsigned short* __restrict__ Bhi, const unsigned short* __restrict__ Blo, int ldB,
    int m0, int n0, int kbeg, int kend, uint32_t sb0, float (&acc)[4][4][4])
{
    const int tid = threadIdx.x;
    const int lane = tid & 31, wid = tid >> 5;
    const int wm = (wid & 1) * 64;
    const int wn = (wid >> 1) * 32;
    const int nch = kend - kbeg;

    auto issue = [&](int c, int s) {
        const int k0 = c * 32;
        const uint32_t sb = sb0 + s * STAGE_BYTES;
#pragma unroll
        for (int t = 0; t < 2; t++) {
            int u = t * 256 + tid;
            int r = u >> 2, c8 = u & 3;
            uint32_t off = r * 64 + ((c8 ^ ((r >> 1) & 3)) << 4);
            cp16(sb + off,         Ahi + (size_t)(m0 + r) * ldA + k0 + c8 * 8);
            cp16(sb + off + 8192,  Alo + (size_t)(m0 + r) * ldA + k0 + c8 * 8);
            cp16(sb + off + 16384, Bhi + (size_t)(n0 + r) * ldB + k0 + c8 * 8);
            cp16(sb + off + 24576, Blo + (size_t)(n0 + r) * ldB + k0 + c8 * 8);
        }
        CP_COMMIT();
    };

    issue(kbeg, 0);
    if (nch > 1) issue(kbeg + 1, 1);
    int s = 0;
    for (int c = kbeg; c < kend; c++) {
        if (c + 1 < kend) asm volatile("cp.async.wait_group 1;" ::: "memory");
        else              asm volatile("cp.async.wait_group 0;" ::: "memory");
        __syncthreads();
        // issue chunk c+2 into the buffer consumed at iteration c-1
        if (c + 2 < kend) {
            int s2 = s + 2; if (s2 >= 3) s2 -= 3;
            issue(c + 2, s2);
        }

        const uint32_t sb = sb0 + s * STAGE_BYTES;
#pragma unroll
        for (int kb = 0; kb < 2; kb++) {
            uint32_t ah[4][4], al[4][4], bh[8], bl[8];
#pragma unroll
            for (int mt = 0; mt < 4; mt++) {
                int row = wm + mt * 16 + (lane & 15);
                int c8 = kb * 2 + (lane >> 4);
                uint32_t a = sb + row * 64 + ((c8 ^ ((row >> 1) & 3)) << 4);
                LDSM_X4(ah[mt], a);
                LDSM_X4(al[mt], a + 8192);
            }
#pragma unroll
            for (int nb = 0; nb < 2; nb++) {
                int rn = wn + nb * 16 + (lane & 7) + ((lane >> 4) << 3);
                int c8 = kb * 2 + ((lane >> 3) & 1);
                uint32_t baddr = sb + 16384 + rn * 64 + ((c8 ^ ((rn >> 1) & 3)) << 4);
                LDSM_X4(bh + nb * 4, baddr);
                LDSM_X4(bl + nb * 4, baddr + 8192);
            }
            // pass-major: consecutive MMAs hit different accumulators
#pragma unroll
            for (int mt = 0; mt < 4; mt++)
#pragma unroll
                for (int n8 = 0; n8 < 4; n8++)
                    mma16816(acc[mt][n8], ah[mt], bh + n8 * 2);
#pragma unroll
            for (int mt = 0; mt < 4; mt++)
#pragma unroll
                for (int n8 = 0; n8 < 4; n8++)
                    mma16816(acc[mt][n8], ah[mt], bl + n8 * 2);
#pragma unroll
            for (int mt = 0; mt < 4; mt++)
#pragma unroll
                for (int n8 = 0; n8 < 4; n8++)
                    mma16816(acc[mt][n8], al[mt], bh + n8 * 2);
            if (LOLO) {
#pragma unroll
                for (int mt = 0; mt < 4; mt++)
#pragma unroll
                    for (int n8 = 0; n8 < 4; n8++)
                        mma16816(acc[mt][n8], al[mt], bl + n8 * 2);
            }
        }
        // next buffer
        s++; if (s >= 3) s -= 3;
        __syncthreads();   // all warps done reading buf s-1 before it is refilled
    }
}

#define ACC_DECL float acc[4][4][4]; \
    _Pragma("unroll") for (int a_ = 0; a_ < 4; a_++) \
    _Pragma("unroll") for (int b_ = 0; b_ < 4; b_++) \
    _Pragma("unroll") for (int c_ = 0; c_ < 4; c_++) acc[a_][b_][c_] = 0.f;

// ===========================================================================
// gFG kernel
// ===========================================================================
#define GFG_F_END 240
#define GFG_G_END 412
#define GFG_BLOCKS 581

__global__ void __launch_bounds__(256, 2) gFG_kernel(const float* __restrict__ W,
                                                     const float* __restrict__ b) {
    const int bid = blockIdx.x;
    if (bid >= GFG_G_END) {
        const int tid = threadIdx.x;
        const int n0 = (bid - GFG_G_END) * 16;
        float hacc = 0.f;
        for (int r = 0; r < 16; r++) {
            int n = n0 + r;
            if (n < BD) hacc += __ldg(b + n) * W[(size_t)n * D_DIM + tid];
        }
        atomicAdd(&g_h[tid], hacc);
        return;
    }
    extern __shared__ char smem[];
    uint32_t sb0 = smem_to_u32(smem);
    ACC_DECL;
    const int lane = threadIdx.x & 31, wid = threadIdx.x >> 5;
    const int wm = (wid & 1) * 64, wn = (wid >> 1) * 32;
    const int g = lane >> 2, t = lane & 3;

    int m0, n0, kbeg, kend;
    const unsigned short *Ah, *Al;
    float* outbase;
    if (bid < GFG_F_END) {
        m0 = (bid / 30) * 128;
        int rem = bid % 30;
        n0 = (rem / 15) * 128;
        kbeg = (rem % 15) * 6;
        kend = kbeg + 6; if (kend > 86) kend = 86;
        Ah = g_ehi; Al = g_elo;
        outbase = g_FG;
    } else {
        int l = bid - GFG_F_END;
        m0 = (l / 86) * 128;
        int rem = l % 86;
        n0 = (rem / 43) * 128;
        kbeg = (rem % 43) * 2;
        kend = kbeg + 2;
        Ah = g_wthi; Al = g_wtlo;
        outbase = g_FG + (size_t)NC * D_DIM;
    }
    mma_mainloop<1>(Ah, Al, KPAD, g_wthi, g_wtlo, KPAD, m0, n0, kbeg, kend, sb0, acc);
#pragma unroll
    for (int mt = 0; mt < 4; mt++)
#pragma unroll
        for (int n8 = 0; n8 < 4; n8++) {
            int col = n0 + wn + n8 * 8 + t * 2;
#pragma unroll
            for (int h = 0; h < 2; h++) {
                int m = m0 + wm + mt * 16 + g + h * 8;
                atomicAdd(&outbase[(size_t)m * D_DIM + col],     acc[mt][n8][h * 2 + 0]);
                atomicAdd(&outbase[(size_t)m * D_DIM + col + 1], acc[mt][n8][h * 2 + 1]);
            }
        }
}

// split FG (81920 float4) into fp16 hi/lo
__global__ void __launch_bounds__(256) k_splitFG() {
    int idx = blockIdx.x * 256 + threadIdx.x;
    float4 v = ((const float4*)g_FG)[idx];
    unsigned short h0 = f2h(v.x), h1 = f2h(v.y), h2 = f2h(v.z), h3 = f2h(v.w);
    unsigned short l0 = f2h(v.x - h2f(h0)), l1 = f2h(v.y - h2f(h1));
    unsigned short l2 = f2h(v.z - h2f(h2)), l3 = f2h(v.w - h2f(h3));
    uint2 uh, ul;
    uh.x = (uint32_t)h0 | ((uint32_t)h1 << 16); uh.y = (uint32_t)h2 | ((uint32_t)h3 << 16);
    ul.x = (uint32_t)l0 | ((uint32_t)l1 << 16); ul.y = (uint32_t)l2 | ((uint32_t)l3 << 16);
    ((uint2*)g_FGhi)[idx] = uh;
    ((uint2*)g_FGlo)[idx] = ul;
}

// Fused S-GEMM: n-tiles 0..7 -> dist; 8..9 -> P. grid (10, 64)
__global__ void __launch_bounds__(256, 2) gS_kernel() {
    extern __shared__ char smem[];
    uint32_t sb0 = smem_to_u32(smem);
    ACC_DECL;
    const int m0 = blockIdx.y * 128, n0 = blockIdx.x * 128;
    mma_mainloop<0>(g_sfhi, g_sflo, D_DIM, g_FGhi, g_FGlo, D_DIM, m0, n0, 0, 8, sb0, acc);
    const int lane = threadIdx.x & 31, wid = threadIdx.x >> 5;
    const int wm = (wid & 1) * 64, wn = (wid >> 1) * 32;
    const int g = lane >> 2, t = lane & 3;
    if (blockIdx.x < 8) {
#pragma unroll
        for (int mt = 0; mt < 4; mt++)
#pragma unroll
            for (int n8 = 0; n8 < 4; n8++) {
                int col = n0 + wn + n8 * 8 + t * 2;
                float2 ec = *(const float2*)(g_ecoef + col);
#pragma unroll
                for (int h = 0; h < 2; h++) {
                    int m = m0 + wm + mt * 16 + g + h * 8;
                    float2 o;
                    o.x = ec.x - 2.f * acc[mt][n8][h * 2 + 0];
                    o.y = ec.y - 2.f * acc[mt][n8][h * 2 + 1];
                    *(float2*)(g_dist + (size_t)m * NC + col) = o;
                }
            }
    } else {
        const int p0 = (blockIdx.x - 8) * 128;
#pragma unroll
        for (int mt = 0; mt < 4; mt++)
#pragma unroll
            for (int n8 = 0; n8 < 4; n8++) {
                int col = p0 + wn + n8 * 8 + t * 2;
#pragma unroll
                for (int h = 0; h < 2; h++) {
                    int m = m0 + wm + mt * 16 + g + h * 8;
                    float2 o;
                    o.x = acc[mt][n8][h * 2 + 0];
                    o.y = acc[mt][n8][h * 2 + 1];
                    *(float2*)(g_P + (size_t)m * D_DIM + col) = o;
                }
            }
    }
}

// ===========================================================================
// rowz kernel
// ===========================================================================
__global__ void __launch_bounds__(256) k_rowz(float* __restrict__ out_idx,
                                              const float* __restrict__ sf) {
    const int bid = blockIdx.x;
    const int tid = threadIdx.x, lane = tid & 31, w = tid >> 5;
    if (bid >= 1024) {
        const int row = (bid - 1024) * 8 + w;
        const float4* s4 = (const float4*)(sf + (size_t)row * D_DIM);
        const float4* p4 = (const float4*)(g_P + (size_t)row * D_DIM);
        const float4* h4 = (const float4*)g_h;
        float acc = 0.f;
#pragma unroll
        for (int i = 0; i < 2; i++) {
            int j = lane + i * 32;
            float4 a = s4[j], p = p4[j], hh = h4[j];
            acc += a.x * (p.x + 2.f * hh.x) + a.y * (p.y + 2.f * hh.y)
                 + a.z * (p.z + 2.f * hh.z) + a.w * (p.w + 2.f * hh.w);
        }
        for (int o = 16; o > 0; o >>= 1) acc += __shfl_down_sync(0xffffffffu, acc, o);
        if (lane == 0) atomicAdd(&g_vqsum, acc + g_bnorm);
        return;
    }
    __shared__ float swv[8];
    __shared__ int   swi[8];
    __shared__ float s_min, s_sum;
    float cs0 = 0.f, cs1 = 0.f, cs2 = 0.f, cs3 = 0.f;
    float dmin_sum = 0.f;
    const int r0 = bid * 8;
    for (int rr = 0; rr < 8; rr++) {
        const int row = r0 + rr;
        float4 v = ((const float4*)(g_dist + (size_t)row * NC))[tid];
        float vmin = v.x; int imin = tid * 4;
        if (v.y < vmin) { vmin = v.y; imin = tid * 4 + 1; }
        if (v.z < vmin) { vmin = v.z; imin = tid * 4 + 2; }
        if (v.w < vmin) { vmin = v.w; imin = tid * 4 + 3; }
        for (int o = 16; o > 0; o >>= 1) {
            float ov = __shfl_down_sync(0xffffffffu, vmin, o);
            int   oi = __shfl_down_sync(0xffffffffu, imin, o);
            if (ov < vmin || (ov == vmin && oi < imin)) { vmin = ov; imin = oi; }
        }
        if (lane == 0) { swv[w] = vmin; swi[w] = imin; }
        __syncthreads();
        if (w == 0) {
            vmin = (lane < 8) ? swv[lane] : 3.4e38f;
            imin = (lane < 8) ? swi[lane] : 0x7fffffff;
            for (int o = 4; o > 0; o >>= 1) {
                float ov = __shfl_down_sync(0xffffffffu, vmin, o);
                int   oi = __shfl_down_sync(0xffffffffu, imin, o);
                if (ov < vmin || (ov == vmin && oi < imin)) { vmin = ov; imin = oi; }
            }
            if (lane == 0) {
                s_min = vmin;
                g_idx[row] = imin;
                out_idx[row] = (float)imin;
            }
        }
        __syncthreads();
        const float mn = s_min;
        if (tid == 0) dmin_sum += mn;
        float e0 = expf(mn - v.x), e1 = expf(mn - v.y);
        float e2 = expf(mn - v.z), e3 = expf(mn - v.w);
        float ss = e0 + e1 + e2 + e3;
        for (int o = 16; o > 0; o >>= 1) ss += __shfl_down_sync(0xffffffffu, ss, o);
        if (lane == 0) swv[w] = ss;
        __syncthreads();
        if (w == 0) {
            ss = (lane < 8) ? swv[lane] : 0.f;
            for (int o = 4; o > 0; o >>= 1) ss += __shfl_down_sync(0xffffffffu, ss, o);
            if (lane == 0) s_sum = ss;
        }
        __syncthreads();
        const float inv = 1.f / s_sum;
        cs0 += e0 * inv; cs1 += e1 * inv; cs2 += e2 * inv; cs3 += e3 * inv;
        __syncthreads();
    }
    atomicAdd(&g_colsum[tid * 4 + 0], cs0);
    atomicAdd(&g_colsum[tid * 4 + 1], cs1);
    atomicAdd(&g_colsum[tid * 4 + 2], cs2);
    atomicAdd(&g_colsum[tid * 4 + 3], cs3);
    if (tid == 0) atomicAdd(&g_vqsum, dmin_sum);
}

// ===========================================================================
// gather + final
// ===========================================================================
__global__ void __launch_bounds__(256) k_gatherfinal(const float* __restrict__ E,
                                                     float* __restrict__ out) {
    const int bid = blockIdx.x;
    const int tid = threadIdx.x;
    if (bid < M_TOT) {
        const int idx = g_idx[bid];
        const float4* e4 = (const float4*)(E + (size_t)idx * BD);
        float4* o4 = (float4*)(out + (size_t)bid * BD);
        for (int i = tid; i < BD / 4; i += 256) o4[i] = e4[i];
        return;
    }
    float t = 0.f;
#pragma unroll
    for (int i = 0; i < 4; i++) {
        float avg = g_colsum[tid + i * 256] * (1.0f / (float)M_TOT);
        t += -avg * logf(avg + EPS_ENT);
    }
    __shared__ float sw[8];
    for (int o = 16; o > 0; o >>= 1) t += __shfl_down_sync(0xffffffffu, t, o);
    int lane = tid & 31, w = tid >> 5;
    if (lane == 0) sw[w] = t;
    __syncthreads();
    if (w == 0) {
        t = (lane < 8) ? sw[lane] : 0.f;
        for (int o = 4; o > 0; o >>= 1) t += __shfl_down_sync(0xffffffffu, t, o);
        if (lane == 0) {
            const size_t OFF = (size_t)M_TOT * BD + M_TOT;
            out[OFF]     = g_vqsum * (1.0f / ((float)M_TOT * (float)BD));
            out[OFF + 1] = t;
        }
    }
}

// ---------------------------------------------------------------------------
extern "C" void kernel_launch(void* const* d_in, const int* in_sizes, int n_in,
                              void* d_out, int out_size) {
    const float* sf = (const float*)d_in[0];
    const float* W  = (const float*)d_in[1];
    const float* b  = (const float*)d_in[2];
    const float* E  = (const float*)d_in[3];
    float* out      = (float*)d_out;
    float* out_idx  = out + (size_t)M_TOT * BD;

    cudaFuncSetAttribute(gFG_kernel, cudaFuncAttributeMaxDynamicSharedMemorySize, SMEM_BYTES);
    cudaFuncSetAttribute(gS_kernel,  cudaFuncAttributeMaxDynamicSharedMemorySize, SMEM_BYTES);

    k_prep<<<PREP_BLOCKS, 256>>>(E, b, sf, W);
    gFG_kernel<<<GFG_BLOCKS, 256, SMEM_BYTES>>>(W, b);
    k_splitFG<<<320, 256>>>();
    gS_kernel<<<dim3(10, 64), 256, SMEM_BYTES>>>();
    k_rowz<<<2048, 256>>>(out_idx, sf);
    k_gatherfinal<<<M_TOT + 1, 256>>>(E, out);
}

// round 9
// speedup vs baseline: 11.7753x; 1.0180x over previous
#include <cuda_runtime.h>
#include <cuda_fp16.h>
#include <math.h>
#include <stdint.h>

// Problem dims
#define M_TOT 8192
#define D_DIM 256
#define BD    2700
#define NC    1024
#define KPAD  2752          // 86 * 32
#define NFG   1280          // NC + D_DIM = 5 * 256
#define EPS_ENT 1e-8f

// ---------------------------------------------------------------------------
__device__ __forceinline__ uint32_t smem_to_u32(const void* p) {
    uint32_t a;
    asm("{ .reg .u64 t; cvta.to.shared.u64 t, %1; cvt.u32.u64 %0, t; }" : "=r"(a) : "l"(p));
    return a;
}
__device__ __forceinline__ unsigned short f2h(float x) {
    unsigned short r;
    asm("cvt.rn.f16.f32 %0, %1;" : "=h"(r) : "f"(x));
    return r;
}
__device__ __forceinline__ float h2f(unsigned short h) {
    float f;
    asm("cvt.f32.f16 %0, %1;" : "=f"(f) : "h"(h));
    return f;
}
#define LDSM_X4(R, addr) \
    asm volatile("ldmatrix.sync.aligned.m8n8.x4.shared.b16 {%0,%1,%2,%3}, [%4];" \
        : "=r"((R)[0]), "=r"((R)[1]), "=r"((R)[2]), "=r"((R)[3]) : "r"(addr))

__device__ __forceinline__ void mma16816(float* c, const uint32_t* a, const uint32_t* b) {
    asm volatile("mma.sync.aligned.m16n8k16.row.col.f32.f16.f16.f32 "
        "{%0,%1,%2,%3}, {%4,%5,%6,%7}, {%8,%9}, {%0,%1,%2,%3};"
        : "+f"(c[0]), "+f"(c[1]), "+f"(c[2]), "+f"(c[3])
        : "r"(a[0]), "r"(a[1]), "r"(a[2]), "r"(a[3]), "r"(b[0]), "r"(b[1]));
}
__device__ __forceinline__ void cp16(uint32_t dst, const void* src) {
    asm volatile("cp.async.cg.shared.global [%0], [%1], 16;" :: "r"(dst), "l"(src) : "memory");
}
#define CP_COMMIT() asm volatile("cp.async.commit_group;" ::: "memory")

// ---------------------------------------------------------------------------
// Scratch (device globals)
// ---------------------------------------------------------------------------
__device__ __align__(16) unsigned short g_ehi[(size_t)NC * KPAD];
__device__ __align__(16) unsigned short g_elo[(size_t)NC * KPAD];
__device__ __align__(16) unsigned short g_wthi[(size_t)D_DIM * KPAD];
__device__ __align__(16) unsigned short g_wtlo[(size_t)D_DIM * KPAD];
__device__ __align__(16) unsigned short g_sfhi[(size_t)M_TOT * D_DIM];
__device__ __align__(16) unsigned short g_sflo[(size_t)M_TOT * D_DIM];
__device__ __align__(16) float g_FG[(size_t)NFG * D_DIM];
// B fragments for gS: [ntile 160][chunk 4][kq 4][lane 32] -> uint2 (b0,b1)
__device__ __align__(16) uint2 g_Bfh[160 * 4 * 4 * 32];
__device__ __align__(16) uint2 g_Bfl[160 * 4 * 4 * 32];
__device__ __align__(16) float g_P[(size_t)M_TOT * D_DIM];
__device__ __align__(16) float g_dist[(size_t)M_TOT * NC];
__device__ __align__(16) float g_ecoef[NC];
__device__ __align__(16) float g_h[D_DIM];
__device__ float g_colsum[NC];
__device__ int   g_idx[M_TOT];
__device__ float g_vqsum;
__device__ float g_bnorm;
__device__ unsigned int g_ticket;

// ===========================================================================
// PREP kernel
// ===========================================================================
#define PREP_ZERO_END  1280
#define PREP_E_END     2304
#define PREP_SF_END    4352
#define PREP_W_END     5040
#define PREP_BLOCKS    5041

__global__ void __launch_bounds__(256) k_prep(const float* __restrict__ E,
                                              const float* __restrict__ b,
                                              const float* __restrict__ sf,
                                              const float* __restrict__ W) {
    const int bid = blockIdx.x;
    const int tid = threadIdx.x;

    if (bid < PREP_ZERO_END) {
        g_FG[bid * 256 + tid] = 0.f;
        return;
    }
    if (bid < PREP_E_END) {
        const int row = bid - PREP_ZERO_END;
        const float4* src = (const float4*)(E + (size_t)row * BD);
        const float4* b4 = (const float4*)b;
        uint2* dh = (uint2*)(g_ehi + (size_t)row * KPAD);
        uint2* dl = (uint2*)(g_elo + (size_t)row * KPAD);
        float s = 0.f, s2 = 0.f;
        for (int i = tid; i < BD / 4; i += 256) {
            float4 v = src[i];
            float4 bv = b4[i];
            s  += v.x * v.x + v.y * v.y + v.z * v.z + v.w * v.w;
            s2 += v.x * bv.x + v.y * bv.y + v.z * bv.z + v.w * bv.w;
            unsigned short h0 = f2h(v.x), h1 = f2h(v.y), h2 = f2h(v.z), h3 = f2h(v.w);
            unsigned short l0 = f2h(v.x - h2f(h0)), l1 = f2h(v.y - h2f(h1));
            unsigned short l2 = f2h(v.z - h2f(h2)), l3 = f2h(v.w - h2f(h3));
            uint2 uh, ul;
            uh.x = (uint32_t)h0 | ((uint32_t)h1 << 16); uh.y = (uint32_t)h2 | ((uint32_t)h3 << 16);
            ul.x = (uint32_t)l0 | ((uint32_t)l1 << 16); ul.y = (uint32_t)l2 | ((uint32_t)l3 << 16);
            dh[i] = uh; dl[i] = ul;
        }
        __shared__ float sw[8], sw2[8];
        for (int o = 16; o > 0; o >>= 1) {
            s  += __shfl_down_sync(0xffffffffu, s, o);
            s2 += __shfl_down_sync(0xffffffffu, s2, o);
        }
        int lane = tid & 31, w = tid >> 5;
        if (lane == 0) { sw[w] = s; sw2[w] = s2; }
        __syncthreads();
        if (w == 0) {
            s  = (lane < 8) ? sw[lane] : 0.f;
            s2 = (lane < 8) ? sw2[lane] : 0.f;
            for (int o = 4; o > 0; o >>= 1) {
                s  += __shfl_down_sync(0xffffffffu, s, o);
                s2 += __shfl_down_sync(0xffffffffu, s2, o);
            }
            if (lane == 0) g_ecoef[row] = s - 2.f * s2;
        }
        return;
    }
    if (bid < PREP_SF_END) {
        int idx = (bid - PREP_E_END) * 256 + tid;
        float4 v = ((const float4*)sf)[idx];
        unsigned short h0 = f2h(v.x), h1 = f2h(v.y), h2 = f2h(v.z), h3 = f2h(v.w);
        unsigned short l0 = f2h(v.x - h2f(h0)), l1 = f2h(v.y - h2f(h1));
        unsigned short l2 = f2h(v.z - h2f(h2)), l3 = f2h(v.w - h2f(h3));
        uint2 uh, ul;
        uh.x = (uint32_t)h0 | ((uint32_t)h1 << 16); uh.y = (uint32_t)h2 | ((uint32_t)h3 << 16);
        ul.x = (uint32_t)l0 | ((uint32_t)l1 << 16); ul.y = (uint32_t)l2 | ((uint32_t)l3 << 16);
        ((uint2*)g_sfhi)[idx] = uh;
        ((uint2*)g_sflo)[idx] = ul;
        return;
    }
    if (bid < PREP_W_END) {
        __shared__ float tile[32][33];
        const int l = bid - PREP_SF_END;
        const int d0 = (l & 7) * 32, n0 = (l >> 3) * 32;
        const int tx = tid & 31, ty = tid >> 5;
#pragma unroll
        for (int i = 0; i < 4; i++) {
            int n = n0 + ty + i * 8;
            tile[ty + i * 8][tx] = (n < BD) ? W[(size_t)n * D_DIM + d0 + tx] : 0.f;
        }
        __syncthreads();
#pragma unroll
        for (int i = 0; i < 4; i++) {
            int d = d0 + ty + i * 8;
            int n = n0 + tx;
            float v = tile[tx][ty + i * 8];
            unsigned short h = f2h(v);
            g_wthi[(size_t)d * KPAD + n] = h;
            g_wtlo[(size_t)d * KPAD + n] = f2h(v - h2f(h));
        }
        return;
    }
    {
#pragma unroll
        for (int i = 0; i < 4; i++) g_colsum[tid + i * 256] = 0.f;
        g_h[tid] = 0.f;
        if (tid == 0) { g_vqsum = 0.f; g_ticket = 0u; }
        float s = 0.f;
        for (int i = tid; i < BD; i += 256) { float bv = b[i]; s += bv * bv; }
        __shared__ float sw[8];
        for (int o = 16; o > 0; o >>= 1) s += __shfl_down_sync(0xffffffffu, s, o);
        int lane = tid & 31, w = tid >> 5;
        if (lane == 0) sw[w] = s;
        __syncthreads();
        if (w == 0) {
            s = (lane < 8) ? sw[lane] : 0.f;
            for (int o = 4; o > 0; o >>= 1) s += __shfl_down_sync(0xffffffffu, s, o);
            if (lane == 0) g_bnorm = s;
        }
    }
}

// ---------------------------------------------------------------------------
// gFG mainloop (B in smem, K-chunk 32, 3-stage) — unchanged from R8
// ---------------------------------------------------------------------------
#define STAGE_FG 32768
#define SMEM_FG  (3 * STAGE_FG)

__device__ __forceinline__ void fg_mainloop(
    const unsigned short* __restrict__ Ahi, const unsigned short* __restrict__ Alo,
    const unsigned short* __restrict__ Bhi, const unsigned short* __restrict__ Blo,
    int m0, int n0, int kbeg, int kend, uint32_t sb0, float (&acc)[4][4][4])
{
    const int tid = threadIdx.x;
    const int lane = tid & 31, wid = tid >> 5;
    const int wm = (wid & 1) * 64;
    const int wn = (wid >> 1) * 32;
    const int nch = kend - kbeg;

    auto issue = [&](int c, int s) {
        const int k0 = c * 32;
        const uint32_t sb = sb0 + s * STAGE_FG;
#pragma unroll
        for (int t = 0; t < 2; t++) {
            int u = t * 256 + tid;
            int r = u >> 2, c8 = u & 3;
            uint32_t off = r * 64 + ((c8 ^ ((r >> 1) & 3)) << 4);
            cp16(sb + off,         Ahi + (size_t)(m0 + r) * KPAD + k0 + c8 * 8);
            cp16(sb + off + 8192,  Alo + (size_t)(m0 + r) * KPAD + k0 + c8 * 8);
            cp16(sb + off + 16384, Bhi + (size_t)(n0 + r) * KPAD + k0 + c8 * 8);
            cp16(sb + off + 24576, Blo + (size_t)(n0 + r) * KPAD + k0 + c8 * 8);
        }
        CP_COMMIT();
    };

    issue(kbeg, 0);
    if (nch > 1) issue(kbeg + 1, 1);
    int s = 0;
    for (int c = kbeg; c < kend; c++) {
        if (c + 1 < kend) asm volatile("cp.async.wait_group 1;" ::: "memory");
        else              asm volatile("cp.async.wait_group 0;" ::: "memory");
        __syncthreads();
        if (c + 2 < kend) {
            int s2 = s + 2; if (s2 >= 3) s2 -= 3;
            issue(c + 2, s2);
        }
        const uint32_t sb = sb0 + s * STAGE_FG;
#pragma unroll
        for (int kb = 0; kb < 2; kb++) {
            uint32_t ah[4][4], al[4][4], bh[8], bl[8];
#pragma unroll
            for (int mt = 0; mt < 4; mt++) {
                int row = wm + mt * 16 + (lane & 15);
                int c8 = kb * 2 + (lane >> 4);
                uint32_t a = sb + row * 64 + ((c8 ^ ((row >> 1) & 3)) << 4);
                LDSM_X4(ah[mt], a);
                LDSM_X4(al[mt], a + 8192);
            }
#pragma unroll
            for (int nb = 0; nb < 2; nb++) {
                int rn = wn + nb * 16 + (lane & 7) + ((lane >> 4) << 3);
                int c8 = kb * 2 + ((lane >> 3) & 1);
                uint32_t baddr = sb + 16384 + rn * 64 + ((c8 ^ ((rn >> 1) & 3)) << 4);
                LDSM_X4(bh + nb * 4, baddr);
                LDSM_X4(bl + nb * 4, baddr + 8192);
            }
#pragma unroll
            for (int mt = 0; mt < 4; mt++)
#pragma unroll
                for (int n8 = 0; n8 < 4; n8++)
                    mma16816(acc[mt][n8], ah[mt], bh + n8 * 2);
#pragma unroll
            for (int mt = 0; mt < 4; mt++)
#pragma unroll
                for (int n8 = 0; n8 < 4; n8++)
                    mma16816(acc[mt][n8], ah[mt], bl + n8 * 2);
#pragma unroll
            for (int mt = 0; mt < 4; mt++)
#pragma unroll
                for (int n8 = 0; n8 < 4; n8++)
                    mma16816(acc[mt][n8], al[mt], bh + n8 * 2);
#pragma unroll
            for (int mt = 0; mt < 4; mt++)
#pragma unroll
                for (int n8 = 0; n8 < 4; n8++)
                    mma16816(acc[mt][n8], al[mt], bl + n8 * 2);
        }
        s++; if (s >= 3) s -= 3;
        __syncthreads();
    }
}

#define ACC_DECL float acc[4][4][4]; \
    _Pragma("unroll") for (int a_ = 0; a_ < 4; a_++) \
    _Pragma("unroll") for (int b_ = 0; b_ < 4; b_++) \
    _Pragma("unroll") for (int c_ = 0; c_ < 4; c_++) acc[a_][b_][c_] = 0.f;

// ===========================================================================
// gFG kernel
// ===========================================================================
#define GFG_F_END 240
#define GFG_G_END 412
#define GFG_BLOCKS 581

__global__ void __launch_bounds__(256, 2) gFG_kernel(const float* __restrict__ W,
                                                     const float* __restrict__ b) {
    const int bid = blockIdx.x;
    if (bid >= GFG_G_END) {
        const int tid = threadIdx.x;
        const int n0 = (bid - GFG_G_END) * 16;
        float hacc = 0.f;
        for (int r = 0; r < 16; r++) {
            int n = n0 + r;
            if (n < BD) hacc += __ldg(b + n) * W[(size_t)n * D_DIM + tid];
        }
        atomicAdd(&g_h[tid], hacc);
        return;
    }
    extern __shared__ char smem[];
    uint32_t sb0 = smem_to_u32(smem);
    ACC_DECL;
    const int lane = threadIdx.x & 31, wid = threadIdx.x >> 5;
    const int wm = (wid & 1) * 64, wn = (wid >> 1) * 32;
    const int g = lane >> 2, t = lane & 3;

    int m0, n0, kbeg, kend;
    const unsigned short *Ah, *Al;
    float* outbase;
    if (bid < GFG_F_END) {
        m0 = (bid / 30) * 128;
        int rem = bid % 30;
        n0 = (rem / 15) * 128;
        kbeg = (rem % 15) * 6;
        kend = kbeg + 6; if (kend > 86) kend = 86;
        Ah = g_ehi; Al = g_elo;
        outbase = g_FG;
    } else {
        int l = bid - GFG_F_END;
        m0 = (l / 86) * 128;
        int rem = l % 86;
        n0 = (rem / 43) * 128;
        kbeg = (rem % 43) * 2;
        kend = kbeg + 2;
        Ah = g_wthi; Al = g_wtlo;
        outbase = g_FG + (size_t)NC * D_DIM;
    }
    fg_mainloop(Ah, Al, g_wthi, g_wtlo, m0, n0, kbeg, kend, sb0, acc);
#pragma unroll
    for (int mt = 0; mt < 4; mt++)
#pragma unroll
        for (int n8 = 0; n8 < 4; n8++) {
            int col = n0 + wn + n8 * 8 + t * 2;
#pragma unroll
            for (int h = 0; h < 2; h++) {
                int m = m0 + wm + mt * 16 + g + h * 8;
                atomicAdd(&outbase[(size_t)m * D_DIM + col],     acc[mt][n8][h * 2 + 0]);
                atomicAdd(&outbase[(size_t)m * D_DIM + col + 1], acc[mt][n8][h * 2 + 1]);
            }
        }
}

// ===========================================================================
// splitFG: pack FG fp32 -> mma B-fragment layout (hi/lo fp16)
// idx = ((ntile*4 + chunk)*4 + kq)*32 + lane
// n = ntile*8 + lane/4 ; k = chunk*64 + kq*16 + (lane&3)*2 (+8 for .y)
// ===========================================================================
__global__ void __launch_bounds__(256) k_splitFG() {
    int idx = blockIdx.x * 256 + threadIdx.x;     // [0, 81920)
    int lane = idx & 31;
    int kq = (idx >> 5) & 3;
    int chunk = (idx >> 7) & 3;
    int ntile = idx >> 9;
    int n = ntile * 8 + (lane >> 2);
    int kb = chunk * 64 + kq * 16 + (lane & 3) * 2;
    const float* Fr = g_FG + (size_t)n * D_DIM + kb;
    float2 v0 = *(const float2*)Fr;
    float2 v1 = *(const float2*)(Fr + 8);
    unsigned short h00 = f2h(v0.x), h01 = f2h(v0.y);
    unsigned short h10 = f2h(v1.x), h11 = f2h(v1.y);
    unsigned short l00 = f2h(v0.x - h2f(h00)), l01 = f2h(v0.y - h2f(h01));
    unsigned short l10 = f2h(v1.x - h2f(h10)), l11 = f2h(v1.y - h2f(h11));
    uint2 uh, ul;
    uh.x = (uint32_t)h00 | ((uint32_t)h01 << 16);
    uh.y = (uint32_t)h10 | ((uint32_t)h11 << 16);
    ul.x = (uint32_t)l00 | ((uint32_t)l01 << 16);
    ul.y = (uint32_t)l10 | ((uint32_t)l11 << 16);
    g_Bfh[idx] = uh;
    g_Bfl[idx] = ul;
}

// ===========================================================================
// gS kernel: A in smem (K-chunk 64, 3-stage), B direct from fragment gmem.
// grid (10, 64): n-tiles 0..7 -> dist; 8..9 -> P
// ===========================================================================
#define STAGE_S 32768
#define SMEM_S  (3 * STAGE_S)

__global__ void __launch_bounds__(256, 2) gS_kernel() {
    extern __shared__ char smem[];
    uint32_t sb0 = smem_to_u32(smem);
    ACC_DECL;
    const int tid = threadIdx.x;
    const int lane = tid & 31, wid = tid >> 5;
    const int wm = (wid & 1) * 64, wn = (wid >> 1) * 32;
    const int m0 = blockIdx.y * 128, n0 = blockIdx.x * 128;
    const int bntile = (n0 + wn) >> 3;

    auto issueA = [&](int c, int s) {
        const int k0 = c * 64;
        const uint32_t sb = sb0 + s * STAGE_S;
#pragma unroll
        for (int t = 0; t < 4; t++) {
            int u = t * 256 + tid;
            int r = u >> 3, c8 = u & 7;
            uint32_t off = r * 128 + ((c8 ^ (r & 7)) << 4);
            cp16(sb + off,         g_sfhi + (size_t)(m0 + r) * D_DIM + k0 + c8 * 8);
            cp16(sb + off + 16384, g_sflo + (size_t)(m0 + r) * D_DIM + k0 + c8 * 8);
        }
        CP_COMMIT();
    };

    issueA(0, 0);
    issueA(1, 1);
    int s = 0;
    for (int c = 0; c < 4; c++) {
        if (c < 3) asm volatile("cp.async.wait_group 1;" ::: "memory");
        else       asm volatile("cp.async.wait_group 0;" ::: "memory");
        __syncthreads();
        if (c + 2 < 4) {
            int s2 = s + 2; if (s2 >= 3) s2 -= 3;
            issueA(c + 2, s2);
        }
        const uint32_t sb = sb0 + s * STAGE_S;
#pragma unroll
        for (int kq = 0; kq < 4; kq++) {
            uint32_t ah[4][4], al[4][4], bh[8], bl[8];
#pragma unroll
            for (int mt = 0; mt < 4; mt++) {
                int row = wm + mt * 16 + (lane & 15);
                int c8 = kq * 2 + (lane >> 4);
                uint32_t a = sb + row * 128 + ((c8 ^ (row & 7)) << 4);
                LDSM_X4(ah[mt], a);
                LDSM_X4(al[mt], a + 16384);
            }
#pragma unroll
            for (int n8 = 0; n8 < 4; n8++) {
                size_t bi = (((size_t)(bntile + n8) * 4 + c) * 4 + kq) * 32 + lane;
                uint2 h2 = g_Bfh[bi];
                uint2 l2 = g_Bfl[bi];
                bh[n8 * 2] = h2.x; bh[n8 * 2 + 1] = h2.y;
                bl[n8 * 2] = l2.x; bl[n8 * 2 + 1] = l2.y;
            }
#pragma unroll
            for (int mt = 0; mt < 4; mt++)
#pragma unroll
                for (int n8 = 0; n8 < 4; n8++)
                    mma16816(acc[mt][n8], ah[mt], bh + n8 * 2);
#pragma unroll
            for (int mt = 0; mt < 4; mt++)
#pragma unroll
                for (int n8 = 0; n8 < 4; n8++)
                    mma16816(acc[mt][n8], ah[mt], bl + n8 * 2);
#pragma unroll
            for (int mt = 0; mt < 4; mt++)
#pragma unroll
                for (int n8 = 0; n8 < 4; n8++)
                    mma16816(acc[mt][n8], al[mt], bh + n8 * 2);
        }
        s++; if (s >= 3) s -= 3;
        __syncthreads();
    }

    const int g = lane >> 2, t = lane & 3;
    if (blockIdx.x < 8) {
#pragma unroll
        for (int mt = 0; mt < 4; mt++)
#pragma unroll
            for (int n8 = 0; n8 < 4; n8++) {
                int col = n0 + wn + n8 * 8 + t * 2;
                float2 ec = *(const float2*)(g_ecoef + col);
#pragma unroll
                for (int h = 0; h < 2; h++) {
                    int m = m0 + wm + mt * 16 + g + h * 8;
                    float2 o;
                    o.x = ec.x - 2.f * acc[mt][n8][h * 2 + 0];
                    o.y = ec.y - 2.f * acc[mt][n8][h * 2 + 1];
                    *(float2*)(g_dist + (size_t)m * NC + col) = o;
                }
            }
    } else {
        const int p0 = (blockIdx.x - 8) * 128;
#pragma unroll
        for (int mt = 0; mt < 4; mt++)
#pragma unroll
            for (int n8 = 0; n8 < 4; n8++) {
                int col = p0 + wn + n8 * 8 + t * 2;
#pragma unroll
                for (int h = 0; h < 2; h++) {
                    int m = m0 + wm + mt * 16 + g + h * 8;
                    float2 o;
                    o.x = acc[mt][n8][h * 2 + 0];
                    o.y = acc[mt][n8][h * 2 + 1];
                    *(float2*)(g_P + (size_t)m * D_DIM + col) = o;
                }
            }
    }
}

// ===========================================================================
// rowz kernel: [0,1024) argmin+softmax+colsum+dmin + GATHER; [1024,2048) znorm
// Last block (atomic ticket) computes final scalars.
// ===========================================================================
__global__ void __launch_bounds__(256) k_rowz(float* __restrict__ out_idx,
                                              const float* __restrict__ sf,
                                              const float* __restrict__ E,
                                              float* __restrict__ out) {
    const int bid = blockIdx.x;
    const int tid = threadIdx.x, lane = tid & 31, w = tid >> 5;
    if (bid >= 1024) {
        const int row = (bid - 1024) * 8 + w;
        const float4* s4 = (const float4*)(sf + (size_t)row * D_DIM);
        const float4* p4 = (const float4*)(g_P + (size_t)row * D_DIM);
        const float4* h4 = (const float4*)g_h;
        float acc = 0.f;
#pragma unroll
        for (int i = 0; i < 2; i++) {
            int j = lane + i * 32;
            float4 a = s4[j], p = p4[j], hh = h4[j];
            acc += a.x * (p.x + 2.f * hh.x) + a.y * (p.y + 2.f * hh.y)
                 + a.z * (p.z + 2.f * hh.z) + a.w * (p.w + 2.f * hh.w);
        }
        for (int o = 16; o > 0; o >>= 1) acc += __shfl_down_sync(0xffffffffu, acc, o);
        if (lane == 0) atomicAdd(&g_vqsum, acc + g_bnorm);
    } else {
        __shared__ float swv[8];
        __shared__ int   swi[8];
        __shared__ float s_min, s_sum;
        __shared__ int   sidx[8];
        float cs0 = 0.f, cs1 = 0.f, cs2 = 0.f, cs3 = 0.f;
        float dmin_sum = 0.f;
        const int r0 = bid * 8;
        for (int rr = 0; rr < 8; rr++) {
            const int row = r0 + rr;
            float4 v = ((const float4*)(g_dist + (size_t)row * NC))[tid];
            float vmin = v.x; int imin = tid * 4;
            if (v.y < vmin) { vmin = v.y; imin = tid * 4 + 1; }
            if (v.z < vmin) { vmin = v.z; imin = tid * 4 + 2; }
            if (v.w < vmin) { vmin = v.w; imin = tid * 4 + 3; }
            for (int o = 16; o > 0; o >>= 1) {
                float ov = __shfl_down_sync(0xffffffffu, vmin, o);
                int   oi = __shfl_down_sync(0xffffffffu, imin, o);
                if (ov < vmin || (ov == vmin && oi < imin)) { vmin = ov; imin = oi; }
            }
            if (lane == 0) { swv[w] = vmin; swi[w] = imin; }
            __syncthreads();
            if (w == 0) {
                vmin = (lane < 8) ? swv[lane] : 3.4e38f;
                imin = (lane < 8) ? swi[lane] : 0x7fffffff;
                for (int o = 4; o > 0; o >>= 1) {
                    float ov = __shfl_down_sync(0xffffffffu, vmin, o);
                    int   oi = __shfl_down_sync(0xffffffffu, imin, o);
                    if (ov < vmin || (ov == vmin && oi < imin)) { vmin = ov; imin = oi; }
                }
                if (lane == 0) {
                    s_min = vmin;
                    sidx[rr] = imin;
                    out_idx[row] = (float)imin;
                }
            }
            __syncthreads();
            const float mn = s_min;
            if (tid == 0) dmin_sum += mn;
            float e0 = expf(mn - v.x), e1 = expf(mn - v.y);
            float e2 = expf(mn - v.z), e3 = expf(mn - v.w);
            float ss = e0 + e1 + e2 + e3;
            for (int o = 16; o > 0; o >>= 1) ss += __shfl_down_sync(0xffffffffu, ss, o);
            if (lane == 0) swv[w] = ss;
            __syncthreads();
            if (w == 0) {
                ss = (lane < 8) ? swv[lane] : 0.f;
                for (int o = 4; o > 0; o >>= 1) ss += __shfl_down_sync(0xffffffffu, ss, o);
                if (lane == 0) s_sum = ss;
            }
            __syncthreads();
            const float inv = 1.f / s_sum;
            cs0 += e0 * inv; cs1 += e1 * inv; cs2 += e2 * inv; cs3 += e3 * inv;
            __syncthreads();
        }
        atomicAdd(&g_colsum[tid * 4 + 0], cs0);
        atomicAdd(&g_colsum[tid * 4 + 1], cs1);
        atomicAdd(&g_colsum[tid * 4 + 2], cs2);
        atomicAdd(&g_colsum[tid * 4 + 3], cs3);
        if (tid == 0) atomicAdd(&g_vqsum, dmin_sum);
        // gather q_st = E[idx] for the 8 rows
        for (int rr = 0; rr < 8; rr++) {
            const float4* e4 = (const float4*)(E + (size_t)sidx[rr] * BD);
            float4* o4 = (float4*)(out + (size_t)(r0 + rr) * BD);
            for (int i = tid; i < BD / 4; i += 256) o4[i] = e4[i];
        }
    }

    // ---- last-block final scalars ----
    __shared__ unsigned int s_t;
    __threadfence();
    __syncthreads();
    if (tid == 0) s_t = atomicAdd(&g_ticket, 1u);
    __syncthreads();
    if (s_t == 2047u) {
        __threadfence();
        float t = 0.f;
#pragma unroll
        for (int i = 0; i < 4; i++) {
            float avg = g_colsum[tid + i * 256] * (1.0f / (float)M_TOT);
            t += -avg * logf(avg + EPS_ENT);
        }
        __shared__ float sw[8];
        for (int o = 16; o > 0; o >>= 1) t += __shfl_down_sync(0xffffffffu, t, o);
        if (lane == 0) sw[w] = t;
        __syncthreads();
        if (w == 0) {
            t = (lane < 8) ? sw[lane] : 0.f;
            for (int o = 4; o > 0; o >>= 1) t += __shfl_down_sync(0xffffffffu, t, o);
            if (lane == 0) {
                const size_t OFF = (size_t)M_TOT * BD + M_TOT;
                out[OFF]     = g_vqsum * (1.0f / ((float)M_TOT * (float)BD));
                out[OFF + 1] = t;
            }
        }
    }
}

// ---------------------------------------------------------------------------
extern "C" void kernel_launch(void* const* d_in, const int* in_sizes, int n_in,
                              void* d_out, int out_size) {
    const float* sf = (const float*)d_in[0];
    const float* W  = (const float*)d_in[1];
    const float* b  = (const float*)d_in[2];
    const float* E  = (const float*)d_in[3];
    float* out      = (float*)d_out;
    float* out_idx  = out + (size_t)M_TOT * BD;

    cudaFuncSetAttribute(gFG_kernel, cudaFuncAttributeMaxDynamicSharedMemorySize, SMEM_FG);
    cudaFuncSetAttribute(gS_kernel,  cudaFuncAttributeMaxDynamicSharedMemorySize, SMEM_S);

    k_prep<<<PREP_BLOCKS, 256>>>(E, b, sf, W);
    gFG_kernel<<<GFG_BLOCKS, 256, SMEM_FG>>>(W, b);
    k_splitFG<<<320, 256>>>();
    gS_kernel<<<dim3(10, 64), 256, SMEM_S>>>();
    k_rowz<<<2048, 256>>>(out_idx, sf, E, out);
}